// round 4
// baseline (speedup 1.0000x reference)
#include <cuda_runtime.h>
#include <cuda_bf16.h>
#include <cstdint>

#define T_TOK 16384
#define H_DIM 512
#define M_MEM 4096
#define INV_TEMP 10.0f

// ---------------------------------------------------------------------------
// Scratch (static device globals; no allocations anywhere)
// ---------------------------------------------------------------------------
__device__ __nv_bfloat16 g_hid_hi[(size_t)T_TOK * H_DIM];
__device__ __nv_bfloat16 g_hid_lo[(size_t)T_TOK * H_DIM];
__device__ __nv_bfloat16 g_wk_hi[(size_t)H_DIM * H_DIM];
__device__ __nv_bfloat16 g_wk_lo[(size_t)H_DIM * H_DIM];
__device__ __nv_bfloat16 g_wo_hi[(size_t)H_DIM * H_DIM];
__device__ __nv_bfloat16 g_wo_lo[(size_t)H_DIM * H_DIM];
__device__ __nv_bfloat16 g_mv_hi[(size_t)M_MEM * H_DIM];
__device__ __nv_bfloat16 g_mv_lo[(size_t)M_MEM * H_DIM];
__device__ __nv_bfloat16 g_mk_hi[(size_t)M_MEM * H_DIM];
__device__ __nv_bfloat16 g_mk_lo[(size_t)M_MEM * H_DIM];
__device__ float         g_w2t[(size_t)H_DIM * M_MEM];      // W2T[h,m] = sum_v Wo[h,v] mv[m,v]
__device__ __nv_bfloat16 g_w2t_hi[(size_t)H_DIM * M_MEM];
__device__ __nv_bfloat16 g_w2t_lo[(size_t)H_DIM * M_MEM];
__device__ float         g_q[(size_t)T_TOK * H_DIM];
__device__ __nv_bfloat16 g_q_hi[(size_t)T_TOK * H_DIM];
__device__ __nv_bfloat16 g_q_lo[(size_t)T_TOK * H_DIM];
__device__ float         g_scores[(size_t)T_TOK * M_MEM];
__device__ __nv_bfloat16 g_attn_hi[(size_t)T_TOK * M_MEM];
__device__ __nv_bfloat16 g_attn_lo[(size_t)T_TOK * M_MEM];

// ---------------------------------------------------------------------------
// Helpers (baseline PTX only: cp.async / ldmatrix / mma.sync)
// ---------------------------------------------------------------------------
__device__ __forceinline__ uint32_t su32(const void* p) {
    return (uint32_t)__cvta_generic_to_shared(p);
}
__device__ __forceinline__ void cp16(uint32_t dst, const void* src) {
    asm volatile("cp.async.cg.shared.global [%0], [%1], 16;\n" :: "r"(dst), "l"(src) : "memory");
}
__device__ __forceinline__ void cp_commit() { asm volatile("cp.async.commit_group;\n" ::: "memory"); }
__device__ __forceinline__ void cp_wait1()  { asm volatile("cp.async.wait_group 1;\n" ::: "memory"); }

__device__ __forceinline__ void ldsm_x4(uint32_t* r, uint32_t addr) {
    asm volatile("ldmatrix.sync.aligned.m8n8.x4.shared.b16 {%0,%1,%2,%3}, [%4];"
                 : "=r"(r[0]), "=r"(r[1]), "=r"(r[2]), "=r"(r[3]) : "r"(addr));
}
__device__ __forceinline__ void mma16816(float* c, const uint32_t* a, const uint32_t* b) {
    asm volatile(
        "mma.sync.aligned.m16n8k16.row.col.f32.bf16.bf16.f32 "
        "{%0,%1,%2,%3}, {%4,%5,%6,%7}, {%8,%9}, {%0,%1,%2,%3};"
        : "+f"(c[0]), "+f"(c[1]), "+f"(c[2]), "+f"(c[3])
        : "r"(a[0]), "r"(a[1]), "r"(a[2]), "r"(a[3]), "r"(b[0]), "r"(b[1]));
}

__device__ __forceinline__ void split1(float x, __nv_bfloat16& h, __nv_bfloat16& l) {
    h = __float2bfloat16(x);
    l = __float2bfloat16(x - __bfloat162float(h));
}

// ---------------------------------------------------------------------------
// HMMA GEMM:  C[M,N] = split(A) @ split(B)^T   (A:[M,K], B:[N,K], bf16 hi/lo)
// 128x128 CTA tile, 512 threads, 16 warps (4x4) of 32x32, BK=64,
// 3-stage cp.async pipeline. Ah*Bh + Ah*Bl + Al*Bh with fp32 accumulators.
// EPI: 0 = plain, 1 = +bias[n], 2 = masked scale (scores).
// Requires M,N % 128 == 0, K % 64 == 0.
// ---------------------------------------------------------------------------
#define BK      64
#define TROW    144                    // 128B data + 16B pad per row
#define TILE_SZ (128 * TROW)           // 18432 B
#define STG_SZ  (4 * TILE_SZ)          // Ah, Al, Bh, Bl
#define MM_SMEM (3 * STG_SZ)           // 221184 B

__device__ __forceinline__ void load_chunk(uint32_t sb, int stage,
    const __nv_bfloat16* __restrict__ Ah, const __nv_bfloat16* __restrict__ Al,
    const __nv_bfloat16* __restrict__ Bh, const __nv_bfloat16* __restrict__ Bl,
    int K, int m0, int n0, int k0, int t)
{
    const uint32_t st = sb + (uint32_t)stage * STG_SZ;
    const __nv_bfloat16* gp[4] = {Ah, Al, Bh, Bl};
    const int rb[4] = {m0, m0, n0, n0};
#pragma unroll
    for (int tile = 0; tile < 4; tile++) {
        const __nv_bfloat16* g = gp[tile];
        const int r0 = rb[tile];
#pragma unroll
        for (int i = 0; i < 2; i++) {
            const int idx = (i << 9) + t;          // 0..1023 (512 threads x 2)
            const int row = idx >> 3, j = idx & 7; // 8 x 16B per 128B row
            cp16(st + (uint32_t)tile * TILE_SZ + row * TROW + j * 16,
                 g + (size_t)(r0 + row) * K + k0 + (j << 3));
        }
    }
}

template <int EPI>
__global__ __launch_bounds__(512, 1)
void mm_gemm(const __nv_bfloat16* __restrict__ Ah, const __nv_bfloat16* __restrict__ Al,
             const __nv_bfloat16* __restrict__ Bh, const __nv_bfloat16* __restrict__ Bl,
             float* __restrict__ C, int Ntot, int K,
             const float* __restrict__ bias, const int* __restrict__ usage)
{
    extern __shared__ char smem[];
    const uint32_t sb = su32(smem);
    const int t   = threadIdx.x;
    const int wid = t >> 5, l = t & 31;
    const int wm  = wid & 3;            // 4 warp-rows (32 m each)
    const int wn  = wid >> 2;           // 4 warp-cols (32 n each)
    const int m0  = blockIdx.y << 7, n0 = blockIdx.x << 7;

    // lane-dependent ldmatrix base offsets (bytes) inside a tile
    const uint32_t aoff = (uint32_t)(wm * 32 + (l & 7) + ((l >> 3) & 1) * 8) * TROW
                        + ((l >> 4) & 1) * 16;
    const uint32_t boff = (uint32_t)(wn * 32 + (l & 7) + ((l >> 4) & 1) * 8) * TROW
                        + ((l >> 3) & 1) * 16;

    float acc[2][4][4];
#pragma unroll
    for (int mf = 0; mf < 2; mf++)
#pragma unroll
        for (int nf = 0; nf < 4; nf++)
#pragma unroll
            for (int i = 0; i < 4; i++) acc[mf][nf][i] = 0.0f;

    const int nch = K / BK;

    load_chunk(sb, 0, Ah, Al, Bh, Bl, K, m0, n0, 0, t);  cp_commit();
    load_chunk(sb, 1, Ah, Al, Bh, Bl, K, m0, n0, BK, t); cp_commit();

    for (int c = 0; c < nch; c++) {
        cp_wait1();
        __syncthreads();
        if (c + 2 < nch)
            load_chunk(sb, (c + 2) % 3, Ah, Al, Bh, Bl, K, m0, n0, (c + 2) * BK, t);
        cp_commit();

        const uint32_t st = sb + (uint32_t)(c % 3) * STG_SZ;
#pragma unroll
        for (int ks = 0; ks < 4; ks++) {
            uint32_t ah[2][4], al[2][4], bh[2][4], bl[2][4];
#pragma unroll
            for (int mf = 0; mf < 2; mf++) {
                ldsm_x4(ah[mf], st + 0 * TILE_SZ + aoff + mf * (16 * TROW) + ks * 32);
                ldsm_x4(al[mf], st + 1 * TILE_SZ + aoff + mf * (16 * TROW) + ks * 32);
            }
#pragma unroll
            for (int nf2 = 0; nf2 < 2; nf2++) {
                ldsm_x4(bh[nf2], st + 2 * TILE_SZ + boff + nf2 * (16 * TROW) + ks * 32);
                ldsm_x4(bl[nf2], st + 3 * TILE_SZ + boff + nf2 * (16 * TROW) + ks * 32);
            }
#pragma unroll
            for (int mf = 0; mf < 2; mf++)
#pragma unroll
                for (int nf = 0; nf < 4; nf++) {
                    const uint32_t* bhp = &bh[nf >> 1][(nf & 1) * 2];
                    const uint32_t* blp = &bl[nf >> 1][(nf & 1) * 2];
                    mma16816(acc[mf][nf], ah[mf], bhp);
                    mma16816(acc[mf][nf], ah[mf], blp);
                    mma16816(acc[mf][nf], al[mf], bhp);
                }
        }
    }

    // Epilogue: c0,c1 at (row, col..col+1); c2,c3 at (row+8, ...)
#pragma unroll
    for (int mf = 0; mf < 2; mf++) {
        const int r0 = m0 + wm * 32 + mf * 16 + (l >> 2);
#pragma unroll
        for (int nf = 0; nf < 4; nf++) {
            const int c0 = n0 + wn * 32 + nf * 8 + ((l & 3) << 1);
            float v0 = acc[mf][nf][0], v1 = acc[mf][nf][1];
            float v2 = acc[mf][nf][2], v3 = acc[mf][nf][3];
            if (EPI == 1) {
                const float b0 = __ldg(bias + c0), b1 = __ldg(bias + c0 + 1);
                v0 += b0; v1 += b1; v2 += b0; v3 += b1;
            }
            if (EPI == 2) {
                const bool u0 = __ldg(usage + c0) > 0, u1 = __ldg(usage + c0 + 1) > 0;
                v0 = u0 ? v0 * INV_TEMP : -1e9f;  v1 = u1 ? v1 * INV_TEMP : -1e9f;
                v2 = u0 ? v2 * INV_TEMP : -1e9f;  v3 = u1 ? v3 * INV_TEMP : -1e9f;
            }
            *(float2*)(C + (size_t)r0 * Ntot + c0)       = make_float2(v0, v1);
            *(float2*)(C + (size_t)(r0 + 8) * Ntot + c0) = make_float2(v2, v3);
        }
    }
}

// ---------------------------------------------------------------------------
// Elementwise fp32 -> (hi, lo) bf16 split
// ---------------------------------------------------------------------------
__global__ void split_kernel(const float* __restrict__ in, __nv_bfloat16* __restrict__ oh,
                             __nv_bfloat16* __restrict__ ol, int n4)
{
    int idx = blockIdx.x * blockDim.x + threadIdx.x;
    const int stride = gridDim.x * blockDim.x;
    for (; idx < n4; idx += stride) {
        float4 v = ((const float4*)in)[idx];
        __nv_bfloat16 h0, l0, h1, l1, h2, l2, h3, l3;
        split1(v.x, h0, l0); split1(v.y, h1, l1); split1(v.z, h2, l2); split1(v.w, h3, l3);
        ((__nv_bfloat162*)oh)[idx * 2 + 0] = __halves2bfloat162(h0, h1);
        ((__nv_bfloat162*)oh)[idx * 2 + 1] = __halves2bfloat162(h2, h3);
        ((__nv_bfloat162*)ol)[idx * 2 + 0] = __halves2bfloat162(l0, l1);
        ((__nv_bfloat162*)ol)[idx * 2 + 1] = __halves2bfloat162(l2, l3);
    }
}

// ---------------------------------------------------------------------------
// Row L2-style normalize + split
// ---------------------------------------------------------------------------
__global__ void rownorm_split_kernel(const float* __restrict__ in,
                                     __nv_bfloat16* __restrict__ oh,
                                     __nv_bfloat16* __restrict__ ol)
{
    __shared__ float sh[4];
    const int row = blockIdx.x;
    const int tid = threadIdx.x;
    float4 v = ((const float4*)(in + (size_t)row * H_DIM))[tid];
    float s = v.x * v.x + v.y * v.y + v.z * v.z + v.w * v.w;
#pragma unroll
    for (int o = 16; o; o >>= 1) s += __shfl_xor_sync(0xffffffffu, s, o);
    if ((tid & 31) == 0) sh[tid >> 5] = s;
    __syncthreads();
    float r = rsqrtf(sh[0] + sh[1] + sh[2] + sh[3] + 1e-6f);
    __nv_bfloat16 h0, l0, h1, l1, h2, l2, h3, l3;
    split1(v.x * r, h0, l0); split1(v.y * r, h1, l1);
    split1(v.z * r, h2, l2); split1(v.w * r, h3, l3);
    const size_t off = (size_t)row * H_DIM + tid * 4;
    *(__nv_bfloat162*)(oh + off + 0) = __halves2bfloat162(h0, h1);
    *(__nv_bfloat162*)(oh + off + 2) = __halves2bfloat162(h2, h3);
    *(__nv_bfloat162*)(ol + off + 0) = __halves2bfloat162(l0, l1);
    *(__nv_bfloat162*)(ol + off + 2) = __halves2bfloat162(l2, l3);
}

// ---------------------------------------------------------------------------
// Softmax over M=4096 per row + bf16 hi/lo split output. 256 threads/row.
// ---------------------------------------------------------------------------
__global__ void softmax_split_kernel(const float* __restrict__ scores,
                                     __nv_bfloat16* __restrict__ oh,
                                     __nv_bfloat16* __restrict__ ol)
{
    __shared__ float sh[8];
    const int tid = threadIdx.x;
    const float4* p = (const float4*)(scores + (size_t)blockIdx.x * M_MEM);

    float4 v[4];
    float mx = -3.402823466e38f;
#pragma unroll
    for (int i = 0; i < 4; i++) {
        v[i] = p[tid + (i << 8)];
        mx = fmaxf(mx, fmaxf(fmaxf(v[i].x, v[i].y), fmaxf(v[i].z, v[i].w)));
    }
#pragma unroll
    for (int o = 16; o; o >>= 1) mx = fmaxf(mx, __shfl_xor_sync(0xffffffffu, mx, o));
    if ((tid & 31) == 0) sh[tid >> 5] = mx;
    __syncthreads();
    mx = sh[0];
#pragma unroll
    for (int i = 1; i < 8; i++) mx = fmaxf(mx, sh[i]);
    __syncthreads();

    float s = 0.0f;
#pragma unroll
    for (int i = 0; i < 4; i++) {
        v[i].x = __expf(v[i].x - mx); v[i].y = __expf(v[i].y - mx);
        v[i].z = __expf(v[i].z - mx); v[i].w = __expf(v[i].w - mx);
        s += v[i].x + v[i].y + v[i].z + v[i].w;
    }
#pragma unroll
    for (int o = 16; o; o >>= 1) s += __shfl_xor_sync(0xffffffffu, s, o);
    if ((tid & 31) == 0) sh[tid >> 5] = s;
    __syncthreads();
    float tot = sh[0];
#pragma unroll
    for (int i = 1; i < 8; i++) tot += sh[i];
    const float inv = 1.0f / tot;

#pragma unroll
    for (int i = 0; i < 4; i++) {
        const size_t off = (size_t)blockIdx.x * M_MEM + (size_t)(tid + (i << 8)) * 4;
        __nv_bfloat16 h0, l0, h1, l1, h2, l2, h3, l3;
        split1(v[i].x * inv, h0, l0); split1(v[i].y * inv, h1, l1);
        split1(v[i].z * inv, h2, l2); split1(v[i].w * inv, h3, l3);
        *(__nv_bfloat162*)(oh + off + 0) = __halves2bfloat162(h0, h1);
        *(__nv_bfloat162*)(oh + off + 2) = __halves2bfloat162(h2, h3);
        *(__nv_bfloat162*)(ol + off + 0) = __halves2bfloat162(l0, l1);
        *(__nv_bfloat162*)(ol + off + 2) = __halves2bfloat162(l2, l3);
    }
}

// ---------------------------------------------------------------------------
// Launch pipeline
// ---------------------------------------------------------------------------
extern "C" void kernel_launch(void* const* d_in, const int* in_sizes, int n_in,
                              void* d_out, int out_size)
{
    const float* hidden = (const float*)d_in[0];
    const float* mk     = (const float*)d_in[1];
    const float* mv     = (const float*)d_in[2];
    const float* Wk     = (const float*)d_in[3];
    const float* bk     = (const float*)d_in[4];
    const float* Wo     = (const float*)d_in[5];
    const float* bo     = (const float*)d_in[6];
    const int*   usage  = (const int*)d_in[7];
    float* out = (float*)d_out;

    __nv_bfloat16 *hid_hi, *hid_lo, *wk_hi, *wk_lo, *wo_hi, *wo_lo, *mv_hi, *mv_lo;
    __nv_bfloat16 *mk_hi, *mk_lo, *w2t_hi, *w2t_lo, *q_hi, *q_lo, *attn_hi, *attn_lo;
    float *w2t, *qp, *scp;
    cudaGetSymbolAddress((void**)&hid_hi, g_hid_hi);
    cudaGetSymbolAddress((void**)&hid_lo, g_hid_lo);
    cudaGetSymbolAddress((void**)&wk_hi, g_wk_hi);
    cudaGetSymbolAddress((void**)&wk_lo, g_wk_lo);
    cudaGetSymbolAddress((void**)&wo_hi, g_wo_hi);
    cudaGetSymbolAddress((void**)&wo_lo, g_wo_lo);
    cudaGetSymbolAddress((void**)&mv_hi, g_mv_hi);
    cudaGetSymbolAddress((void**)&mv_lo, g_mv_lo);
    cudaGetSymbolAddress((void**)&mk_hi, g_mk_hi);
    cudaGetSymbolAddress((void**)&mk_lo, g_mk_lo);
    cudaGetSymbolAddress((void**)&w2t, g_w2t);
    cudaGetSymbolAddress((void**)&w2t_hi, g_w2t_hi);
    cudaGetSymbolAddress((void**)&w2t_lo, g_w2t_lo);
    cudaGetSymbolAddress((void**)&qp, g_q);
    cudaGetSymbolAddress((void**)&q_hi, g_q_hi);
    cudaGetSymbolAddress((void**)&q_lo, g_q_lo);
    cudaGetSymbolAddress((void**)&scp, g_scores);
    cudaGetSymbolAddress((void**)&attn_hi, g_attn_hi);
    cudaGetSymbolAddress((void**)&attn_lo, g_attn_lo);

    cudaFuncSetAttribute(mm_gemm<0>, cudaFuncAttributeMaxDynamicSharedMemorySize, MM_SMEM);
    cudaFuncSetAttribute(mm_gemm<1>, cudaFuncAttributeMaxDynamicSharedMemorySize, MM_SMEM);
    cudaFuncSetAttribute(mm_gemm<2>, cudaFuncAttributeMaxDynamicSharedMemorySize, MM_SMEM);

    // inputs -> bf16 hi/lo splits
    split_kernel<<<2048, 256>>>(hidden, hid_hi, hid_lo, T_TOK * H_DIM / 4);
    split_kernel<<<256, 256>>>(Wk, wk_hi, wk_lo, H_DIM * H_DIM / 4);
    split_kernel<<<256, 256>>>(Wo, wo_hi, wo_lo, H_DIM * H_DIM / 4);
    split_kernel<<<1024, 256>>>(mv, mv_hi, mv_lo, M_MEM * H_DIM / 4);
    rownorm_split_kernel<<<M_MEM, 128>>>(mk, mk_hi, mk_lo);

    // W2T[h,m] = sum_v Wo[h,v] * mv[m,v]  (folds out-projection into retrieval)
    mm_gemm<0><<<dim3(M_MEM / 128, H_DIM / 128), 512, MM_SMEM>>>(
        wo_hi, wo_lo, mv_hi, mv_lo, w2t, M_MEM, H_DIM, nullptr, nullptr);
    split_kernel<<<2048, 256>>>(w2t, w2t_hi, w2t_lo, H_DIM * M_MEM / 4);

    // q = hidden @ Wk^T + bk  (HMMA split)
    mm_gemm<1><<<dim3(H_DIM / 128, T_TOK / 128), 512, MM_SMEM>>>(
        hid_hi, hid_lo, wk_hi, wk_lo, qp, H_DIM, H_DIM, bk, nullptr);
    rownorm_split_kernel<<<T_TOK, 128>>>(qp, q_hi, q_lo);

    // logits = mask_scale(q_n @ mk_n^T)
    mm_gemm<2><<<dim3(M_MEM / 128, T_TOK / 128), 512, MM_SMEM>>>(
        q_hi, q_lo, mk_hi, mk_lo, scp, M_MEM, H_DIM, nullptr, usage);

    // softmax rows -> attn hi/lo bf16
    softmax_split_kernel<<<T_TOK, 256>>>(scp, attn_hi, attn_lo);

    // out = attn @ W2T^T + bo
    mm_gemm<1><<<dim3(H_DIM / 128, T_TOK / 128), 512, MM_SMEM>>>(
        attn_hi, attn_lo, w2t_hi, w2t_lo, out, H_DIM, M_MEM, bo, nullptr);
}

// round 5
// speedup vs baseline: 1.0966x; 1.0966x over previous
#include <cuda_runtime.h>
#include <cuda_bf16.h>
#include <cstdint>

#define T_TOK 16384
#define H_DIM 512
#define M_MEM 4096
#define INV_TEMP 10.0f

// ---------------------------------------------------------------------------
// Scratch (static device globals; no allocations anywhere)
// ---------------------------------------------------------------------------
__device__ __nv_bfloat16 g_hid_hi[(size_t)T_TOK * H_DIM];
__device__ __nv_bfloat16 g_hid_lo[(size_t)T_TOK * H_DIM];
__device__ __nv_bfloat16 g_wk_hi[(size_t)H_DIM * H_DIM];
__device__ __nv_bfloat16 g_wk_lo[(size_t)H_DIM * H_DIM];
__device__ __nv_bfloat16 g_wo_hi[(size_t)H_DIM * H_DIM];
__device__ __nv_bfloat16 g_wo_lo[(size_t)H_DIM * H_DIM];
__device__ __nv_bfloat16 g_mv_hi[(size_t)M_MEM * H_DIM];
__device__ __nv_bfloat16 g_mv_lo[(size_t)M_MEM * H_DIM];
__device__ __nv_bfloat16 g_mk_hi[(size_t)M_MEM * H_DIM];
__device__ __nv_bfloat16 g_mk_lo[(size_t)M_MEM * H_DIM];
__device__ float         g_w2t[(size_t)H_DIM * M_MEM];      // W2T[h,m] = sum_v Wo[h,v] mv[m,v]
__device__ __nv_bfloat16 g_w2t_hi[(size_t)H_DIM * M_MEM];
__device__ __nv_bfloat16 g_w2t_lo[(size_t)H_DIM * M_MEM];
__device__ float         g_q[(size_t)T_TOK * H_DIM];
__device__ __nv_bfloat16 g_q_hi[(size_t)T_TOK * H_DIM];
__device__ __nv_bfloat16 g_q_lo[(size_t)T_TOK * H_DIM];
__device__ float         g_scores[(size_t)T_TOK * M_MEM];
__device__ __nv_bfloat16 g_attn_hi[(size_t)T_TOK * M_MEM];
__device__ __nv_bfloat16 g_attn_lo[(size_t)T_TOK * M_MEM];

// ---------------------------------------------------------------------------
// Helpers (baseline PTX only: cp.async / ldmatrix / mma.sync)
// ---------------------------------------------------------------------------
__device__ __forceinline__ uint32_t su32(const void* p) {
    return (uint32_t)__cvta_generic_to_shared(p);
}
__device__ __forceinline__ void cp16(uint32_t dst, const void* src) {
    asm volatile("cp.async.cg.shared.global [%0], [%1], 16;\n" :: "r"(dst), "l"(src) : "memory");
}
__device__ __forceinline__ void cp_commit() { asm volatile("cp.async.commit_group;\n" ::: "memory"); }
__device__ __forceinline__ void cp_wait1()  { asm volatile("cp.async.wait_group 1;\n" ::: "memory"); }

__device__ __forceinline__ void ldsm_x4(uint32_t* r, uint32_t addr) {
    asm volatile("ldmatrix.sync.aligned.m8n8.x4.shared.b16 {%0,%1,%2,%3}, [%4];"
                 : "=r"(r[0]), "=r"(r[1]), "=r"(r[2]), "=r"(r[3]) : "r"(addr));
}
__device__ __forceinline__ void mma16816(float* c, const uint32_t* a, const uint32_t* b) {
    asm volatile(
        "mma.sync.aligned.m16n8k16.row.col.f32.bf16.bf16.f32 "
        "{%0,%1,%2,%3}, {%4,%5,%6,%7}, {%8,%9}, {%0,%1,%2,%3};"
        : "+f"(c[0]), "+f"(c[1]), "+f"(c[2]), "+f"(c[3])
        : "r"(a[0]), "r"(a[1]), "r"(a[2]), "r"(a[3]), "r"(b[0]), "r"(b[1]));
}

__device__ __forceinline__ void split1(float x, __nv_bfloat16& h, __nv_bfloat16& l) {
    h = __float2bfloat16(x);
    l = __float2bfloat16(x - __bfloat162float(h));
}

// ---------------------------------------------------------------------------
// HMMA GEMM:  C[M,N] = split(A) @ split(B)^T   (A:[M,K], B:[N,K], bf16 hi/lo)
// CTA tile 128x256, 256 threads = 8 warps (2x4) of 64x64 tiles, BK=64,
// double-buffered cp.async. Ah*Bh + Ah*Bl + Al*Bh with fp32 accumulators.
// Warp tile 64x64 -> 24 MACs per SMEM byte (compute-bound vs 16 balance).
// EPI: 0 = plain, 1 = +bias[n], 2 = masked scale (scores).
// Requires M % 128 == 0, N % 256 == 0, K % 64 == 0.
// ---------------------------------------------------------------------------
#define BK       64
#define TROW     144                       // 128B data + 16B pad per row
#define A_TSZ    (128 * TROW)              // 18432 B
#define B_TSZ    (256 * TROW)              // 36864 B
#define STG_SZ   (2 * A_TSZ + 2 * B_TSZ)   // Ah, Al, Bh, Bl = 110592 B
#define MM_SMEM  (2 * STG_SZ)              // 221184 B

__device__ __forceinline__ void load_chunk(uint32_t sb, int stage,
    const __nv_bfloat16* __restrict__ Ah, const __nv_bfloat16* __restrict__ Al,
    const __nv_bfloat16* __restrict__ Bh, const __nv_bfloat16* __restrict__ Bl,
    int K, int m0, int n0, int k0, int t)
{
    const uint32_t st = sb + (uint32_t)stage * STG_SZ;
    // A tiles: 128 rows x 8 chunks of 16B = 1024 ops -> 4 iters of 256 threads
#pragma unroll
    for (int i = 0; i < 4; i++) {
        const int idx = (i << 8) + t;
        const int row = idx >> 3, j = idx & 7;
        const uint32_t so = (uint32_t)(row * TROW + j * 16);
        const size_t  go = (size_t)(m0 + row) * K + k0 + (j << 3);
        cp16(st + so, Ah + go);
        cp16(st + A_TSZ + so, Al + go);
    }
    // B tiles: 256 rows x 8 chunks = 2048 ops -> 8 iters
#pragma unroll
    for (int i = 0; i < 8; i++) {
        const int idx = (i << 8) + t;
        const int row = idx >> 3, j = idx & 7;
        const uint32_t so = (uint32_t)(row * TROW + j * 16);
        const size_t  go = (size_t)(n0 + row) * K + k0 + (j << 3);
        cp16(st + 2 * A_TSZ + so, Bh + go);
        cp16(st + 2 * A_TSZ + B_TSZ + so, Bl + go);
    }
}

template <int EPI>
__global__ __launch_bounds__(256, 1)
void mm_gemm(const __nv_bfloat16* __restrict__ Ah, const __nv_bfloat16* __restrict__ Al,
             const __nv_bfloat16* __restrict__ Bh, const __nv_bfloat16* __restrict__ Bl,
             float* __restrict__ C, int Ntot, int K,
             const float* __restrict__ bias, const int* __restrict__ usage)
{
    extern __shared__ char smem[];
    const uint32_t sb = su32(smem);
    const int t   = threadIdx.x;
    const int wid = t >> 5, l = t & 31;
    const int wm  = wid & 1;            // 2 warp-rows (64 m each)
    const int wn  = wid >> 1;           // 4 warp-cols (64 n each)
    const int m0  = blockIdx.y << 7, n0 = blockIdx.x << 8;

    // lane-dependent ldmatrix base offsets (bytes) inside a tile
    const uint32_t aoff = (uint32_t)(wm * 64 + (l & 7) + ((l >> 3) & 1) * 8) * TROW
                        + ((l >> 4) & 1) * 16;
    const uint32_t boff = (uint32_t)(wn * 64 + (l & 7) + ((l >> 4) & 1) * 8) * TROW
                        + ((l >> 3) & 1) * 16;

    float acc[4][8][4];
#pragma unroll
    for (int mf = 0; mf < 4; mf++)
#pragma unroll
        for (int nf = 0; nf < 8; nf++)
#pragma unroll
            for (int i = 0; i < 4; i++) acc[mf][nf][i] = 0.0f;

    const int nch = K / BK;

    load_chunk(sb, 0, Ah, Al, Bh, Bl, K, m0, n0, 0, t);  cp_commit();
    load_chunk(sb, 1, Ah, Al, Bh, Bl, K, m0, n0, BK, t); cp_commit();

    for (int c = 0; c < nch; c++) {
        cp_wait1();
        __syncthreads();
        const uint32_t st = sb + (uint32_t)(c & 1) * STG_SZ;
#pragma unroll
        for (int ks = 0; ks < 4; ks++) {
            uint32_t ah[4][4], al[4][4], bh[4][4], bl[4][4];
#pragma unroll
            for (int mf = 0; mf < 4; mf++) {
                ldsm_x4(ah[mf], st + aoff + mf * (16 * TROW) + ks * 32);
                ldsm_x4(al[mf], st + A_TSZ + aoff + mf * (16 * TROW) + ks * 32);
            }
#pragma unroll
            for (int nf2 = 0; nf2 < 4; nf2++) {
                ldsm_x4(bh[nf2], st + 2 * A_TSZ + boff + nf2 * (16 * TROW) + ks * 32);
                ldsm_x4(bl[nf2], st + 2 * A_TSZ + B_TSZ + boff + nf2 * (16 * TROW) + ks * 32);
            }
#pragma unroll
            for (int mf = 0; mf < 4; mf++)
#pragma unroll
                for (int nf = 0; nf < 8; nf++) {
                    const uint32_t* bhp = &bh[nf >> 1][(nf & 1) * 2];
                    const uint32_t* blp = &bl[nf >> 1][(nf & 1) * 2];
                    mma16816(acc[mf][nf], ah[mf], bhp);
                    mma16816(acc[mf][nf], ah[mf], blp);
                    mma16816(acc[mf][nf], al[mf], bhp);
                }
        }
        __syncthreads();   // all warps done reading this slot before overwrite
        if (c + 2 < nch)
            load_chunk(sb, c & 1, Ah, Al, Bh, Bl, K, m0, n0, (c + 2) * BK, t);
        cp_commit();       // keep group count aligned even when empty
    }

    // Epilogue: c0,c1 at (row, col..col+1); c2,c3 at (row+8, ...)
#pragma unroll
    for (int mf = 0; mf < 4; mf++) {
        const int r0 = m0 + wm * 64 + mf * 16 + (l >> 2);
#pragma unroll
        for (int nf = 0; nf < 8; nf++) {
            const int c0 = n0 + wn * 64 + nf * 8 + ((l & 3) << 1);
            float v0 = acc[mf][nf][0], v1 = acc[mf][nf][1];
            float v2 = acc[mf][nf][2], v3 = acc[mf][nf][3];
            if (EPI == 1) {
                const float b0 = __ldg(bias + c0), b1 = __ldg(bias + c0 + 1);
                v0 += b0; v1 += b1; v2 += b0; v3 += b1;
            }
            if (EPI == 2) {
                const bool u0 = __ldg(usage + c0) > 0, u1 = __ldg(usage + c0 + 1) > 0;
                v0 = u0 ? v0 * INV_TEMP : -1e9f;  v1 = u1 ? v1 * INV_TEMP : -1e9f;
                v2 = u0 ? v2 * INV_TEMP : -1e9f;  v3 = u1 ? v3 * INV_TEMP : -1e9f;
            }
            *(float2*)(C + (size_t)r0 * Ntot + c0)       = make_float2(v0, v1);
            *(float2*)(C + (size_t)(r0 + 8) * Ntot + c0) = make_float2(v2, v3);
        }
    }
}

// ---------------------------------------------------------------------------
// Elementwise fp32 -> (hi, lo) bf16 split
// ---------------------------------------------------------------------------
__global__ void split_kernel(const float* __restrict__ in, __nv_bfloat16* __restrict__ oh,
                             __nv_bfloat16* __restrict__ ol, int n4)
{
    int idx = blockIdx.x * blockDim.x + threadIdx.x;
    const int stride = gridDim.x * blockDim.x;
    for (; idx < n4; idx += stride) {
        float4 v = ((const float4*)in)[idx];
        __nv_bfloat16 h0, l0, h1, l1, h2, l2, h3, l3;
        split1(v.x, h0, l0); split1(v.y, h1, l1); split1(v.z, h2, l2); split1(v.w, h3, l3);
        ((__nv_bfloat162*)oh)[idx * 2 + 0] = __halves2bfloat162(h0, h1);
        ((__nv_bfloat162*)oh)[idx * 2 + 1] = __halves2bfloat162(h2, h3);
        ((__nv_bfloat162*)ol)[idx * 2 + 0] = __halves2bfloat162(l0, l1);
        ((__nv_bfloat162*)ol)[idx * 2 + 1] = __halves2bfloat162(l2, l3);
    }
}

// ---------------------------------------------------------------------------
// Row L2-style normalize + split
// ---------------------------------------------------------------------------
__global__ void rownorm_split_kernel(const float* __restrict__ in,
                                     __nv_bfloat16* __restrict__ oh,
                                     __nv_bfloat16* __restrict__ ol)
{
    __shared__ float sh[4];
    const int row = blockIdx.x;
    const int tid = threadIdx.x;
    float4 v = ((const float4*)(in + (size_t)row * H_DIM))[tid];
    float s = v.x * v.x + v.y * v.y + v.z * v.z + v.w * v.w;
#pragma unroll
    for (int o = 16; o; o >>= 1) s += __shfl_xor_sync(0xffffffffu, s, o);
    if ((tid & 31) == 0) sh[tid >> 5] = s;
    __syncthreads();
    float r = rsqrtf(sh[0] + sh[1] + sh[2] + sh[3] + 1e-6f);
    __nv_bfloat16 h0, l0, h1, l1, h2, l2, h3, l3;
    split1(v.x * r, h0, l0); split1(v.y * r, h1, l1);
    split1(v.z * r, h2, l2); split1(v.w * r, h3, l3);
    const size_t off = (size_t)row * H_DIM + tid * 4;
    *(__nv_bfloat162*)(oh + off + 0) = __halves2bfloat162(h0, h1);
    *(__nv_bfloat162*)(oh + off + 2) = __halves2bfloat162(h2, h3);
    *(__nv_bfloat162*)(ol + off + 0) = __halves2bfloat162(l0, l1);
    *(__nv_bfloat162*)(ol + off + 2) = __halves2bfloat162(l2, l3);
}

// ---------------------------------------------------------------------------
// Softmax over M=4096 per row + bf16 hi/lo split output. 256 threads/row.
// ---------------------------------------------------------------------------
__global__ void softmax_split_kernel(const float* __restrict__ scores,
                                     __nv_bfloat16* __restrict__ oh,
                                     __nv_bfloat16* __restrict__ ol)
{
    __shared__ float sh[8];
    const int tid = threadIdx.x;
    const float4* p = (const float4*)(scores + (size_t)blockIdx.x * M_MEM);

    float4 v[4];
    float mx = -3.402823466e38f;
#pragma unroll
    for (int i = 0; i < 4; i++) {
        v[i] = p[tid + (i << 8)];
        mx = fmaxf(mx, fmaxf(fmaxf(v[i].x, v[i].y), fmaxf(v[i].z, v[i].w)));
    }
#pragma unroll
    for (int o = 16; o; o >>= 1) mx = fmaxf(mx, __shfl_xor_sync(0xffffffffu, mx, o));
    if ((tid & 31) == 0) sh[tid >> 5] = mx;
    __syncthreads();
    mx = sh[0];
#pragma unroll
    for (int i = 1; i < 8; i++) mx = fmaxf(mx, sh[i]);
    __syncthreads();

    float s = 0.0f;
#pragma unroll
    for (int i = 0; i < 4; i++) {
        v[i].x = __expf(v[i].x - mx); v[i].y = __expf(v[i].y - mx);
        v[i].z = __expf(v[i].z - mx); v[i].w = __expf(v[i].w - mx);
        s += v[i].x + v[i].y + v[i].z + v[i].w;
    }
#pragma unroll
    for (int o = 16; o; o >>= 1) s += __shfl_xor_sync(0xffffffffu, s, o);
    if ((tid & 31) == 0) sh[tid >> 5] = s;
    __syncthreads();
    float tot = sh[0];
#pragma unroll
    for (int i = 1; i < 8; i++) tot += sh[i];
    const float inv = 1.0f / tot;

#pragma unroll
    for (int i = 0; i < 4; i++) {
        const size_t off = (size_t)blockIdx.x * M_MEM + (size_t)(tid + (i << 8)) * 4;
        __nv_bfloat16 h0, l0, h1, l1, h2, l2, h3, l3;
        split1(v[i].x * inv, h0, l0); split1(v[i].y * inv, h1, l1);
        split1(v[i].z * inv, h2, l2); split1(v[i].w * inv, h3, l3);
        *(__nv_bfloat162*)(oh + off + 0) = __halves2bfloat162(h0, h1);
        *(__nv_bfloat162*)(oh + off + 2) = __halves2bfloat162(h2, h3);
        *(__nv_bfloat162*)(ol + off + 0) = __halves2bfloat162(l0, l1);
        *(__nv_bfloat162*)(ol + off + 2) = __halves2bfloat162(l2, l3);
    }
}

// ---------------------------------------------------------------------------
// Launch pipeline
// ---------------------------------------------------------------------------
extern "C" void kernel_launch(void* const* d_in, const int* in_sizes, int n_in,
                              void* d_out, int out_size)
{
    const float* hidden = (const float*)d_in[0];
    const float* mk     = (const float*)d_in[1];
    const float* mv     = (const float*)d_in[2];
    const float* Wk     = (const float*)d_in[3];
    const float* bk     = (const float*)d_in[4];
    const float* Wo     = (const float*)d_in[5];
    const float* bo     = (const float*)d_in[6];
    const int*   usage  = (const int*)d_in[7];
    float* out = (float*)d_out;

    __nv_bfloat16 *hid_hi, *hid_lo, *wk_hi, *wk_lo, *wo_hi, *wo_lo, *mv_hi, *mv_lo;
    __nv_bfloat16 *mk_hi, *mk_lo, *w2t_hi, *w2t_lo, *q_hi, *q_lo, *attn_hi, *attn_lo;
    float *w2t, *qp, *scp;
    cudaGetSymbolAddress((void**)&hid_hi, g_hid_hi);
    cudaGetSymbolAddress((void**)&hid_lo, g_hid_lo);
    cudaGetSymbolAddress((void**)&wk_hi, g_wk_hi);
    cudaGetSymbolAddress((void**)&wk_lo, g_wk_lo);
    cudaGetSymbolAddress((void**)&wo_hi, g_wo_hi);
    cudaGetSymbolAddress((void**)&wo_lo, g_wo_lo);
    cudaGetSymbolAddress((void**)&mv_hi, g_mv_hi);
    cudaGetSymbolAddress((void**)&mv_lo, g_mv_lo);
    cudaGetSymbolAddress((void**)&mk_hi, g_mk_hi);
    cudaGetSymbolAddress((void**)&mk_lo, g_mk_lo);
    cudaGetSymbolAddress((void**)&w2t, g_w2t);
    cudaGetSymbolAddress((void**)&w2t_hi, g_w2t_hi);
    cudaGetSymbolAddress((void**)&w2t_lo, g_w2t_lo);
    cudaGetSymbolAddress((void**)&qp, g_q);
    cudaGetSymbolAddress((void**)&q_hi, g_q_hi);
    cudaGetSymbolAddress((void**)&q_lo, g_q_lo);
    cudaGetSymbolAddress((void**)&scp, g_scores);
    cudaGetSymbolAddress((void**)&attn_hi, g_attn_hi);
    cudaGetSymbolAddress((void**)&attn_lo, g_attn_lo);

    cudaFuncSetAttribute(mm_gemm<0>, cudaFuncAttributeMaxDynamicSharedMemorySize, MM_SMEM);
    cudaFuncSetAttribute(mm_gemm<1>, cudaFuncAttributeMaxDynamicSharedMemorySize, MM_SMEM);
    cudaFuncSetAttribute(mm_gemm<2>, cudaFuncAttributeMaxDynamicSharedMemorySize, MM_SMEM);

    // inputs -> bf16 hi/lo splits
    split_kernel<<<2048, 256>>>(hidden, hid_hi, hid_lo, T_TOK * H_DIM / 4);
    split_kernel<<<256, 256>>>(Wk, wk_hi, wk_lo, H_DIM * H_DIM / 4);
    split_kernel<<<256, 256>>>(Wo, wo_hi, wo_lo, H_DIM * H_DIM / 4);
    split_kernel<<<1024, 256>>>(mv, mv_hi, mv_lo, M_MEM * H_DIM / 4);
    rownorm_split_kernel<<<M_MEM, 128>>>(mk, mk_hi, mk_lo);

    // W2T[h,m] = sum_v Wo[h,v] * mv[m,v]  (folds out-projection into retrieval)
    mm_gemm<0><<<dim3(M_MEM / 256, H_DIM / 128), 256, MM_SMEM>>>(
        wo_hi, wo_lo, mv_hi, mv_lo, w2t, M_MEM, H_DIM, nullptr, nullptr);
    split_kernel<<<2048, 256>>>(w2t, w2t_hi, w2t_lo, H_DIM * M_MEM / 4);

    // q = hidden @ Wk^T + bk  (HMMA split)
    mm_gemm<1><<<dim3(H_DIM / 256, T_TOK / 128), 256, MM_SMEM>>>(
        hid_hi, hid_lo, wk_hi, wk_lo, qp, H_DIM, H_DIM, bk, nullptr);
    rownorm_split_kernel<<<T_TOK, 128>>>(qp, q_hi, q_lo);

    // logits = mask_scale(q_n @ mk_n^T)
    mm_gemm<2><<<dim3(M_MEM / 256, T_TOK / 128), 256, MM_SMEM>>>(
        q_hi, q_lo, mk_hi, mk_lo, scp, M_MEM, H_DIM, nullptr, usage);

    // softmax rows -> attn hi/lo bf16
    softmax_split_kernel<<<T_TOK, 256>>>(scp, attn_hi, attn_lo);

    // out = attn @ W2T^T + bo
    mm_gemm<1><<<dim3(H_DIM / 256, T_TOK / 128), 256, MM_SMEM>>>(
        attn_hi, attn_lo, w2t_hi, w2t_lo, out, H_DIM, M_MEM, bo, nullptr);
}

// round 6
// speedup vs baseline: 1.4573x; 1.3290x over previous
#include <cuda_runtime.h>
#include <cuda_fp16.h>
#include <cstdint>

#define T_TOK 16384
#define H_DIM 512
#define M_MEM 4096
#define INV_TEMP 10.0f
#define ATTN_SCALE 256.0f

// ---------------------------------------------------------------------------
// Scratch (static device globals; no allocations anywhere)
// ---------------------------------------------------------------------------
__device__ __half g_hid_hi[(size_t)T_TOK * H_DIM];
__device__ __half g_hid_lo[(size_t)T_TOK * H_DIM];
__device__ __half g_wk_hi[(size_t)H_DIM * H_DIM];
__device__ __half g_wk_lo[(size_t)H_DIM * H_DIM];
__device__ __half g_wo_hi[(size_t)H_DIM * H_DIM];
__device__ __half g_wo_lo[(size_t)H_DIM * H_DIM];
__device__ __half g_mv_hi[(size_t)M_MEM * H_DIM];
__device__ __half g_mv_lo[(size_t)M_MEM * H_DIM];
__device__ __half g_mk_hi[(size_t)M_MEM * H_DIM];
__device__ __half g_mk_lo[(size_t)M_MEM * H_DIM];
__device__ float  g_w2t[(size_t)H_DIM * M_MEM];     // W2T[h,m] = sum_v Wo[h,v] mv[m,v]
__device__ __half g_w2t_hi[(size_t)H_DIM * M_MEM];
__device__ __half g_w2t_lo[(size_t)H_DIM * M_MEM];
__device__ float  g_q[(size_t)T_TOK * H_DIM];
__device__ __half g_q_hi[(size_t)T_TOK * H_DIM];
__device__ float  g_scores[(size_t)T_TOK * M_MEM];
__device__ __half g_attn_hi[(size_t)T_TOK * M_MEM]; // attn * 256

// ---------------------------------------------------------------------------
// Helpers (baseline PTX only: cp.async / ldmatrix / mma.sync)
// ---------------------------------------------------------------------------
__device__ __forceinline__ uint32_t su32(const void* p) {
    return (uint32_t)__cvta_generic_to_shared(p);
}
__device__ __forceinline__ void cp16(uint32_t dst, const void* src) {
    asm volatile("cp.async.cg.shared.global [%0], [%1], 16;\n" :: "r"(dst), "l"(src) : "memory");
}
__device__ __forceinline__ void cp_commit() { asm volatile("cp.async.commit_group;\n" ::: "memory"); }
__device__ __forceinline__ void cp_wait1()  { asm volatile("cp.async.wait_group 1;\n" ::: "memory"); }

__device__ __forceinline__ void ldsm_x4(uint32_t* r, uint32_t addr) {
    asm volatile("ldmatrix.sync.aligned.m8n8.x4.shared.b16 {%0,%1,%2,%3}, [%4];"
                 : "=r"(r[0]), "=r"(r[1]), "=r"(r[2]), "=r"(r[3]) : "r"(addr));
}
__device__ __forceinline__ void mma16816(float* c, const uint32_t* a, const uint32_t* b) {
    asm volatile(
        "mma.sync.aligned.m16n8k16.row.col.f32.f16.f16.f32 "
        "{%0,%1,%2,%3}, {%4,%5,%6,%7}, {%8,%9}, {%0,%1,%2,%3};"
        : "+f"(c[0]), "+f"(c[1]), "+f"(c[2]), "+f"(c[3])
        : "r"(a[0]), "r"(a[1]), "r"(a[2]), "r"(a[3]), "r"(b[0]), "r"(b[1]));
}

__device__ __forceinline__ void split1(float x, __half& h, __half& l) {
    h = __float2half_rn(x);
    l = __float2half_rn(x - __half2float(h));
}

// ---------------------------------------------------------------------------
// HMMA GEMM:  C[M,N] = split(A) @ split(B)^T   (A:[M,K], B:[N,K], fp16)
// CTA tile 128x256, 256 threads = 8 warps (2x4) of 64x64 tiles, BK=64,
// double-buffered cp.async, fp32 accumulators.
// TERMS=2: Ah*Bh + Ah*Bl (A single array); TERMS=3: + Al*Bh.
// EPI: 0 plain, 1 +bias[n], 2 masked scale (scores), 3 *(1/256) + bias[n].
// Requires M % 128 == 0, N % 256 == 0, K % 64 == 0.
// ---------------------------------------------------------------------------
#define BK       64
#define TROW     144                       // 128B data + 16B pad per row
#define A_TSZ    (128 * TROW)              // 18432 B
#define B_TSZ    (256 * TROW)              // 36864 B

template <int TERMS>
__device__ __forceinline__ void load_chunk(uint32_t st,
    const __half* __restrict__ Ah, const __half* __restrict__ Al,
    const __half* __restrict__ Bh, const __half* __restrict__ Bl,
    int K, int m0, int n0, int k0, int t)
{
    // A tile(s): 128 rows x 8 chunks of 16B = 1024 ops -> 4 iters of 256 threads
#pragma unroll
    for (int i = 0; i < 4; i++) {
        const int idx = (i << 8) + t;
        const int row = idx >> 3, j = idx & 7;
        const uint32_t so = (uint32_t)(row * TROW + j * 16);
        const size_t  go = (size_t)(m0 + row) * K + k0 + (j << 3);
        cp16(st + so, Ah + go);
        if (TERMS == 3) cp16(st + A_TSZ + so, Al + go);
    }
    // B tiles: 256 rows x 8 chunks = 2048 ops -> 8 iters
    const uint32_t bb = st + (TERMS == 3 ? 2 : 1) * A_TSZ;
#pragma unroll
    for (int i = 0; i < 8; i++) {
        const int idx = (i << 8) + t;
        const int row = idx >> 3, j = idx & 7;
        const uint32_t so = (uint32_t)(row * TROW + j * 16);
        const size_t  go = (size_t)(n0 + row) * K + k0 + (j << 3);
        cp16(bb + so, Bh + go);
        cp16(bb + B_TSZ + so, Bl + go);
    }
}

template <int EPI, int TERMS>
__global__ __launch_bounds__(256, 1)
void mm_gemm(const __half* __restrict__ Ah, const __half* __restrict__ Al,
             const __half* __restrict__ Bh, const __half* __restrict__ Bl,
             float* __restrict__ C, int Ntot, int K,
             const float* __restrict__ bias, const int* __restrict__ usage)
{
    constexpr uint32_t STG = (TERMS == 3 ? 2 : 1) * A_TSZ + 2 * B_TSZ;
    extern __shared__ char smem[];
    const uint32_t sb = su32(smem);
    const int t   = threadIdx.x;
    const int wid = t >> 5, l = t & 31;
    const int wm  = wid & 1;            // 2 warp-rows (64 m each)
    const int wn  = wid >> 1;           // 4 warp-cols (64 n each)
    const int m0  = blockIdx.y << 7, n0 = blockIdx.x << 8;

    const uint32_t aoff = (uint32_t)(wm * 64 + (l & 7) + ((l >> 3) & 1) * 8) * TROW
                        + ((l >> 4) & 1) * 16;
    const uint32_t boff = (uint32_t)(wn * 64 + (l & 7) + ((l >> 4) & 1) * 8) * TROW
                        + ((l >> 3) & 1) * 16;
    const uint32_t bbase = (TERMS == 3 ? 2 : 1) * A_TSZ;

    float acc[4][8][4];
#pragma unroll
    for (int mf = 0; mf < 4; mf++)
#pragma unroll
        for (int nf = 0; nf < 8; nf++)
#pragma unroll
            for (int i = 0; i < 4; i++) acc[mf][nf][i] = 0.0f;

    const int nch = K / BK;

    load_chunk<TERMS>(sb, Ah, Al, Bh, Bl, K, m0, n0, 0, t);        cp_commit();
    load_chunk<TERMS>(sb + STG, Ah, Al, Bh, Bl, K, m0, n0, BK, t); cp_commit();

    for (int c = 0; c < nch; c++) {
        cp_wait1();
        __syncthreads();
        const uint32_t st = sb + (uint32_t)(c & 1) * STG;
#pragma unroll
        for (int ks = 0; ks < 4; ks++) {
            uint32_t ah[4][4], al[4][4], bh[4][4], bl[4][4];
#pragma unroll
            for (int mf = 0; mf < 4; mf++) {
                ldsm_x4(ah[mf], st + aoff + mf * (16 * TROW) + ks * 32);
                if (TERMS == 3)
                    ldsm_x4(al[mf], st + A_TSZ + aoff + mf * (16 * TROW) + ks * 32);
            }
#pragma unroll
            for (int nf2 = 0; nf2 < 4; nf2++) {
                ldsm_x4(bh[nf2], st + bbase + boff + nf2 * (16 * TROW) + ks * 32);
                ldsm_x4(bl[nf2], st + bbase + B_TSZ + boff + nf2 * (16 * TROW) + ks * 32);
            }
#pragma unroll
            for (int mf = 0; mf < 4; mf++)
#pragma unroll
                for (int nf = 0; nf < 8; nf++) {
                    const uint32_t* bhp = &bh[nf >> 1][(nf & 1) * 2];
                    const uint32_t* blp = &bl[nf >> 1][(nf & 1) * 2];
                    mma16816(acc[mf][nf], ah[mf], bhp);
                    mma16816(acc[mf][nf], ah[mf], blp);
                    if (TERMS == 3) mma16816(acc[mf][nf], al[mf], bhp);
                }
        }
        __syncthreads();   // all warps done reading this slot before overwrite
        if (c + 2 < nch)
            load_chunk<TERMS>(sb + (uint32_t)(c & 1) * STG, Ah, Al, Bh, Bl,
                              K, m0, n0, (c + 2) * BK, t);
        cp_commit();       // keep group count aligned even when empty
    }

    // Epilogue: c0,c1 at (row, col..col+1); c2,c3 at (row+8, ...)
#pragma unroll
    for (int mf = 0; mf < 4; mf++) {
        const int r0 = m0 + wm * 64 + mf * 16 + (l >> 2);
#pragma unroll
        for (int nf = 0; nf < 8; nf++) {
            const int c0 = n0 + wn * 64 + nf * 8 + ((l & 3) << 1);
            float v0 = acc[mf][nf][0], v1 = acc[mf][nf][1];
            float v2 = acc[mf][nf][2], v3 = acc[mf][nf][3];
            if (EPI == 1) {
                const float b0 = __ldg(bias + c0), b1 = __ldg(bias + c0 + 1);
                v0 += b0; v1 += b1; v2 += b0; v3 += b1;
            }
            if (EPI == 2) {
                const bool u0 = __ldg(usage + c0) > 0, u1 = __ldg(usage + c0 + 1) > 0;
                v0 = u0 ? v0 * INV_TEMP : -1e9f;  v1 = u1 ? v1 * INV_TEMP : -1e9f;
                v2 = u0 ? v2 * INV_TEMP : -1e9f;  v3 = u1 ? v3 * INV_TEMP : -1e9f;
            }
            if (EPI == 3) {
                const float b0 = __ldg(bias + c0), b1 = __ldg(bias + c0 + 1);
                const float s = 1.0f / ATTN_SCALE;
                v0 = fmaf(v0, s, b0); v1 = fmaf(v1, s, b1);
                v2 = fmaf(v2, s, b0); v3 = fmaf(v3, s, b1);
            }
            *(float2*)(C + (size_t)r0 * Ntot + c0)       = make_float2(v0, v1);
            *(float2*)(C + (size_t)(r0 + 8) * Ntot + c0) = make_float2(v2, v3);
        }
    }
}

// ---------------------------------------------------------------------------
// Elementwise fp32 -> (hi, lo) fp16 split
// ---------------------------------------------------------------------------
__global__ void split_kernel(const float* __restrict__ in, __half* __restrict__ oh,
                             __half* __restrict__ ol, int n4)
{
    int idx = blockIdx.x * blockDim.x + threadIdx.x;
    const int stride = gridDim.x * blockDim.x;
    for (; idx < n4; idx += stride) {
        float4 v = ((const float4*)in)[idx];
        __half h0, l0, h1, l1, h2, l2, h3, l3;
        split1(v.x, h0, l0); split1(v.y, h1, l1); split1(v.z, h2, l2); split1(v.w, h3, l3);
        ((__half2*)oh)[idx * 2 + 0] = __halves2half2(h0, h1);
        ((__half2*)oh)[idx * 2 + 1] = __halves2half2(h2, h3);
        ((__half2*)ol)[idx * 2 + 0] = __halves2half2(l0, l1);
        ((__half2*)ol)[idx * 2 + 1] = __halves2half2(l2, l3);
    }
}

// ---------------------------------------------------------------------------
// Row L2-style normalize + fp16 hi/lo split (for memory keys)
// ---------------------------------------------------------------------------
__global__ void rownorm_split_kernel(const float* __restrict__ in,
                                     __half* __restrict__ oh, __half* __restrict__ ol)
{
    __shared__ float sh[4];
    const int row = blockIdx.x;
    const int tid = threadIdx.x;
    float4 v = ((const float4*)(in + (size_t)row * H_DIM))[tid];
    float s = v.x * v.x + v.y * v.y + v.z * v.z + v.w * v.w;
#pragma unroll
    for (int o = 16; o; o >>= 1) s += __shfl_xor_sync(0xffffffffu, s, o);
    if ((tid & 31) == 0) sh[tid >> 5] = s;
    __syncthreads();
    float r = rsqrtf(sh[0] + sh[1] + sh[2] + sh[3] + 1e-6f);
    __half h0, l0, h1, l1, h2, l2, h3, l3;
    split1(v.x * r, h0, l0); split1(v.y * r, h1, l1);
    split1(v.z * r, h2, l2); split1(v.w * r, h3, l3);
    const size_t off = (size_t)row * H_DIM + tid * 4;
    *(__half2*)(oh + off + 0) = __halves2half2(h0, h1);
    *(__half2*)(oh + off + 2) = __halves2half2(h2, h3);
    *(__half2*)(ol + off + 0) = __halves2half2(l0, l1);
    *(__half2*)(ol + off + 2) = __halves2half2(l2, l3);
}

// ---------------------------------------------------------------------------
// Row L2-style normalize, fp16 hi only (for q)
// ---------------------------------------------------------------------------
__global__ void rownorm_hi_kernel(const float* __restrict__ in, __half* __restrict__ oh)
{
    __shared__ float sh[4];
    const int row = blockIdx.x;
    const int tid = threadIdx.x;
    float4 v = ((const float4*)(in + (size_t)row * H_DIM))[tid];
    float s = v.x * v.x + v.y * v.y + v.z * v.z + v.w * v.w;
#pragma unroll
    for (int o = 16; o; o >>= 1) s += __shfl_xor_sync(0xffffffffu, s, o);
    if ((tid & 31) == 0) sh[tid >> 5] = s;
    __syncthreads();
    float r = rsqrtf(sh[0] + sh[1] + sh[2] + sh[3] + 1e-6f);
    const size_t off = (size_t)row * H_DIM + tid * 4;
    *(__half2*)(oh + off + 0) = __halves2half2(__float2half_rn(v.x * r), __float2half_rn(v.y * r));
    *(__half2*)(oh + off + 2) = __halves2half2(__float2half_rn(v.z * r), __float2half_rn(v.w * r));
}

// ---------------------------------------------------------------------------
// Softmax over M=4096 per row -> fp16 (attn * 256). 256 threads/row.
// ---------------------------------------------------------------------------
__global__ void softmax_kernel(const float* __restrict__ scores, __half* __restrict__ oh)
{
    __shared__ float sh[8];
    const int tid = threadIdx.x;
    const float4* p = (const float4*)(scores + (size_t)blockIdx.x * M_MEM);

    float4 v[4];
    float mx = -3.402823466e38f;
#pragma unroll
    for (int i = 0; i < 4; i++) {
        v[i] = p[tid + (i << 8)];
        mx = fmaxf(mx, fmaxf(fmaxf(v[i].x, v[i].y), fmaxf(v[i].z, v[i].w)));
    }
#pragma unroll
    for (int o = 16; o; o >>= 1) mx = fmaxf(mx, __shfl_xor_sync(0xffffffffu, mx, o));
    if ((tid & 31) == 0) sh[tid >> 5] = mx;
    __syncthreads();
    mx = sh[0];
#pragma unroll
    for (int i = 1; i < 8; i++) mx = fmaxf(mx, sh[i]);
    __syncthreads();

    float s = 0.0f;
#pragma unroll
    for (int i = 0; i < 4; i++) {
        v[i].x = __expf(v[i].x - mx); v[i].y = __expf(v[i].y - mx);
        v[i].z = __expf(v[i].z - mx); v[i].w = __expf(v[i].w - mx);
        s += v[i].x + v[i].y + v[i].z + v[i].w;
    }
#pragma unroll
    for (int o = 16; o; o >>= 1) s += __shfl_xor_sync(0xffffffffu, s, o);
    if ((tid & 31) == 0) sh[tid >> 5] = s;
    __syncthreads();
    float tot = sh[0];
#pragma unroll
    for (int i = 1; i < 8; i++) tot += sh[i];
    const float inv = ATTN_SCALE / tot;

#pragma unroll
    for (int i = 0; i < 4; i++) {
        const size_t off = (size_t)blockIdx.x * M_MEM + (size_t)(tid + (i << 8)) * 4;
        *(__half2*)(oh + off + 0) = __halves2half2(__float2half_rn(v[i].x * inv),
                                                   __float2half_rn(v[i].y * inv));
        *(__half2*)(oh + off + 2) = __halves2half2(__float2half_rn(v[i].z * inv),
                                                   __float2half_rn(v[i].w * inv));
    }
}

// ---------------------------------------------------------------------------
// Launch pipeline
// ---------------------------------------------------------------------------
#define MM_SMEM2 (2 * (A_TSZ + 2 * B_TSZ))      // 184320
#define MM_SMEM3 (2 * (2 * A_TSZ + 2 * B_TSZ))  // 221184

extern "C" void kernel_launch(void* const* d_in, const int* in_sizes, int n_in,
                              void* d_out, int out_size)
{
    const float* hidden = (const float*)d_in[0];
    const float* mk     = (const float*)d_in[1];
    const float* mv     = (const float*)d_in[2];
    const float* Wk     = (const float*)d_in[3];
    const float* bk     = (const float*)d_in[4];
    const float* Wo     = (const float*)d_in[5];
    const float* bo     = (const float*)d_in[6];
    const int*   usage  = (const int*)d_in[7];
    float* out = (float*)d_out;

    __half *hid_hi, *hid_lo, *wk_hi, *wk_lo, *wo_hi, *wo_lo, *mv_hi, *mv_lo;
    __half *mk_hi, *mk_lo, *w2t_hi, *w2t_lo, *q_hi, *attn_hi;
    float *w2t, *qp, *scp;
    cudaGetSymbolAddress((void**)&hid_hi, g_hid_hi);
    cudaGetSymbolAddress((void**)&hid_lo, g_hid_lo);
    cudaGetSymbolAddress((void**)&wk_hi, g_wk_hi);
    cudaGetSymbolAddress((void**)&wk_lo, g_wk_lo);
    cudaGetSymbolAddress((void**)&wo_hi, g_wo_hi);
    cudaGetSymbolAddress((void**)&wo_lo, g_wo_lo);
    cudaGetSymbolAddress((void**)&mv_hi, g_mv_hi);
    cudaGetSymbolAddress((void**)&mv_lo, g_mv_lo);
    cudaGetSymbolAddress((void**)&mk_hi, g_mk_hi);
    cudaGetSymbolAddress((void**)&mk_lo, g_mk_lo);
    cudaGetSymbolAddress((void**)&w2t, g_w2t);
    cudaGetSymbolAddress((void**)&w2t_hi, g_w2t_hi);
    cudaGetSymbolAddress((void**)&w2t_lo, g_w2t_lo);
    cudaGetSymbolAddress((void**)&qp, g_q);
    cudaGetSymbolAddress((void**)&q_hi, g_q_hi);
    cudaGetSymbolAddress((void**)&scp, g_scores);
    cudaGetSymbolAddress((void**)&attn_hi, g_attn_hi);

    cudaFuncSetAttribute(mm_gemm<0,3>, cudaFuncAttributeMaxDynamicSharedMemorySize, MM_SMEM3);
    cudaFuncSetAttribute(mm_gemm<1,3>, cudaFuncAttributeMaxDynamicSharedMemorySize, MM_SMEM3);
    cudaFuncSetAttribute(mm_gemm<2,2>, cudaFuncAttributeMaxDynamicSharedMemorySize, MM_SMEM2);
    cudaFuncSetAttribute(mm_gemm<3,2>, cudaFuncAttributeMaxDynamicSharedMemorySize, MM_SMEM2);

    // inputs -> fp16 hi/lo splits
    split_kernel<<<2048, 256>>>(hidden, hid_hi, hid_lo, T_TOK * H_DIM / 4);
    split_kernel<<<256, 256>>>(Wk, wk_hi, wk_lo, H_DIM * H_DIM / 4);
    split_kernel<<<256, 256>>>(Wo, wo_hi, wo_lo, H_DIM * H_DIM / 4);
    split_kernel<<<1024, 256>>>(mv, mv_hi, mv_lo, M_MEM * H_DIM / 4);
    rownorm_split_kernel<<<M_MEM, 128>>>(mk, mk_hi, mk_lo);

    // W2T[h,m] = sum_v Wo[h,v] * mv[m,v]  (folds out-projection into retrieval)
    mm_gemm<0,3><<<dim3(M_MEM / 256, H_DIM / 128), 256, MM_SMEM3>>>(
        wo_hi, wo_lo, mv_hi, mv_lo, w2t, M_MEM, H_DIM, nullptr, nullptr);
    split_kernel<<<2048, 256>>>(w2t, w2t_hi, w2t_lo, H_DIM * M_MEM / 4);

    // q = hidden @ Wk^T + bk  (3-term fp16 HMMA)
    mm_gemm<1,3><<<dim3(H_DIM / 256, T_TOK / 128), 256, MM_SMEM3>>>(
        hid_hi, hid_lo, wk_hi, wk_lo, qp, H_DIM, H_DIM, bk, nullptr);
    rownorm_hi_kernel<<<T_TOK, 128>>>(qp, q_hi);

    // logits = mask_scale(q_hi @ (mk_hi + mk_lo)^T)  (2-term)
    mm_gemm<2,2><<<dim3(M_MEM / 256, T_TOK / 128), 256, MM_SMEM2>>>(
        q_hi, nullptr, mk_hi, mk_lo, scp, M_MEM, H_DIM, nullptr, usage);

    // softmax rows -> attn*256 fp16
    softmax_kernel<<<T_TOK, 256>>>(scp, attn_hi);

    // out = (attn*256) @ (w2t_hi + w2t_lo)^T / 256 + bo  (2-term)
    mm_gemm<3,2><<<dim3(H_DIM / 256, T_TOK / 128), 256, MM_SMEM2>>>(
        attn_hi, nullptr, w2t_hi, w2t_lo, out, H_DIM, M_MEM, bo, nullptr);
}

// round 7
// speedup vs baseline: 2.4251x; 1.6640x over previous
#include <cuda_runtime.h>
#include <cuda_fp16.h>
#include <cstdint>

#define T_TOK 16384
#define H_DIM 512
#define M_MEM 4096
#define INV_TEMP 10.0f
#define ATTN_SCALE 256.0f

// ---------------------------------------------------------------------------
// Scratch (static device globals; no allocations anywhere)
// ---------------------------------------------------------------------------
__device__ __half g_hid_hi[(size_t)T_TOK * H_DIM];
__device__ __half g_hid_lo[(size_t)T_TOK * H_DIM];
__device__ __half g_wk_hi[(size_t)H_DIM * H_DIM];
__device__ __half g_wk_lo[(size_t)H_DIM * H_DIM];
__device__ __half g_wo_hi[(size_t)H_DIM * H_DIM];
__device__ __half g_wo_lo[(size_t)H_DIM * H_DIM];
__device__ __half g_mv_hi[(size_t)M_MEM * H_DIM];   // compacted mv
__device__ __half g_mv_lo[(size_t)M_MEM * H_DIM];
__device__ __half g_mk_hi[(size_t)M_MEM * H_DIM];   // compacted, normalized mk
__device__ __half g_mk_lo[(size_t)M_MEM * H_DIM];
__device__ __half g_w2t_hi[(size_t)H_DIM * M_MEM];  // W2T over compacted bank
__device__ __half g_w2t_lo[(size_t)H_DIM * M_MEM];
__device__ float  g_q[(size_t)T_TOK * H_DIM];
__device__ __half g_q_hi[(size_t)T_TOK * H_DIM];
__device__ float  g_scores[(size_t)T_TOK * M_MEM];
__device__ __half g_attn[(size_t)T_TOK * M_MEM];    // attn * 256, compacted cols
__device__ int    g_idx[M_MEM];                     // compacted slot -> original slot
__device__ int    g_meta[2];                        // [0]=M_active, [1]=pad256(M_active)

// ---------------------------------------------------------------------------
// Helpers (baseline PTX only: cp.async / ldmatrix / mma.sync)
// ---------------------------------------------------------------------------
__device__ __forceinline__ uint32_t su32(const void* p) {
    return (uint32_t)__cvta_generic_to_shared(p);
}
__device__ __forceinline__ void cp16(uint32_t dst, const void* src) {
    asm volatile("cp.async.cg.shared.global [%0], [%1], 16;\n" :: "r"(dst), "l"(src) : "memory");
}
__device__ __forceinline__ void cp_commit() { asm volatile("cp.async.commit_group;\n" ::: "memory"); }
__device__ __forceinline__ void cp_wait1()  { asm volatile("cp.async.wait_group 1;\n" ::: "memory"); }

__device__ __forceinline__ void ldsm_x4(uint32_t* r, uint32_t addr) {
    asm volatile("ldmatrix.sync.aligned.m8n8.x4.shared.b16 {%0,%1,%2,%3}, [%4];"
                 : "=r"(r[0]), "=r"(r[1]), "=r"(r[2]), "=r"(r[3]) : "r"(addr));
}
__device__ __forceinline__ void mma16816(float* c, const uint32_t* a, const uint32_t* b) {
    asm volatile(
        "mma.sync.aligned.m16n8k16.row.col.f32.f16.f16.f32 "
        "{%0,%1,%2,%3}, {%4,%5,%6,%7}, {%8,%9}, {%0,%1,%2,%3};"
        : "+f"(c[0]), "+f"(c[1]), "+f"(c[2]), "+f"(c[3])
        : "r"(a[0]), "r"(a[1]), "r"(a[2]), "r"(a[3]), "r"(b[0]), "r"(b[1]));
}

__device__ __forceinline__ void split1(float x, __half& h, __half& l) {
    h = __float2half_rn(x);
    l = __float2half_rn(x - __half2float(h));
}

// ---------------------------------------------------------------------------
// Compaction: stable prefix-scan over usage>0 -> idx list + meta
// Single CTA, 1024 threads, 4 entries each.
// ---------------------------------------------------------------------------
__global__ void compact_kernel(const int* __restrict__ usage, int* __restrict__ idx,
                               int* __restrict__ meta)
{
    __shared__ int wsum[32];
    const int t = threadIdx.x, lane = t & 31, w = t >> 5;
    const int base = t * 4;
    int f[4], cnt = 0;
#pragma unroll
    for (int i = 0; i < 4; i++) { f[i] = usage[base + i] > 0; cnt += f[i]; }
    int inc = cnt;
#pragma unroll
    for (int o = 1; o < 32; o <<= 1) {
        int v = __shfl_up_sync(0xffffffffu, inc, o);
        if (lane >= o) inc += v;
    }
    const int exc = inc - cnt;
    if (lane == 31) wsum[w] = inc;
    __syncthreads();
    if (w == 0) {
        int v = wsum[lane];
        __syncwarp();
#pragma unroll
        for (int o = 1; o < 32; o <<= 1) {
            int u = __shfl_up_sync(0xffffffffu, v, o);
            if (lane >= o) v += u;
        }
        wsum[lane] = v;
    }
    __syncthreads();
    int pos = (w > 0 ? wsum[w - 1] : 0) + exc;
#pragma unroll
    for (int i = 0; i < 4; i++)
        if (f[i]) idx[pos++] = base + i;
    if (t == 1023) {
        const int tot = wsum[31];
        meta[0] = tot;
        int pad = ((tot + 255) >> 8) << 8;
        meta[1] = pad < 256 ? 256 : pad;
    }
}

// ---------------------------------------------------------------------------
// Gather + fp16 split (mv). Block j handles compacted row j (zeros if padded).
// ---------------------------------------------------------------------------
__global__ void gather_split_kernel(const float* __restrict__ in, const int* __restrict__ idx,
                                    const int* __restrict__ meta,
                                    __half* __restrict__ oh, __half* __restrict__ ol)
{
    const int j = blockIdx.x, tid = threadIdx.x;
    const size_t off = (size_t)j * H_DIM + tid * 4;
    if (j >= meta[0]) {
        const __half2 z = __halves2half2(__float2half_rn(0.f), __float2half_rn(0.f));
        *(__half2*)(oh + off + 0) = z; *(__half2*)(oh + off + 2) = z;
        *(__half2*)(ol + off + 0) = z; *(__half2*)(ol + off + 2) = z;
        return;
    }
    const int row = idx[j];
    float4 v = ((const float4*)(in + (size_t)row * H_DIM))[tid];
    __half h0, l0, h1, l1, h2, l2, h3, l3;
    split1(v.x, h0, l0); split1(v.y, h1, l1); split1(v.z, h2, l2); split1(v.w, h3, l3);
    *(__half2*)(oh + off + 0) = __halves2half2(h0, h1);
    *(__half2*)(oh + off + 2) = __halves2half2(h2, h3);
    *(__half2*)(ol + off + 0) = __halves2half2(l0, l1);
    *(__half2*)(ol + off + 2) = __halves2half2(l2, l3);
}

// ---------------------------------------------------------------------------
// Gather + row L2-normalize + fp16 split (mk).
// ---------------------------------------------------------------------------
__global__ void gather_rownorm_split_kernel(const float* __restrict__ in,
                                            const int* __restrict__ idx,
                                            const int* __restrict__ meta,
                                            __half* __restrict__ oh, __half* __restrict__ ol)
{
    __shared__ float sh[4];
    const int j = blockIdx.x, tid = threadIdx.x;
    const size_t off = (size_t)j * H_DIM + tid * 4;
    if (j >= meta[0]) {
        const __half2 z = __halves2half2(__float2half_rn(0.f), __float2half_rn(0.f));
        *(__half2*)(oh + off + 0) = z; *(__half2*)(oh + off + 2) = z;
        *(__half2*)(ol + off + 0) = z; *(__half2*)(ol + off + 2) = z;
        return;
    }
    const int row = idx[j];
    float4 v = ((const float4*)(in + (size_t)row * H_DIM))[tid];
    float s = v.x * v.x + v.y * v.y + v.z * v.z + v.w * v.w;
#pragma unroll
    for (int o = 16; o; o >>= 1) s += __shfl_xor_sync(0xffffffffu, s, o);
    if ((tid & 31) == 0) sh[tid >> 5] = s;
    __syncthreads();
    const float r = rsqrtf(sh[0] + sh[1] + sh[2] + sh[3] + 1e-6f);
    __half h0, l0, h1, l1, h2, l2, h3, l3;
    split1(v.x * r, h0, l0); split1(v.y * r, h1, l1);
    split1(v.z * r, h2, l2); split1(v.w * r, h3, l3);
    *(__half2*)(oh + off + 0) = __halves2half2(h0, h1);
    *(__half2*)(oh + off + 2) = __halves2half2(h2, h3);
    *(__half2*)(ol + off + 0) = __halves2half2(l0, l1);
    *(__half2*)(ol + off + 2) = __halves2half2(l2, l3);
}

// ---------------------------------------------------------------------------
// HMMA GEMM:  C[M,N] = split(A) @ split(B)^T   (A:[M,K], B:[N,K], fp16)
// CTA tile 128x256, 8 warps (2x4) of 64x64, BK=64, double-buffered cp.async.
// TERMS=2: Ah*(Bh+Bl); TERMS=3: + Al*Bh. All accum fp32.
// EPI: 1 +bias; 2 compact-mask scores (meta); 3 /256 + bias, K dyn = meta[1];
//      4 write hi/lo fp16 split (Ch/Cl), early-exit n0 >= meta[1].
// LD = row stride of A and B (equal at all call sites).
// ---------------------------------------------------------------------------
#define BK       64
#define TROW     144
#define A_TSZ    (128 * TROW)              // 18432 B
#define B_TSZ    (256 * TROW)              // 36864 B
#define MM_SMEM2 (2 * (A_TSZ + 2 * B_TSZ))      // 184320
#define MM_SMEM3 (2 * (2 * A_TSZ + 2 * B_TSZ))  // 221184

template <int TERMS>
__device__ __forceinline__ void load_chunk(uint32_t st,
    const __half* __restrict__ Ah, const __half* __restrict__ Al,
    const __half* __restrict__ Bh, const __half* __restrict__ Bl,
    int LD, int m0, int n0, int k0, int t)
{
#pragma unroll
    for (int i = 0; i < 4; i++) {
        const int idx = (i << 8) + t;
        const int row = idx >> 3, j = idx & 7;
        const uint32_t so = (uint32_t)(row * TROW + j * 16);
        const size_t  go = (size_t)(m0 + row) * LD + k0 + (j << 3);
        cp16(st + so, Ah + go);
        if (TERMS == 3) cp16(st + A_TSZ + so, Al + go);
    }
    const uint32_t bb = st + (TERMS == 3 ? 2 : 1) * A_TSZ;
#pragma unroll
    for (int i = 0; i < 8; i++) {
        const int idx = (i << 8) + t;
        const int row = idx >> 3, j = idx & 7;
        const uint32_t so = (uint32_t)(row * TROW + j * 16);
        const size_t  go = (size_t)(n0 + row) * LD + k0 + (j << 3);
        cp16(bb + so, Bh + go);
        cp16(bb + B_TSZ + so, Bl + go);
    }
}

template <int EPI, int TERMS>
__global__ __launch_bounds__(256, 1)
void mm_gemm(const __half* __restrict__ Ah, const __half* __restrict__ Al,
             const __half* __restrict__ Bh, const __half* __restrict__ Bl,
             float* __restrict__ C, __half* __restrict__ Ch, __half* __restrict__ Cl,
             int Ntot, int LD, int Kstat,
             const int* __restrict__ meta, const float* __restrict__ bias)
{
    constexpr uint32_t STG = (TERMS == 3 ? 2 : 1) * A_TSZ + 2 * B_TSZ;
    extern __shared__ char smem[];
    const uint32_t sb = su32(smem);
    const int t   = threadIdx.x;
    const int wid = t >> 5, l = t & 31;
    const int wm  = wid & 1;
    const int wn  = wid >> 1;
    const int m0  = blockIdx.y << 7, n0 = blockIdx.x << 8;

    if ((EPI == 2 || EPI == 4) && n0 >= __ldg(meta + 1)) return;
    const int K = (EPI == 3) ? __ldg(meta + 1) : Kstat;

    const uint32_t aoff = (uint32_t)(wm * 64 + (l & 7) + ((l >> 3) & 1) * 8) * TROW
                        + ((l >> 4) & 1) * 16;
    const uint32_t boff = (uint32_t)(wn * 64 + (l & 7) + ((l >> 4) & 1) * 8) * TROW
                        + ((l >> 3) & 1) * 16;
    const uint32_t bbase = (TERMS == 3 ? 2 : 1) * A_TSZ;

    float acc[4][8][4];
#pragma unroll
    for (int mf = 0; mf < 4; mf++)
#pragma unroll
        for (int nf = 0; nf < 8; nf++)
#pragma unroll
            for (int i = 0; i < 4; i++) acc[mf][nf][i] = 0.0f;

    const int nch = K / BK;

    load_chunk<TERMS>(sb, Ah, Al, Bh, Bl, LD, m0, n0, 0, t);        cp_commit();
    load_chunk<TERMS>(sb + STG, Ah, Al, Bh, Bl, LD, m0, n0, BK, t); cp_commit();

    for (int c = 0; c < nch; c++) {
        cp_wait1();
        __syncthreads();
        const uint32_t st = sb + (uint32_t)(c & 1) * STG;
#pragma unroll
        for (int ks = 0; ks < 4; ks++) {
            uint32_t ah[4][4], al[4][4], bh[4][4], bl[4][4];
#pragma unroll
            for (int mf = 0; mf < 4; mf++) {
                ldsm_x4(ah[mf], st + aoff + mf * (16 * TROW) + ks * 32);
                if (TERMS == 3)
                    ldsm_x4(al[mf], st + A_TSZ + aoff + mf * (16 * TROW) + ks * 32);
            }
#pragma unroll
            for (int nf2 = 0; nf2 < 4; nf2++) {
                ldsm_x4(bh[nf2], st + bbase + boff + nf2 * (16 * TROW) + ks * 32);
                ldsm_x4(bl[nf2], st + bbase + B_TSZ + boff + nf2 * (16 * TROW) + ks * 32);
            }
#pragma unroll
            for (int mf = 0; mf < 4; mf++)
#pragma unroll
                for (int nf = 0; nf < 8; nf++) {
                    const uint32_t* bhp = &bh[nf >> 1][(nf & 1) * 2];
                    const uint32_t* blp = &bl[nf >> 1][(nf & 1) * 2];
                    mma16816(acc[mf][nf], ah[mf], bhp);
                    mma16816(acc[mf][nf], ah[mf], blp);
                    if (TERMS == 3) mma16816(acc[mf][nf], al[mf], bhp);
                }
        }
        __syncthreads();
        if (c + 2 < nch)
            load_chunk<TERMS>(sb + (uint32_t)(c & 1) * STG, Ah, Al, Bh, Bl,
                              LD, m0, n0, (c + 2) * BK, t);
        cp_commit();
    }

    const int mact = (EPI == 2) ? __ldg(meta + 0) : 0;

#pragma unroll
    for (int mf = 0; mf < 4; mf++) {
        const int r0 = m0 + wm * 64 + mf * 16 + (l >> 2);
#pragma unroll
        for (int nf = 0; nf < 8; nf++) {
            const int c0 = n0 + wn * 64 + nf * 8 + ((l & 3) << 1);
            float v0 = acc[mf][nf][0], v1 = acc[mf][nf][1];
            float v2 = acc[mf][nf][2], v3 = acc[mf][nf][3];
            if (EPI == 1) {
                const float b0 = __ldg(bias + c0), b1 = __ldg(bias + c0 + 1);
                v0 += b0; v1 += b1; v2 += b0; v3 += b1;
            }
            if (EPI == 2) {
                const bool u0 = c0 < mact, u1 = (c0 + 1) < mact;
                v0 = u0 ? v0 * INV_TEMP : -1e9f;  v1 = u1 ? v1 * INV_TEMP : -1e9f;
                v2 = u0 ? v2 * INV_TEMP : -1e9f;  v3 = u1 ? v3 * INV_TEMP : -1e9f;
            }
            if (EPI == 3) {
                const float b0 = __ldg(bias + c0), b1 = __ldg(bias + c0 + 1);
                const float s = 1.0f / ATTN_SCALE;
                v0 = fmaf(v0, s, b0); v1 = fmaf(v1, s, b1);
                v2 = fmaf(v2, s, b0); v3 = fmaf(v3, s, b1);
            }
            if (EPI == 4) {
                __half h0, l0h, h1, l1h, h2, l2h, h3, l3h;
                split1(v0, h0, l0h); split1(v1, h1, l1h);
                split1(v2, h2, l2h); split1(v3, h3, l3h);
                *(__half2*)(Ch + (size_t)r0 * Ntot + c0)       = __halves2half2(h0, h1);
                *(__half2*)(Ch + (size_t)(r0 + 8) * Ntot + c0) = __halves2half2(h2, h3);
                *(__half2*)(Cl + (size_t)r0 * Ntot + c0)       = __halves2half2(l0h, l1h);
                *(__half2*)(Cl + (size_t)(r0 + 8) * Ntot + c0) = __halves2half2(l2h, l3h);
            } else {
                *(float2*)(C + (size_t)r0 * Ntot + c0)       = make_float2(v0, v1);
                *(float2*)(C + (size_t)(r0 + 8) * Ntot + c0) = make_float2(v2, v3);
            }
        }
    }
}

// ---------------------------------------------------------------------------
// Elementwise fp32 -> (hi, lo) fp16 split
// ---------------------------------------------------------------------------
__global__ void split_kernel(const float* __restrict__ in, __half* __restrict__ oh,
                             __half* __restrict__ ol, int n4)
{
    int idx = blockIdx.x * blockDim.x + threadIdx.x;
    const int stride = gridDim.x * blockDim.x;
    for (; idx < n4; idx += stride) {
        float4 v = ((const float4*)in)[idx];
        __half h0, l0, h1, l1, h2, l2, h3, l3;
        split1(v.x, h0, l0); split1(v.y, h1, l1); split1(v.z, h2, l2); split1(v.w, h3, l3);
        ((__half2*)oh)[idx * 2 + 0] = __halves2half2(h0, h1);
        ((__half2*)oh)[idx * 2 + 1] = __halves2half2(h2, h3);
        ((__half2*)ol)[idx * 2 + 0] = __halves2half2(l0, l1);
        ((__half2*)ol)[idx * 2 + 1] = __halves2half2(l2, l3);
    }
}

// ---------------------------------------------------------------------------
// Row L2-style normalize, fp16 hi only (for q)
// ---------------------------------------------------------------------------
__global__ void rownorm_hi_kernel(const float* __restrict__ in, __half* __restrict__ oh)
{
    __shared__ float sh[4];
    const int row = blockIdx.x;
    const int tid = threadIdx.x;
    float4 v = ((const float4*)(in + (size_t)row * H_DIM))[tid];
    float s = v.x * v.x + v.y * v.y + v.z * v.z + v.w * v.w;
#pragma unroll
    for (int o = 16; o; o >>= 1) s += __shfl_xor_sync(0xffffffffu, s, o);
    if ((tid & 31) == 0) sh[tid >> 5] = s;
    __syncthreads();
    const float r = rsqrtf(sh[0] + sh[1] + sh[2] + sh[3] + 1e-6f);
    const size_t off = (size_t)row * H_DIM + tid * 4;
    *(__half2*)(oh + off + 0) = __halves2half2(__float2half_rn(v.x * r), __float2half_rn(v.y * r));
    *(__half2*)(oh + off + 2) = __halves2half2(__float2half_rn(v.z * r), __float2half_rn(v.w * r));
}

// ---------------------------------------------------------------------------
// Softmax over dynamic row length meta[1] -> fp16 (attn * 256). 256 thr/row.
// ---------------------------------------------------------------------------
__global__ void softmax_kernel(const float* __restrict__ scores, __half* __restrict__ oh,
                               const int* __restrict__ meta)
{
    __shared__ float sh[8];
    const int tid = threadIdx.x;
    const int nf4 = __ldg(meta + 1) >> 2;   // row length in float4s (mult of 64)
    const float4* p = (const float4*)(scores + (size_t)blockIdx.x * M_MEM);

    float4 v[4];
    bool ok[4];
    float mx = -3.402823466e38f;
#pragma unroll
    for (int i = 0; i < 4; i++) {
        const int fi = tid + (i << 8);
        ok[i] = fi < nf4;
        if (ok[i]) {
            v[i] = p[fi];
            mx = fmaxf(mx, fmaxf(fmaxf(v[i].x, v[i].y), fmaxf(v[i].z, v[i].w)));
        }
    }
#pragma unroll
    for (int o = 16; o; o >>= 1) mx = fmaxf(mx, __shfl_xor_sync(0xffffffffu, mx, o));
    if ((tid & 31) == 0) sh[tid >> 5] = mx;
    __syncthreads();
    mx = sh[0];
#pragma unroll
    for (int i = 1; i < 8; i++) mx = fmaxf(mx, sh[i]);
    __syncthreads();

    float s = 0.0f;
#pragma unroll
    for (int i = 0; i < 4; i++) {
        if (ok[i]) {
            v[i].x = __expf(v[i].x - mx); v[i].y = __expf(v[i].y - mx);
            v[i].z = __expf(v[i].z - mx); v[i].w = __expf(v[i].w - mx);
            s += v[i].x + v[i].y + v[i].z + v[i].w;
        }
    }
#pragma unroll
    for (int o = 16; o; o >>= 1) s += __shfl_xor_sync(0xffffffffu, s, o);
    if ((tid & 31) == 0) sh[tid >> 5] = s;
    __syncthreads();
    float tot = sh[0];
#pragma unroll
    for (int i = 1; i < 8; i++) tot += sh[i];
    const float inv = ATTN_SCALE / tot;

#pragma unroll
    for (int i = 0; i < 4; i++) {
        if (ok[i]) {
            const size_t off = (size_t)blockIdx.x * M_MEM + (size_t)(tid + (i << 8)) * 4;
            *(__half2*)(oh + off + 0) = __halves2half2(__float2half_rn(v[i].x * inv),
                                                       __float2half_rn(v[i].y * inv));
            *(__half2*)(oh + off + 2) = __halves2half2(__float2half_rn(v[i].z * inv),
                                                       __float2half_rn(v[i].w * inv));
        }
    }
}

// ---------------------------------------------------------------------------
// Launch pipeline
// ---------------------------------------------------------------------------
extern "C" void kernel_launch(void* const* d_in, const int* in_sizes, int n_in,
                              void* d_out, int out_size)
{
    const float* hidden = (const float*)d_in[0];
    const float* mk     = (const float*)d_in[1];
    const float* mv     = (const float*)d_in[2];
    const float* Wk     = (const float*)d_in[3];
    const float* bk     = (const float*)d_in[4];
    const float* Wo     = (const float*)d_in[5];
    const float* bo     = (const float*)d_in[6];
    const int*   usage  = (const int*)d_in[7];
    float* out = (float*)d_out;

    __half *hid_hi, *hid_lo, *wk_hi, *wk_lo, *wo_hi, *wo_lo, *mv_hi, *mv_lo;
    __half *mk_hi, *mk_lo, *w2t_hi, *w2t_lo, *q_hi, *attn;
    float *qp, *scp;
    int *idxp, *metap;
    cudaGetSymbolAddress((void**)&hid_hi, g_hid_hi);
    cudaGetSymbolAddress((void**)&hid_lo, g_hid_lo);
    cudaGetSymbolAddress((void**)&wk_hi, g_wk_hi);
    cudaGetSymbolAddress((void**)&wk_lo, g_wk_lo);
    cudaGetSymbolAddress((void**)&wo_hi, g_wo_hi);
    cudaGetSymbolAddress((void**)&wo_lo, g_wo_lo);
    cudaGetSymbolAddress((void**)&mv_hi, g_mv_hi);
    cudaGetSymbolAddress((void**)&mv_lo, g_mv_lo);
    cudaGetSymbolAddress((void**)&mk_hi, g_mk_hi);
    cudaGetSymbolAddress((void**)&mk_lo, g_mk_lo);
    cudaGetSymbolAddress((void**)&w2t_hi, g_w2t_hi);
    cudaGetSymbolAddress((void**)&w2t_lo, g_w2t_lo);
    cudaGetSymbolAddress((void**)&qp, g_q);
    cudaGetSymbolAddress((void**)&q_hi, g_q_hi);
    cudaGetSymbolAddress((void**)&scp, g_scores);
    cudaGetSymbolAddress((void**)&attn, g_attn);
    cudaGetSymbolAddress((void**)&idxp, g_idx);
    cudaGetSymbolAddress((void**)&metap, g_meta);

    cudaFuncSetAttribute(mm_gemm<1,3>, cudaFuncAttributeMaxDynamicSharedMemorySize, MM_SMEM3);
    cudaFuncSetAttribute(mm_gemm<4,3>, cudaFuncAttributeMaxDynamicSharedMemorySize, MM_SMEM3);
    cudaFuncSetAttribute(mm_gemm<2,2>, cudaFuncAttributeMaxDynamicSharedMemorySize, MM_SMEM2);
    cudaFuncSetAttribute(mm_gemm<3,2>, cudaFuncAttributeMaxDynamicSharedMemorySize, MM_SMEM2);

    // compaction + splits
    compact_kernel<<<1, 1024>>>(usage, idxp, metap);
    split_kernel<<<2048, 256>>>(hidden, hid_hi, hid_lo, T_TOK * H_DIM / 4);
    split_kernel<<<256, 256>>>(Wk, wk_hi, wk_lo, H_DIM * H_DIM / 4);
    split_kernel<<<256, 256>>>(Wo, wo_hi, wo_lo, H_DIM * H_DIM / 4);
    gather_split_kernel<<<M_MEM, 128>>>(mv, idxp, metap, mv_hi, mv_lo);
    gather_rownorm_split_kernel<<<M_MEM, 128>>>(mk, idxp, metap, mk_hi, mk_lo);

    // W2T[h,j] = sum_v Wo[h,v] * mv_c[j,v]  (compacted; fused split epilogue)
    mm_gemm<4,3><<<dim3(M_MEM / 256, H_DIM / 128), 256, MM_SMEM3>>>(
        wo_hi, wo_lo, mv_hi, mv_lo, nullptr, w2t_hi, w2t_lo,
        M_MEM, H_DIM, H_DIM, metap, nullptr);

    // q = hidden @ Wk^T + bk  (3-term)
    mm_gemm<1,3><<<dim3(H_DIM / 256, T_TOK / 128), 256, MM_SMEM3>>>(
        hid_hi, hid_lo, wk_hi, wk_lo, qp, nullptr, nullptr,
        H_DIM, H_DIM, H_DIM, nullptr, bk);
    rownorm_hi_kernel<<<T_TOK, 128>>>(qp, q_hi);

    // logits over compacted bank (2-term); cols >= M_active -> -1e9
    mm_gemm<2,2><<<dim3(M_MEM / 256, T_TOK / 128), 256, MM_SMEM2>>>(
        q_hi, nullptr, mk_hi, mk_lo, scp, nullptr, nullptr,
        M_MEM, H_DIM, H_DIM, metap, nullptr);

    // softmax over dynamic compacted width -> attn*256 fp16
    softmax_kernel<<<T_TOK, 256>>>(scp, attn, metap);

    // out = (attn*256) @ W2T^T / 256 + bo  (2-term, dynamic K)
    mm_gemm<3,2><<<dim3(H_DIM / 256, T_TOK / 128), 256, MM_SMEM2>>>(
        attn, nullptr, w2t_hi, w2t_lo, out, nullptr, nullptr,
        H_DIM, M_MEM, 0, metap, bo);
}

// round 8
// speedup vs baseline: 2.5447x; 1.0493x over previous
#include <cuda_runtime.h>
#include <cuda_fp16.h>
#include <cstdint>

#define T_TOK 16384
#define H_DIM 512
#define M_MEM 4096
#define EXP_SCALE 8192.0f

// ---------------------------------------------------------------------------
// Scratch (static device globals; no allocations anywhere)
// ---------------------------------------------------------------------------
__device__ __half g_hid_hi[(size_t)T_TOK * H_DIM];
__device__ __half g_wk_hi[(size_t)H_DIM * H_DIM];
__device__ __half g_wk_lo[(size_t)H_DIM * H_DIM];
__device__ __half g_wo_hi[(size_t)H_DIM * H_DIM];
__device__ __half g_wo_lo[(size_t)H_DIM * H_DIM];
__device__ __half g_mv_hi[(size_t)M_MEM * H_DIM];   // compacted mv
__device__ __half g_mv_lo[(size_t)M_MEM * H_DIM];
__device__ __half g_mk_hi[(size_t)M_MEM * H_DIM];   // compacted, normalized mk
__device__ __half g_mk_lo[(size_t)M_MEM * H_DIM];
__device__ __half g_w2t_hi[(size_t)H_DIM * M_MEM];  // W2T over compacted bank
__device__ __half g_w2t_lo[(size_t)H_DIM * M_MEM];
__device__ float  g_q[(size_t)T_TOK * H_DIM];
__device__ __half g_q_hi[(size_t)T_TOK * H_DIM];
__device__ __half g_exp[(size_t)T_TOK * M_MEM];     // exp(logit-10)*8192, compacted cols
__device__ float  g_rowscale[T_TOK];                // 1 / rowsum(g_exp)
__device__ int    g_idx[M_MEM];                     // compacted slot -> original slot
__device__ int    g_meta[2];                        // [0]=M_active, [1]=pad256(M_active)

// ---------------------------------------------------------------------------
// Helpers (baseline PTX only: cp.async / ldmatrix / mma.sync)
// ---------------------------------------------------------------------------
__device__ __forceinline__ uint32_t su32(const void* p) {
    return (uint32_t)__cvta_generic_to_shared(p);
}
__device__ __forceinline__ void cp16(uint32_t dst, const void* src) {
    asm volatile("cp.async.cg.shared.global [%0], [%1], 16;\n" :: "r"(dst), "l"(src) : "memory");
}
__device__ __forceinline__ void cp_commit() { asm volatile("cp.async.commit_group;\n" ::: "memory"); }
__device__ __forceinline__ void cp_wait1()  { asm volatile("cp.async.wait_group 1;\n" ::: "memory"); }

__device__ __forceinline__ void ldsm_x4(uint32_t* r, uint32_t addr) {
    asm volatile("ldmatrix.sync.aligned.m8n8.x4.shared.b16 {%0,%1,%2,%3}, [%4];"
                 : "=r"(r[0]), "=r"(r[1]), "=r"(r[2]), "=r"(r[3]) : "r"(addr));
}
__device__ __forceinline__ void mma16816(float* c, const uint32_t* a, const uint32_t* b) {
    asm volatile(
        "mma.sync.aligned.m16n8k16.row.col.f32.f16.f16.f32 "
        "{%0,%1,%2,%3}, {%4,%5,%6,%7}, {%8,%9}, {%0,%1,%2,%3};"
        : "+f"(c[0]), "+f"(c[1]), "+f"(c[2]), "+f"(c[3])
        : "r"(a[0]), "r"(a[1]), "r"(a[2]), "r"(a[3]), "r"(b[0]), "r"(b[1]));
}

__device__ __forceinline__ void split1(float x, __half& h, __half& l) {
    h = __float2half_rn(x);
    l = __float2half_rn(x - __half2float(h));
}

// ---------------------------------------------------------------------------
// Compaction: stable prefix-scan over usage>0 -> idx list + meta
// ---------------------------------------------------------------------------
__global__ void compact_kernel(const int* __restrict__ usage, int* __restrict__ idx,
                               int* __restrict__ meta)
{
    __shared__ int wsum[32];
    const int t = threadIdx.x, lane = t & 31, w = t >> 5;
    const int base = t * 4;
    int f[4], cnt = 0;
#pragma unroll
    for (int i = 0; i < 4; i++) { f[i] = usage[base + i] > 0; cnt += f[i]; }
    int inc = cnt;
#pragma unroll
    for (int o = 1; o < 32; o <<= 1) {
        int v = __shfl_up_sync(0xffffffffu, inc, o);
        if (lane >= o) inc += v;
    }
    const int exc = inc - cnt;
    if (lane == 31) wsum[w] = inc;
    __syncthreads();
    if (w == 0) {
        int v = wsum[lane];
        __syncwarp();
#pragma unroll
        for (int o = 1; o < 32; o <<= 1) {
            int u = __shfl_up_sync(0xffffffffu, v, o);
            if (lane >= o) v += u;
        }
        wsum[lane] = v;
    }
    __syncthreads();
    int pos = (w > 0 ? wsum[w - 1] : 0) + exc;
#pragma unroll
    for (int i = 0; i < 4; i++)
        if (f[i]) idx[pos++] = base + i;
    if (t == 1023) {
        const int tot = wsum[31];
        meta[0] = tot;
        int pad = ((tot + 255) >> 8) << 8;
        meta[1] = pad < 256 ? 256 : pad;
    }
}

// ---------------------------------------------------------------------------
// Gather + fp16 split (mv). Block j handles compacted row j (zeros if padded).
// ---------------------------------------------------------------------------
__global__ void gather_split_kernel(const float* __restrict__ in, const int* __restrict__ idx,
                                    const int* __restrict__ meta,
                                    __half* __restrict__ oh, __half* __restrict__ ol)
{
    const int j = blockIdx.x, tid = threadIdx.x;
    const size_t off = (size_t)j * H_DIM + tid * 4;
    if (j >= meta[0]) {
        const __half2 z = __halves2half2(__float2half_rn(0.f), __float2half_rn(0.f));
        *(__half2*)(oh + off + 0) = z; *(__half2*)(oh + off + 2) = z;
        *(__half2*)(ol + off + 0) = z; *(__half2*)(ol + off + 2) = z;
        return;
    }
    const int row = idx[j];
    float4 v = ((const float4*)(in + (size_t)row * H_DIM))[tid];
    __half h0, l0, h1, l1, h2, l2, h3, l3;
    split1(v.x, h0, l0); split1(v.y, h1, l1); split1(v.z, h2, l2); split1(v.w, h3, l3);
    *(__half2*)(oh + off + 0) = __halves2half2(h0, h1);
    *(__half2*)(oh + off + 2) = __halves2half2(h2, h3);
    *(__half2*)(ol + off + 0) = __halves2half2(l0, l1);
    *(__half2*)(ol + off + 2) = __halves2half2(l2, l3);
}

// ---------------------------------------------------------------------------
// Gather + row L2-normalize + fp16 split (mk).
// ---------------------------------------------------------------------------
__global__ void gather_rownorm_split_kernel(const float* __restrict__ in,
                                            const int* __restrict__ idx,
                                            const int* __restrict__ meta,
                                            __half* __restrict__ oh, __half* __restrict__ ol)
{
    __shared__ float sh[4];
    const int j = blockIdx.x, tid = threadIdx.x;
    const size_t off = (size_t)j * H_DIM + tid * 4;
    if (j >= meta[0]) {
        const __half2 z = __halves2half2(__float2half_rn(0.f), __float2half_rn(0.f));
        *(__half2*)(oh + off + 0) = z; *(__half2*)(oh + off + 2) = z;
        *(__half2*)(ol + off + 0) = z; *(__half2*)(ol + off + 2) = z;
        return;
    }
    const int row = idx[j];
    float4 v = ((const float4*)(in + (size_t)row * H_DIM))[tid];
    float s = v.x * v.x + v.y * v.y + v.z * v.z + v.w * v.w;
#pragma unroll
    for (int o = 16; o; o >>= 1) s += __shfl_xor_sync(0xffffffffu, s, o);
    if ((tid & 31) == 0) sh[tid >> 5] = s;
    __syncthreads();
    const float r = rsqrtf(sh[0] + sh[1] + sh[2] + sh[3] + 1e-6f);
    __half h0, l0, h1, l1, h2, l2, h3, l3;
    split1(v.x * r, h0, l0); split1(v.y * r, h1, l1);
    split1(v.z * r, h2, l2); split1(v.w * r, h3, l3);
    *(__half2*)(oh + off + 0) = __halves2half2(h0, h1);
    *(__half2*)(oh + off + 2) = __halves2half2(h2, h3);
    *(__half2*)(ol + off + 0) = __halves2half2(l0, l1);
    *(__half2*)(ol + off + 2) = __halves2half2(l2, l3);
}

// ---------------------------------------------------------------------------
// HMMA GEMM:  C[M,N] = split(A) @ split(B)^T   (A:[M,K], B:[N,K], fp16)
// CTA tile 128x256, 8 warps (2x4) of 64x64, BK=64, double-buffered cp.async.
// TERMS=2: Ah*(Bh+Bl); TERMS=3: + Al*Bh. All accum fp32.
// EPI: 1 +bias (fp32 out);
//      2 scores->exp fp16: e = col<mact ? expf(10*acc-10)*8192 : 0, to Ch;
//      3 retrieval: out = acc*rowscale[r] + bias, K dyn = meta[1];
//      4 write hi/lo fp16 split (Ch/Cl), early-exit n0 >= meta[1].
// ---------------------------------------------------------------------------
#define BK       64
#define TROW     144
#define A_TSZ    (128 * TROW)              // 18432 B
#define B_TSZ    (256 * TROW)              // 36864 B
#define MM_SMEM2 (2 * (A_TSZ + 2 * B_TSZ))      // 184320
#define MM_SMEM3 (2 * (2 * A_TSZ + 2 * B_TSZ))  // 221184

template <int TERMS>
__device__ __forceinline__ void load_chunk(uint32_t st,
    const __half* __restrict__ Ah, const __half* __restrict__ Al,
    const __half* __restrict__ Bh, const __half* __restrict__ Bl,
    int LD, int m0, int n0, int k0, int t)
{
#pragma unroll
    for (int i = 0; i < 4; i++) {
        const int idx = (i << 8) + t;
        const int row = idx >> 3, j = idx & 7;
        const uint32_t so = (uint32_t)(row * TROW + j * 16);
        const size_t  go = (size_t)(m0 + row) * LD + k0 + (j << 3);
        cp16(st + so, Ah + go);
        if (TERMS == 3) cp16(st + A_TSZ + so, Al + go);
    }
    const uint32_t bb = st + (TERMS == 3 ? 2 : 1) * A_TSZ;
#pragma unroll
    for (int i = 0; i < 8; i++) {
        const int idx = (i << 8) + t;
        const int row = idx >> 3, j = idx & 7;
        const uint32_t so = (uint32_t)(row * TROW + j * 16);
        const size_t  go = (size_t)(n0 + row) * LD + k0 + (j << 3);
        cp16(bb + so, Bh + go);
        cp16(bb + B_TSZ + so, Bl + go);
    }
}

template <int EPI, int TERMS>
__global__ __launch_bounds__(256, 1)
void mm_gemm(const __half* __restrict__ Ah, const __half* __restrict__ Al,
             const __half* __restrict__ Bh, const __half* __restrict__ Bl,
             float* __restrict__ C, __half* __restrict__ Ch, __half* __restrict__ Cl,
             int Ntot, int LD, int Kstat,
             const int* __restrict__ meta, const float* __restrict__ bias,
             const float* __restrict__ rowscale)
{
    constexpr uint32_t STG = (TERMS == 3 ? 2 : 1) * A_TSZ + 2 * B_TSZ;
    extern __shared__ char smem[];
    const uint32_t sb = su32(smem);
    const int t   = threadIdx.x;
    const int wid = t >> 5, l = t & 31;
    const int wm  = wid & 1;
    const int wn  = wid >> 1;
    const int m0  = blockIdx.y << 7, n0 = blockIdx.x << 8;

    if ((EPI == 2 || EPI == 4) && n0 >= __ldg(meta + 1)) return;
    const int K = (EPI == 3) ? __ldg(meta + 1) : Kstat;

    const uint32_t aoff = (uint32_t)(wm * 64 + (l & 7) + ((l >> 3) & 1) * 8) * TROW
                        + ((l >> 4) & 1) * 16;
    const uint32_t boff = (uint32_t)(wn * 64 + (l & 7) + ((l >> 4) & 1) * 8) * TROW
                        + ((l >> 3) & 1) * 16;
    const uint32_t bbase = (TERMS == 3 ? 2 : 1) * A_TSZ;

    float acc[4][8][4];
#pragma unroll
    for (int mf = 0; mf < 4; mf++)
#pragma unroll
        for (int nf = 0; nf < 8; nf++)
#pragma unroll
            for (int i = 0; i < 4; i++) acc[mf][nf][i] = 0.0f;

    const int nch = K / BK;

    load_chunk<TERMS>(sb, Ah, Al, Bh, Bl, LD, m0, n0, 0, t);        cp_commit();
    load_chunk<TERMS>(sb + STG, Ah, Al, Bh, Bl, LD, m0, n0, BK, t); cp_commit();

    for (int c = 0; c < nch; c++) {
        cp_wait1();
        __syncthreads();
        const uint32_t st = sb + (uint32_t)(c & 1) * STG;
#pragma unroll
        for (int ks = 0; ks < 4; ks++) {
            uint32_t ah[4][4], al[4][4], bh[4][4], bl[4][4];
#pragma unroll
            for (int mf = 0; mf < 4; mf++) {
                ldsm_x4(ah[mf], st + aoff + mf * (16 * TROW) + ks * 32);
                if (TERMS == 3)
                    ldsm_x4(al[mf], st + A_TSZ + aoff + mf * (16 * TROW) + ks * 32);
            }
#pragma unroll
            for (int nf2 = 0; nf2 < 4; nf2++) {
                ldsm_x4(bh[nf2], st + bbase + boff + nf2 * (16 * TROW) + ks * 32);
                ldsm_x4(bl[nf2], st + bbase + B_TSZ + boff + nf2 * (16 * TROW) + ks * 32);
            }
#pragma unroll
            for (int mf = 0; mf < 4; mf++)
#pragma unroll
                for (int nf = 0; nf < 8; nf++) {
                    const uint32_t* bhp = &bh[nf >> 1][(nf & 1) * 2];
                    const uint32_t* blp = &bl[nf >> 1][(nf & 1) * 2];
                    mma16816(acc[mf][nf], ah[mf], bhp);
                    mma16816(acc[mf][nf], ah[mf], blp);
                    if (TERMS == 3) mma16816(acc[mf][nf], al[mf], bhp);
                }
        }
        __syncthreads();
        if (c + 2 < nch)
            load_chunk<TERMS>(sb + (uint32_t)(c & 1) * STG, Ah, Al, Bh, Bl,
                              LD, m0, n0, (c + 2) * BK, t);
        cp_commit();
    }

    const int mact = (EPI == 2) ? __ldg(meta + 0) : 0;

#pragma unroll
    for (int mf = 0; mf < 4; mf++) {
        const int r0 = m0 + wm * 64 + mf * 16 + (l >> 2);
        float s0 = 0.f, s1 = 0.f;
        if (EPI == 3) { s0 = __ldg(rowscale + r0); s1 = __ldg(rowscale + r0 + 8); }
#pragma unroll
        for (int nf = 0; nf < 8; nf++) {
            const int c0 = n0 + wn * 64 + nf * 8 + ((l & 3) << 1);
            float v0 = acc[mf][nf][0], v1 = acc[mf][nf][1];
            float v2 = acc[mf][nf][2], v3 = acc[mf][nf][3];
            if (EPI == 1) {
                const float b0 = __ldg(bias + c0), b1 = __ldg(bias + c0 + 1);
                v0 += b0; v1 += b1; v2 += b0; v3 += b1;
                *(float2*)(C + (size_t)r0 * Ntot + c0)       = make_float2(v0, v1);
                *(float2*)(C + (size_t)(r0 + 8) * Ntot + c0) = make_float2(v2, v3);
            }
            if (EPI == 2) {
                const bool u0 = c0 < mact, u1 = (c0 + 1) < mact;
                const float e0 = u0 ? __expf(fmaf(v0, 10.f, -10.f)) * EXP_SCALE : 0.f;
                const float e1 = u1 ? __expf(fmaf(v1, 10.f, -10.f)) * EXP_SCALE : 0.f;
                const float e2 = u0 ? __expf(fmaf(v2, 10.f, -10.f)) * EXP_SCALE : 0.f;
                const float e3 = u1 ? __expf(fmaf(v3, 10.f, -10.f)) * EXP_SCALE : 0.f;
                *(__half2*)(Ch + (size_t)r0 * Ntot + c0) =
                    __halves2half2(__float2half_rn(e0), __float2half_rn(e1));
                *(__half2*)(Ch + (size_t)(r0 + 8) * Ntot + c0) =
                    __halves2half2(__float2half_rn(e2), __float2half_rn(e3));
            }
            if (EPI == 3) {
                const float b0 = __ldg(bias + c0), b1 = __ldg(bias + c0 + 1);
                v0 = fmaf(v0, s0, b0); v1 = fmaf(v1, s0, b1);
                v2 = fmaf(v2, s1, b0); v3 = fmaf(v3, s1, b1);
                *(float2*)(C + (size_t)r0 * Ntot + c0)       = make_float2(v0, v1);
                *(float2*)(C + (size_t)(r0 + 8) * Ntot + c0) = make_float2(v2, v3);
            }
            if (EPI == 4) {
                __half h0, l0h, h1, l1h, h2, l2h, h3, l3h;
                split1(v0, h0, l0h); split1(v1, h1, l1h);
                split1(v2, h2, l2h); split1(v3, h3, l3h);
                *(__half2*)(Ch + (size_t)r0 * Ntot + c0)       = __halves2half2(h0, h1);
                *(__half2*)(Ch + (size_t)(r0 + 8) * Ntot + c0) = __halves2half2(h2, h3);
                *(__half2*)(Cl + (size_t)r0 * Ntot + c0)       = __halves2half2(l0h, l1h);
                *(__half2*)(Cl + (size_t)(r0 + 8) * Ntot + c0) = __halves2half2(l2h, l3h);
            }
        }
    }
}

// ---------------------------------------------------------------------------
// Elementwise fp32 -> (hi, lo) fp16 split
// ---------------------------------------------------------------------------
__global__ void split_kernel(const float* __restrict__ in, __half* __restrict__ oh,
                             __half* __restrict__ ol, int n4)
{
    int idx = blockIdx.x * blockDim.x + threadIdx.x;
    const int stride = gridDim.x * blockDim.x;
    for (; idx < n4; idx += stride) {
        float4 v = ((const float4*)in)[idx];
        __half h0, l0, h1, l1, h2, l2, h3, l3;
        split1(v.x, h0, l0); split1(v.y, h1, l1); split1(v.z, h2, l2); split1(v.w, h3, l3);
        ((__half2*)oh)[idx * 2 + 0] = __halves2half2(h0, h1);
        ((__half2*)oh)[idx * 2 + 1] = __halves2half2(h2, h3);
        ((__half2*)ol)[idx * 2 + 0] = __halves2half2(l0, l1);
        ((__half2*)ol)[idx * 2 + 1] = __halves2half2(l2, l3);
    }
}

// ---------------------------------------------------------------------------
// Elementwise fp32 -> fp16 (hi only)
// ---------------------------------------------------------------------------
__global__ void convert_hi_kernel(const float* __restrict__ in, __half* __restrict__ oh, int n4)
{
    int idx = blockIdx.x * blockDim.x + threadIdx.x;
    const int stride = gridDim.x * blockDim.x;
    for (; idx < n4; idx += stride) {
        float4 v = ((const float4*)in)[idx];
        ((__half2*)oh)[idx * 2 + 0] = __halves2half2(__float2half_rn(v.x), __float2half_rn(v.y));
        ((__half2*)oh)[idx * 2 + 1] = __halves2half2(__float2half_rn(v.z), __float2half_rn(v.w));
    }
}

// ---------------------------------------------------------------------------
// Row L2-style normalize, fp16 hi only (for q)
// ---------------------------------------------------------------------------
__global__ void rownorm_hi_kernel(const float* __restrict__ in, __half* __restrict__ oh)
{
    __shared__ float sh[4];
    const int row = blockIdx.x;
    const int tid = threadIdx.x;
    float4 v = ((const float4*)(in + (size_t)row * H_DIM))[tid];
    float s = v.x * v.x + v.y * v.y + v.z * v.z + v.w * v.w;
#pragma unroll
    for (int o = 16; o; o >>= 1) s += __shfl_xor_sync(0xffffffffu, s, o);
    if ((tid & 31) == 0) sh[tid >> 5] = s;
    __syncthreads();
    const float r = rsqrtf(sh[0] + sh[1] + sh[2] + sh[3] + 1e-6f);
    const size_t off = (size_t)row * H_DIM + tid * 4;
    *(__half2*)(oh + off + 0) = __halves2half2(__float2half_rn(v.x * r), __float2half_rn(v.y * r));
    *(__half2*)(oh + off + 2) = __halves2half2(__float2half_rn(v.z * r), __float2half_rn(v.w * r));
}

// ---------------------------------------------------------------------------
// Row sums of exp buffer (fp16, dynamic width meta[1]) -> rowscale = 1/sum
// ---------------------------------------------------------------------------
__global__ void rowsum_kernel(const __half* __restrict__ e, float* __restrict__ rowscale,
                              const int* __restrict__ meta)
{
    __shared__ float sh[8];
    const int tid = threadIdx.x;
    const int nh8 = __ldg(meta + 1) >> 3;   // row length in 8-half chunks
    const uint4* p = (const uint4*)(e + (size_t)blockIdx.x * M_MEM);

    float s = 0.0f;
#pragma unroll
    for (int i = 0; i < 2; i++) {
        const int fi = tid + (i << 8);
        if (fi < nh8) {
            uint4 u = p[fi];
            float2 a = __half22float2(*(const __half2*)&u.x);
            float2 b = __half22float2(*(const __half2*)&u.y);
            float2 c = __half22float2(*(const __half2*)&u.z);
            float2 d = __half22float2(*(const __half2*)&u.w);
            s += (a.x + a.y) + (b.x + b.y) + (c.x + c.y) + (d.x + d.y);
        }
    }
#pragma unroll
    for (int o = 16; o; o >>= 1) s += __shfl_xor_sync(0xffffffffu, s, o);
    if ((tid & 31) == 0) sh[tid >> 5] = s;
    __syncthreads();
    if (tid == 0) {
        float tot = sh[0];
#pragma unroll
        for (int i = 1; i < 8; i++) tot += sh[i];
        rowscale[blockIdx.x] = 1.0f / tot;
    }
}

// ---------------------------------------------------------------------------
// Launch pipeline
// ---------------------------------------------------------------------------
extern "C" void kernel_launch(void* const* d_in, const int* in_sizes, int n_in,
                              void* d_out, int out_size)
{
    const float* hidden = (const float*)d_in[0];
    const float* mk     = (const float*)d_in[1];
    const float* mv     = (const float*)d_in[2];
    const float* Wk     = (const float*)d_in[3];
    const float* bk     = (const float*)d_in[4];
    const float* Wo     = (const float*)d_in[5];
    const float* bo     = (const float*)d_in[6];
    const int*   usage  = (const int*)d_in[7];
    float* out = (float*)d_out;

    __half *hid_hi, *wk_hi, *wk_lo, *wo_hi, *wo_lo, *mv_hi, *mv_lo;
    __half *mk_hi, *mk_lo, *w2t_hi, *w2t_lo, *q_hi, *expp;
    float *qp, *rsp;
    int *idxp, *metap;
    cudaGetSymbolAddress((void**)&hid_hi, g_hid_hi);
    cudaGetSymbolAddress((void**)&wk_hi, g_wk_hi);
    cudaGetSymbolAddress((void**)&wk_lo, g_wk_lo);
    cudaGetSymbolAddress((void**)&wo_hi, g_wo_hi);
    cudaGetSymbolAddress((void**)&wo_lo, g_wo_lo);
    cudaGetSymbolAddress((void**)&mv_hi, g_mv_hi);
    cudaGetSymbolAddress((void**)&mv_lo, g_mv_lo);
    cudaGetSymbolAddress((void**)&mk_hi, g_mk_hi);
    cudaGetSymbolAddress((void**)&mk_lo, g_mk_lo);
    cudaGetSymbolAddress((void**)&w2t_hi, g_w2t_hi);
    cudaGetSymbolAddress((void**)&w2t_lo, g_w2t_lo);
    cudaGetSymbolAddress((void**)&qp, g_q);
    cudaGetSymbolAddress((void**)&q_hi, g_q_hi);
    cudaGetSymbolAddress((void**)&expp, g_exp);
    cudaGetSymbolAddress((void**)&rsp, g_rowscale);
    cudaGetSymbolAddress((void**)&idxp, g_idx);
    cudaGetSymbolAddress((void**)&metap, g_meta);

    cudaFuncSetAttribute(mm_gemm<1,2>, cudaFuncAttributeMaxDynamicSharedMemorySize, MM_SMEM2);
    cudaFuncSetAttribute(mm_gemm<4,3>, cudaFuncAttributeMaxDynamicSharedMemorySize, MM_SMEM3);
    cudaFuncSetAttribute(mm_gemm<2,2>, cudaFuncAttributeMaxDynamicSharedMemorySize, MM_SMEM2);
    cudaFuncSetAttribute(mm_gemm<3,2>, cudaFuncAttributeMaxDynamicSharedMemorySize, MM_SMEM2);

    // compaction + splits/conversions
    compact_kernel<<<1, 1024>>>(usage, idxp, metap);
    convert_hi_kernel<<<2048, 256>>>(hidden, hid_hi, T_TOK * H_DIM / 4);
    split_kernel<<<256, 256>>>(Wk, wk_hi, wk_lo, H_DIM * H_DIM / 4);
    split_kernel<<<256, 256>>>(Wo, wo_hi, wo_lo, H_DIM * H_DIM / 4);
    gather_split_kernel<<<M_MEM, 128>>>(mv, idxp, metap, mv_hi, mv_lo);
    gather_rownorm_split_kernel<<<M_MEM, 128>>>(mk, idxp, metap, mk_hi, mk_lo);

    // W2T[h,j] = sum_v Wo[h,v] * mv_c[j,v]  (compacted; fused split epilogue)
    mm_gemm<4,3><<<dim3(M_MEM / 256, H_DIM / 128), 256, MM_SMEM3>>>(
        wo_hi, wo_lo, mv_hi, mv_lo, nullptr, w2t_hi, w2t_lo,
        M_MEM, H_DIM, H_DIM, metap, nullptr, nullptr);

    // q = hidden_hi @ (Wk_hi + Wk_lo)^T + bk  (2-term)
    mm_gemm<1,2><<<dim3(H_DIM / 256, T_TOK / 128), 256, MM_SMEM2>>>(
        hid_hi, nullptr, wk_hi, wk_lo, qp, nullptr, nullptr,
        H_DIM, H_DIM, H_DIM, nullptr, bk, nullptr);
    rownorm_hi_kernel<<<T_TOK, 128>>>(qp, q_hi);

    // exp scores over compacted bank (2-term): e = exp(10*cos - 10)*8192, fp16
    mm_gemm<2,2><<<dim3(M_MEM / 256, T_TOK / 128), 256, MM_SMEM2>>>(
        q_hi, nullptr, mk_hi, mk_lo, nullptr, expp, nullptr,
        M_MEM, H_DIM, H_DIM, metap, nullptr, nullptr);

    // row sums -> rowscale
    rowsum_kernel<<<T_TOK, 256>>>(expp, rsp, metap);

    // out = (exp @ W2T^T) * rowscale + bo  (2-term, dynamic K)
    mm_gemm<3,2><<<dim3(H_DIM / 256, T_TOK / 128), 256, MM_SMEM2>>>(
        expp, nullptr, w2t_hi, w2t_lo, out, nullptr, nullptr,
        H_DIM, M_MEM, 0, metap, bo, rsp);
}

// round 9
// speedup vs baseline: 3.0120x; 1.1836x over previous
#include <cuda_runtime.h>
#include <cuda_fp16.h>
#include <cstdint>

#define T_TOK 16384
#define H_DIM 512
#define M_MEM 4096
#define EXP_SCALE 8192.0f

// ---------------------------------------------------------------------------
// Scratch (static device globals; no allocations anywhere)
// ---------------------------------------------------------------------------
__device__ __half g_hid_hi[(size_t)T_TOK * H_DIM];
__device__ __half g_wk_hi[(size_t)H_DIM * H_DIM];
__device__ __half g_wk_lo[(size_t)H_DIM * H_DIM];
__device__ __half g_wo_hi[(size_t)H_DIM * H_DIM];
__device__ __half g_wo_lo[(size_t)H_DIM * H_DIM];
__device__ __half g_mv_hi[(size_t)M_MEM * H_DIM];   // compacted mv
__device__ __half g_mv_lo[(size_t)M_MEM * H_DIM];
__device__ __half g_mk_hi[(size_t)M_MEM * H_DIM];   // compacted, normalized mk
__device__ __half g_mk_lo[(size_t)M_MEM * H_DIM];
__device__ __half g_w2t_hi[(size_t)H_DIM * M_MEM];  // W2T over compacted bank (hi only)
__device__ float  g_q[(size_t)T_TOK * H_DIM];
__device__ __half g_q_hi[(size_t)T_TOK * H_DIM];
__device__ __half g_exp[(size_t)T_TOK * M_MEM];     // exp(logit-10)*8192, compacted cols
__device__ float  g_rowscale[T_TOK];                // 1 / rowsum(g_exp)
__device__ int    g_idx[M_MEM];                     // compacted slot -> original slot
__device__ int    g_meta[2];                        // [0]=M_active, [1]=pad256(M_active)

// ---------------------------------------------------------------------------
// Helpers (baseline PTX only: cp.async / ldmatrix / mma.sync)
// ---------------------------------------------------------------------------
__device__ __forceinline__ uint32_t su32(const void* p) {
    return (uint32_t)__cvta_generic_to_shared(p);
}
__device__ __forceinline__ void cp16(uint32_t dst, const void* src) {
    asm volatile("cp.async.cg.shared.global [%0], [%1], 16;\n" :: "r"(dst), "l"(src) : "memory");
}
__device__ __forceinline__ void cp_commit() { asm volatile("cp.async.commit_group;\n" ::: "memory"); }
__device__ __forceinline__ void cp_wait1()  { asm volatile("cp.async.wait_group 1;\n" ::: "memory"); }

__device__ __forceinline__ void ldsm_x4(uint32_t* r, uint32_t addr) {
    asm volatile("ldmatrix.sync.aligned.m8n8.x4.shared.b16 {%0,%1,%2,%3}, [%4];"
                 : "=r"(r[0]), "=r"(r[1]), "=r"(r[2]), "=r"(r[3]) : "r"(addr));
}
__device__ __forceinline__ void mma16816(float* c, const uint32_t* a, const uint32_t* b) {
    asm volatile(
        "mma.sync.aligned.m16n8k16.row.col.f32.f16.f16.f32 "
        "{%0,%1,%2,%3}, {%4,%5,%6,%7}, {%8,%9}, {%0,%1,%2,%3};"
        : "+f"(c[0]), "+f"(c[1]), "+f"(c[2]), "+f"(c[3])
        : "r"(a[0]), "r"(a[1]), "r"(a[2]), "r"(a[3]), "r"(b[0]), "r"(b[1]));
}

__device__ __forceinline__ void split1(float x, __half& h, __half& l) {
    h = __float2half_rn(x);
    l = __float2half_rn(x - __half2float(h));
}

// ---------------------------------------------------------------------------
// Compaction: stable prefix-scan over usage>0 -> idx list + meta
// ---------------------------------------------------------------------------
__global__ void compact_kernel(const int* __restrict__ usage, int* __restrict__ idx,
                               int* __restrict__ meta)
{
    __shared__ int wsum[32];
    const int t = threadIdx.x, lane = t & 31, w = t >> 5;
    const int base = t * 4;
    int f[4], cnt = 0;
#pragma unroll
    for (int i = 0; i < 4; i++) { f[i] = usage[base + i] > 0; cnt += f[i]; }
    int inc = cnt;
#pragma unroll
    for (int o = 1; o < 32; o <<= 1) {
        int v = __shfl_up_sync(0xffffffffu, inc, o);
        if (lane >= o) inc += v;
    }
    const int exc = inc - cnt;
    if (lane == 31) wsum[w] = inc;
    __syncthreads();
    if (w == 0) {
        int v = wsum[lane];
        __syncwarp();
#pragma unroll
        for (int o = 1; o < 32; o <<= 1) {
            int u = __shfl_up_sync(0xffffffffu, v, o);
            if (lane >= o) v += u;
        }
        wsum[lane] = v;
    }
    __syncthreads();
    int pos = (w > 0 ? wsum[w - 1] : 0) + exc;
#pragma unroll
    for (int i = 0; i < 4; i++)
        if (f[i]) idx[pos++] = base + i;
    if (t == 1023) {
        const int tot = wsum[31];
        meta[0] = tot;
        int pad = ((tot + 255) >> 8) << 8;
        meta[1] = pad < 256 ? 256 : pad;
    }
}

// ---------------------------------------------------------------------------
// Gather + fp16 split (mv). Block j handles compacted row j (zeros if padded).
// ---------------------------------------------------------------------------
__global__ void gather_split_kernel(const float* __restrict__ in, const int* __restrict__ idx,
                                    const int* __restrict__ meta,
                                    __half* __restrict__ oh, __half* __restrict__ ol)
{
    const int j = blockIdx.x, tid = threadIdx.x;
    const size_t off = (size_t)j * H_DIM + tid * 4;
    if (j >= meta[0]) {
        const __half2 z = __halves2half2(__float2half_rn(0.f), __float2half_rn(0.f));
        *(__half2*)(oh + off + 0) = z; *(__half2*)(oh + off + 2) = z;
        *(__half2*)(ol + off + 0) = z; *(__half2*)(ol + off + 2) = z;
        return;
    }
    const int row = idx[j];
    float4 v = ((const float4*)(in + (size_t)row * H_DIM))[tid];
    __half h0, l0, h1, l1, h2, l2, h3, l3;
    split1(v.x, h0, l0); split1(v.y, h1, l1); split1(v.z, h2, l2); split1(v.w, h3, l3);
    *(__half2*)(oh + off + 0) = __halves2half2(h0, h1);
    *(__half2*)(oh + off + 2) = __halves2half2(h2, h3);
    *(__half2*)(ol + off + 0) = __halves2half2(l0, l1);
    *(__half2*)(ol + off + 2) = __halves2half2(l2, l3);
}

// ---------------------------------------------------------------------------
// Gather + row L2-normalize + fp16 split (mk).
// ---------------------------------------------------------------------------
__global__ void gather_rownorm_split_kernel(const float* __restrict__ in,
                                            const int* __restrict__ idx,
                                            const int* __restrict__ meta,
                                            __half* __restrict__ oh, __half* __restrict__ ol)
{
    __shared__ float sh[4];
    const int j = blockIdx.x, tid = threadIdx.x;
    const size_t off = (size_t)j * H_DIM + tid * 4;
    if (j >= meta[0]) {
        const __half2 z = __halves2half2(__float2half_rn(0.f), __float2half_rn(0.f));
        *(__half2*)(oh + off + 0) = z; *(__half2*)(oh + off + 2) = z;
        *(__half2*)(ol + off + 0) = z; *(__half2*)(ol + off + 2) = z;
        return;
    }
    const int row = idx[j];
    float4 v = ((const float4*)(in + (size_t)row * H_DIM))[tid];
    float s = v.x * v.x + v.y * v.y + v.z * v.z + v.w * v.w;
#pragma unroll
    for (int o = 16; o; o >>= 1) s += __shfl_xor_sync(0xffffffffu, s, o);
    if ((tid & 31) == 0) sh[tid >> 5] = s;
    __syncthreads();
    const float r = rsqrtf(sh[0] + sh[1] + sh[2] + sh[3] + 1e-6f);
    __half h0, l0, h1, l1, h2, l2, h3, l3;
    split1(v.x * r, h0, l0); split1(v.y * r, h1, l1);
    split1(v.z * r, h2, l2); split1(v.w * r, h3, l3);
    *(__half2*)(oh + off + 0) = __halves2half2(h0, h1);
    *(__half2*)(oh + off + 2) = __halves2half2(h2, h3);
    *(__half2*)(ol + off + 0) = __halves2half2(l0, l1);
    *(__half2*)(ol + off + 2) = __halves2half2(l2, l3);
}

// ---------------------------------------------------------------------------
// HMMA GEMM:  C[M,N] = terms(A,B)   (A:[M,K], B:[N,K], fp16, row.col)
// CTA tile 128x256, 8 warps (2x4) of 64x64, BK=64, double-buffered cp.async.
// TERMS=1: Ah*Bh;  TERMS=2: Ah*(Bh+Bl);  TERMS=3: + Al*Bh. fp32 accum.
// EPI: 1 +bias (fp32 out);
//      2 scores->exp fp16: e = col<mact ? expf(10*acc-10)*8192 : 0, to Ch;
//      3 retrieval: out = acc*rowscale[r] + bias, K dyn = meta[1];
//      4 write hi fp16 (Ch), early-exit n0 >= meta[1].
// ---------------------------------------------------------------------------
#define BK       64
#define TROW     144
#define A_TSZ    (128 * TROW)              // 18432 B
#define B_TSZ    (256 * TROW)              // 36864 B
#define MM_SMEM1 (2 * (A_TSZ + B_TSZ))          // 110592
#define MM_SMEM2 (2 * (A_TSZ + 2 * B_TSZ))      // 184320
#define MM_SMEM3 (2 * (2 * A_TSZ + 2 * B_TSZ))  // 221184

template <int TERMS>
__device__ __forceinline__ void load_chunk(uint32_t st,
    const __half* __restrict__ Ah, const __half* __restrict__ Al,
    const __half* __restrict__ Bh, const __half* __restrict__ Bl,
    int LD, int m0, int n0, int k0, int t)
{
#pragma unroll
    for (int i = 0; i < 4; i++) {
        const int idx = (i << 8) + t;
        const int row = idx >> 3, j = idx & 7;
        const uint32_t so = (uint32_t)(row * TROW + j * 16);
        const size_t  go = (size_t)(m0 + row) * LD + k0 + (j << 3);
        cp16(st + so, Ah + go);
        if (TERMS == 3) cp16(st + A_TSZ + so, Al + go);
    }
    const uint32_t bb = st + (TERMS == 3 ? 2 : 1) * A_TSZ;
#pragma unroll
    for (int i = 0; i < 8; i++) {
        const int idx = (i << 8) + t;
        const int row = idx >> 3, j = idx & 7;
        const uint32_t so = (uint32_t)(row * TROW + j * 16);
        const size_t  go = (size_t)(n0 + row) * LD + k0 + (j << 3);
        cp16(bb + so, Bh + go);
        if (TERMS >= 2) cp16(bb + B_TSZ + so, Bl + go);
    }
}

template <int EPI, int TERMS>
__global__ __launch_bounds__(256, 1)
void mm_gemm(const __half* __restrict__ Ah, const __half* __restrict__ Al,
             const __half* __restrict__ Bh, const __half* __restrict__ Bl,
             float* __restrict__ C, __half* __restrict__ Ch,
             int Ntot, int LD, int Kstat,
             const int* __restrict__ meta, const float* __restrict__ bias,
             const float* __restrict__ rowscale)
{
    constexpr uint32_t STG = (TERMS == 3 ? 2 : 1) * A_TSZ + (TERMS >= 2 ? 2 : 1) * B_TSZ;
    extern __shared__ char smem[];
    const uint32_t sb = su32(smem);
    const int t   = threadIdx.x;
    const int wid = t >> 5, l = t & 31;
    const int wm  = wid & 1;
    const int wn  = wid >> 1;
    const int m0  = blockIdx.y << 7, n0 = blockIdx.x << 8;

    if ((EPI == 2 || EPI == 4) && n0 >= __ldg(meta + 1)) return;
    const int K = (EPI == 3) ? __ldg(meta + 1) : Kstat;

    const uint32_t aoff = (uint32_t)(wm * 64 + (l & 7) + ((l >> 3) & 1) * 8) * TROW
                        + ((l >> 4) & 1) * 16;
    const uint32_t boff = (uint32_t)(wn * 64 + (l & 7) + ((l >> 4) & 1) * 8) * TROW
                        + ((l >> 3) & 1) * 16;
    const uint32_t bbase = (TERMS == 3 ? 2 : 1) * A_TSZ;

    float acc[4][8][4];
#pragma unroll
    for (int mf = 0; mf < 4; mf++)
#pragma unroll
        for (int nf = 0; nf < 8; nf++)
#pragma unroll
            for (int i = 0; i < 4; i++) acc[mf][nf][i] = 0.0f;

    const int nch = K / BK;

    load_chunk<TERMS>(sb, Ah, Al, Bh, Bl, LD, m0, n0, 0, t);        cp_commit();
    load_chunk<TERMS>(sb + STG, Ah, Al, Bh, Bl, LD, m0, n0, BK, t); cp_commit();

    for (int c = 0; c < nch; c++) {
        cp_wait1();
        __syncthreads();
        const uint32_t st = sb + (uint32_t)(c & 1) * STG;
#pragma unroll
        for (int ks = 0; ks < 4; ks++) {
            uint32_t ah[4][4], al[4][4], bh[4][4], bl[4][4];
#pragma unroll
            for (int mf = 0; mf < 4; mf++) {
                ldsm_x4(ah[mf], st + aoff + mf * (16 * TROW) + ks * 32);
                if (TERMS == 3)
                    ldsm_x4(al[mf], st + A_TSZ + aoff + mf * (16 * TROW) + ks * 32);
            }
#pragma unroll
            for (int nf2 = 0; nf2 < 4; nf2++) {
                ldsm_x4(bh[nf2], st + bbase + boff + nf2 * (16 * TROW) + ks * 32);
                if (TERMS >= 2)
                    ldsm_x4(bl[nf2], st + bbase + B_TSZ + boff + nf2 * (16 * TROW) + ks * 32);
            }
#pragma unroll
            for (int mf = 0; mf < 4; mf++)
#pragma unroll
                for (int nf = 0; nf < 8; nf++) {
                    const uint32_t* bhp = &bh[nf >> 1][(nf & 1) * 2];
                    const uint32_t* blp = &bl[nf >> 1][(nf & 1) * 2];
                    mma16816(acc[mf][nf], ah[mf], bhp);
                    if (TERMS >= 2) mma16816(acc[mf][nf], ah[mf], blp);
                    if (TERMS == 3) mma16816(acc[mf][nf], al[mf], bhp);
                }
        }
        __syncthreads();
        if (c + 2 < nch)
            load_chunk<TERMS>(sb + (uint32_t)(c & 1) * STG, Ah, Al, Bh, Bl,
                              LD, m0, n0, (c + 2) * BK, t);
        cp_commit();
    }

    const int mact = (EPI == 2) ? __ldg(meta + 0) : 0;

#pragma unroll
    for (int mf = 0; mf < 4; mf++) {
        const int r0 = m0 + wm * 64 + mf * 16 + (l >> 2);
        float s0 = 0.f, s1 = 0.f;
        if (EPI == 3) { s0 = __ldg(rowscale + r0); s1 = __ldg(rowscale + r0 + 8); }
#pragma unroll
        for (int nf = 0; nf < 8; nf++) {
            const int c0 = n0 + wn * 64 + nf * 8 + ((l & 3) << 1);
            float v0 = acc[mf][nf][0], v1 = acc[mf][nf][1];
            float v2 = acc[mf][nf][2], v3 = acc[mf][nf][3];
            if (EPI == 1) {
                const float b0 = __ldg(bias + c0), b1 = __ldg(bias + c0 + 1);
                v0 += b0; v1 += b1; v2 += b0; v3 += b1;
                *(float2*)(C + (size_t)r0 * Ntot + c0)       = make_float2(v0, v1);
                *(float2*)(C + (size_t)(r0 + 8) * Ntot + c0) = make_float2(v2, v3);
            }
            if (EPI == 2) {
                const bool u0 = c0 < mact, u1 = (c0 + 1) < mact;
                const float e0 = u0 ? __expf(fmaf(v0, 10.f, -10.f)) * EXP_SCALE : 0.f;
                const float e1 = u1 ? __expf(fmaf(v1, 10.f, -10.f)) * EXP_SCALE : 0.f;
                const float e2 = u0 ? __expf(fmaf(v2, 10.f, -10.f)) * EXP_SCALE : 0.f;
                const float e3 = u1 ? __expf(fmaf(v3, 10.f, -10.f)) * EXP_SCALE : 0.f;
                *(__half2*)(Ch + (size_t)r0 * Ntot + c0) =
                    __halves2half2(__float2half_rn(e0), __float2half_rn(e1));
                *(__half2*)(Ch + (size_t)(r0 + 8) * Ntot + c0) =
                    __halves2half2(__float2half_rn(e2), __float2half_rn(e3));
            }
            if (EPI == 3) {
                const float b0 = __ldg(bias + c0), b1 = __ldg(bias + c0 + 1);
                v0 = fmaf(v0, s0, b0); v1 = fmaf(v1, s0, b1);
                v2 = fmaf(v2, s1, b0); v3 = fmaf(v3, s1, b1);
                *(float2*)(C + (size_t)r0 * Ntot + c0)       = make_float2(v0, v1);
                *(float2*)(C + (size_t)(r0 + 8) * Ntot + c0) = make_float2(v2, v3);
            }
            if (EPI == 4) {
                *(__half2*)(Ch + (size_t)r0 * Ntot + c0) =
                    __halves2half2(__float2half_rn(v0), __float2half_rn(v1));
                *(__half2*)(Ch + (size_t)(r0 + 8) * Ntot + c0) =
                    __halves2half2(__float2half_rn(v2), __float2half_rn(v3));
            }
        }
    }
}

// ---------------------------------------------------------------------------
// Elementwise fp32 -> (hi, lo) fp16 split
// ---------------------------------------------------------------------------
__global__ void split_kernel(const float* __restrict__ in, __half* __restrict__ oh,
                             __half* __restrict__ ol, int n4)
{
    int idx = blockIdx.x * blockDim.x + threadIdx.x;
    const int stride = gridDim.x * blockDim.x;
    for (; idx < n4; idx += stride) {
        float4 v = ((const float4*)in)[idx];
        __half h0, l0, h1, l1, h2, l2, h3, l3;
        split1(v.x, h0, l0); split1(v.y, h1, l1); split1(v.z, h2, l2); split1(v.w, h3, l3);
        ((__half2*)oh)[idx * 2 + 0] = __halves2half2(h0, h1);
        ((__half2*)oh)[idx * 2 + 1] = __halves2half2(h2, h3);
        ((__half2*)ol)[idx * 2 + 0] = __halves2half2(l0, l1);
        ((__half2*)ol)[idx * 2 + 1] = __halves2half2(l2, l3);
    }
}

// ---------------------------------------------------------------------------
// Elementwise fp32 -> fp16 (hi only)
// ---------------------------------------------------------------------------
__global__ void convert_hi_kernel(const float* __restrict__ in, __half* __restrict__ oh, int n4)
{
    int idx = blockIdx.x * blockDim.x + threadIdx.x;
    const int stride = gridDim.x * blockDim.x;
    for (; idx < n4; idx += stride) {
        float4 v = ((const float4*)in)[idx];
        ((__half2*)oh)[idx * 2 + 0] = __halves2half2(__float2half_rn(v.x), __float2half_rn(v.y));
        ((__half2*)oh)[idx * 2 + 1] = __halves2half2(__float2half_rn(v.z), __float2half_rn(v.w));
    }
}

// ---------------------------------------------------------------------------
// Row L2-style normalize, fp16 hi only (for q)
// ---------------------------------------------------------------------------
__global__ void rownorm_hi_kernel(const float* __restrict__ in, __half* __restrict__ oh)
{
    __shared__ float sh[4];
    const int row = blockIdx.x;
    const int tid = threadIdx.x;
    float4 v = ((const float4*)(in + (size_t)row * H_DIM))[tid];
    float s = v.x * v.x + v.y * v.y + v.z * v.z + v.w * v.w;
#pragma unroll
    for (int o = 16; o; o >>= 1) s += __shfl_xor_sync(0xffffffffu, s, o);
    if ((tid & 31) == 0) sh[tid >> 5] = s;
    __syncthreads();
    const float r = rsqrtf(sh[0] + sh[1] + sh[2] + sh[3] + 1e-6f);
    const size_t off = (size_t)row * H_DIM + tid * 4;
    *(__half2*)(oh + off + 0) = __halves2half2(__float2half_rn(v.x * r), __float2half_rn(v.y * r));
    *(__half2*)(oh + off + 2) = __halves2half2(__float2half_rn(v.z * r), __float2half_rn(v.w * r));
}

// ---------------------------------------------------------------------------
// Row sums of exp buffer (fp16, dynamic width meta[1]) -> rowscale = 1/sum
// ---------------------------------------------------------------------------
__global__ void rowsum_kernel(const __half* __restrict__ e, float* __restrict__ rowscale,
                              const int* __restrict__ meta)
{
    __shared__ float sh[8];
    const int tid = threadIdx.x;
    const int nh8 = __ldg(meta + 1) >> 3;
    const uint4* p = (const uint4*)(e + (size_t)blockIdx.x * M_MEM);

    float s = 0.0f;
#pragma unroll
    for (int i = 0; i < 2; i++) {
        const int fi = tid + (i << 8);
        if (fi < nh8) {
            uint4 u = p[fi];
            float2 a = __half22float2(*(const __half2*)&u.x);
            float2 b = __half22float2(*(const __half2*)&u.y);
            float2 c = __half22float2(*(const __half2*)&u.z);
            float2 d = __half22float2(*(const __half2*)&u.w);
            s += (a.x + a.y) + (b.x + b.y) + (c.x + c.y) + (d.x + d.y);
        }
    }
#pragma unroll
    for (int o = 16; o; o >>= 1) s += __shfl_xor_sync(0xffffffffu, s, o);
    if ((tid & 31) == 0) sh[tid >> 5] = s;
    __syncthreads();
    if (tid == 0) {
        float tot = sh[0];
#pragma unroll
        for (int i = 1; i < 8; i++) tot += sh[i];
        rowscale[blockIdx.x] = 1.0f / tot;
    }
}

// ---------------------------------------------------------------------------
// Launch pipeline
// ---------------------------------------------------------------------------
extern "C" void kernel_launch(void* const* d_in, const int* in_sizes, int n_in,
                              void* d_out, int out_size)
{
    const float* hidden = (const float*)d_in[0];
    const float* mk     = (const float*)d_in[1];
    const float* mv     = (const float*)d_in[2];
    const float* Wk     = (const float*)d_in[3];
    const float* bk     = (const float*)d_in[4];
    const float* Wo     = (const float*)d_in[5];
    const float* bo     = (const float*)d_in[6];
    const int*   usage  = (const int*)d_in[7];
    float* out = (float*)d_out;

    __half *hid_hi, *wk_hi, *wk_lo, *wo_hi, *wo_lo, *mv_hi, *mv_lo;
    __half *mk_hi, *mk_lo, *w2t_hi, *q_hi, *expp;
    float *qp, *rsp;
    int *idxp, *metap;
    cudaGetSymbolAddress((void**)&hid_hi, g_hid_hi);
    cudaGetSymbolAddress((void**)&wk_hi, g_wk_hi);
    cudaGetSymbolAddress((void**)&wk_lo, g_wk_lo);
    cudaGetSymbolAddress((void**)&wo_hi, g_wo_hi);
    cudaGetSymbolAddress((void**)&wo_lo, g_wo_lo);
    cudaGetSymbolAddress((void**)&mv_hi, g_mv_hi);
    cudaGetSymbolAddress((void**)&mv_lo, g_mv_lo);
    cudaGetSymbolAddress((void**)&mk_hi, g_mk_hi);
    cudaGetSymbolAddress((void**)&mk_lo, g_mk_lo);
    cudaGetSymbolAddress((void**)&w2t_hi, g_w2t_hi);
    cudaGetSymbolAddress((void**)&qp, g_q);
    cudaGetSymbolAddress((void**)&q_hi, g_q_hi);
    cudaGetSymbolAddress((void**)&expp, g_exp);
    cudaGetSymbolAddress((void**)&rsp, g_rowscale);
    cudaGetSymbolAddress((void**)&idxp, g_idx);
    cudaGetSymbolAddress((void**)&metap, g_meta);

    cudaFuncSetAttribute(mm_gemm<1,2>, cudaFuncAttributeMaxDynamicSharedMemorySize, MM_SMEM2);
    cudaFuncSetAttribute(mm_gemm<4,3>, cudaFuncAttributeMaxDynamicSharedMemorySize, MM_SMEM3);
    cudaFuncSetAttribute(mm_gemm<2,2>, cudaFuncAttributeMaxDynamicSharedMemorySize, MM_SMEM2);
    cudaFuncSetAttribute(mm_gemm<3,1>, cudaFuncAttributeMaxDynamicSharedMemorySize, MM_SMEM1);

    // compaction + splits/conversions
    compact_kernel<<<1, 1024>>>(usage, idxp, metap);
    convert_hi_kernel<<<2048, 256>>>(hidden, hid_hi, T_TOK * H_DIM / 4);
    split_kernel<<<256, 256>>>(Wk, wk_hi, wk_lo, H_DIM * H_DIM / 4);
    split_kernel<<<256, 256>>>(Wo, wo_hi, wo_lo, H_DIM * H_DIM / 4);
    gather_split_kernel<<<M_MEM, 128>>>(mv, idxp, metap, mv_hi, mv_lo);
    gather_rownorm_split_kernel<<<M_MEM, 128>>>(mk, idxp, metap, mk_hi, mk_lo);

    // W2T[h,j] = sum_v Wo[h,v] * mv_c[j,v]  (3-term; write hi fp16)
    mm_gemm<4,3><<<dim3(M_MEM / 256, H_DIM / 128), 256, MM_SMEM3>>>(
        wo_hi, wo_lo, mv_hi, mv_lo, nullptr, w2t_hi,
        M_MEM, H_DIM, H_DIM, metap, nullptr, nullptr);

    // q = hidden_hi @ (Wk_hi + Wk_lo)^T + bk  (2-term)
    mm_gemm<1,2><<<dim3(H_DIM / 256, T_TOK / 128), 256, MM_SMEM2>>>(
        hid_hi, nullptr, wk_hi, wk_lo, qp, nullptr,
        H_DIM, H_DIM, H_DIM, nullptr, bk, nullptr);
    rownorm_hi_kernel<<<T_TOK, 128>>>(qp, q_hi);

    // exp scores over compacted bank (2-term): e = exp(10*cos - 10)*8192, fp16
    mm_gemm<2,2><<<dim3(M_MEM / 256, T_TOK / 128), 256, MM_SMEM2>>>(
        q_hi, nullptr, mk_hi, mk_lo, nullptr, expp,
        M_MEM, H_DIM, H_DIM, metap, nullptr, nullptr);

    // row sums -> rowscale
    rowsum_kernel<<<T_TOK, 256>>>(expp, rsp, metap);

    // out = (exp @ w2t_hi^T) * rowscale + bo  (1-term, dynamic K)
    mm_gemm<3,1><<<dim3(H_DIM / 256, T_TOK / 128), 256, MM_SMEM1>>>(
        expp, nullptr, w2t_hi, nullptr, out, nullptr,
        H_DIM, M_MEM, 0, metap, bo, rsp);
}

// round 10
// speedup vs baseline: 3.7690x; 1.2513x over previous
#include <cuda_runtime.h>
#include <cuda_fp16.h>
#include <cstdint>

#define T_TOK 16384
#define H_DIM 512
#define M_MEM 4096
#define EXP_SCALE 8192.0f

// ---------------------------------------------------------------------------
// Scratch (static device globals; no allocations anywhere)
// ---------------------------------------------------------------------------
__device__ __half g_hid_hi[(size_t)T_TOK * H_DIM];
__device__ __half g_wk_hi[(size_t)H_DIM * H_DIM];
__device__ __half g_wo_hi[(size_t)H_DIM * H_DIM];
__device__ __half g_wo_lo[(size_t)H_DIM * H_DIM];
__device__ __half g_mv_hi[(size_t)M_MEM * H_DIM];   // compacted mv
__device__ __half g_mv_lo[(size_t)M_MEM * H_DIM];
__device__ __half g_mk_hi[(size_t)M_MEM * H_DIM];   // compacted, normalized mk (hi only)
__device__ __half g_w2t_hi[(size_t)H_DIM * M_MEM];  // W2T over compacted bank (hi only)
__device__ float  g_q[(size_t)T_TOK * H_DIM];
__device__ __half g_q_hi[(size_t)T_TOK * H_DIM];
__device__ __half g_exp[(size_t)T_TOK * M_MEM];     // exp(logit-10)*8192, compacted cols
__device__ float  g_rowscale[T_TOK];                // 1 / rowsum(g_exp)
__device__ int    g_idx[M_MEM];                     // compacted slot -> original slot
__device__ int    g_meta[2];                        // [0]=M_active, [1]=pad256(M_active)

// ---------------------------------------------------------------------------
// Helpers (baseline PTX only: cp.async / ldmatrix / mma.sync)
// ---------------------------------------------------------------------------
__device__ __forceinline__ uint32_t su32(const void* p) {
    return (uint32_t)__cvta_generic_to_shared(p);
}
__device__ __forceinline__ void cp16(uint32_t dst, const void* src) {
    asm volatile("cp.async.cg.shared.global [%0], [%1], 16;\n" :: "r"(dst), "l"(src) : "memory");
}
__device__ __forceinline__ void cp_commit() { asm volatile("cp.async.commit_group;\n" ::: "memory"); }
__device__ __forceinline__ void cp_wait1()  { asm volatile("cp.async.wait_group 1;\n" ::: "memory"); }

__device__ __forceinline__ void ldsm_x4(uint32_t* r, uint32_t addr) {
    asm volatile("ldmatrix.sync.aligned.m8n8.x4.shared.b16 {%0,%1,%2,%3}, [%4];"
                 : "=r"(r[0]), "=r"(r[1]), "=r"(r[2]), "=r"(r[3]) : "r"(addr));
}
__device__ __forceinline__ void mma16816(float* c, const uint32_t* a, const uint32_t* b) {
    asm volatile(
        "mma.sync.aligned.m16n8k16.row.col.f32.f16.f16.f32 "
        "{%0,%1,%2,%3}, {%4,%5,%6,%7}, {%8,%9}, {%0,%1,%2,%3};"
        : "+f"(c[0]), "+f"(c[1]), "+f"(c[2]), "+f"(c[3])
        : "r"(a[0]), "r"(a[1]), "r"(a[2]), "r"(a[3]), "r"(b[0]), "r"(b[1]));
}

__device__ __forceinline__ void split1(float x, __half& h, __half& l) {
    h = __float2half_rn(x);
    l = __float2half_rn(x - __half2float(h));
}

// ---------------------------------------------------------------------------
// Compaction: stable prefix-scan over usage>0 -> idx list + meta
// ---------------------------------------------------------------------------
__global__ void compact_kernel(const int* __restrict__ usage, int* __restrict__ idx,
                               int* __restrict__ meta)
{
    __shared__ int wsum[32];
    const int t = threadIdx.x, lane = t & 31, w = t >> 5;
    const int base = t * 4;
    int f[4], cnt = 0;
#pragma unroll
    for (int i = 0; i < 4; i++) { f[i] = usage[base + i] > 0; cnt += f[i]; }
    int inc = cnt;
#pragma unroll
    for (int o = 1; o < 32; o <<= 1) {
        int v = __shfl_up_sync(0xffffffffu, inc, o);
        if (lane >= o) inc += v;
    }
    const int exc = inc - cnt;
    if (lane == 31) wsum[w] = inc;
    __syncthreads();
    if (w == 0) {
        int v = wsum[lane];
        __syncwarp();
#pragma unroll
        for (int o = 1; o < 32; o <<= 1) {
            int u = __shfl_up_sync(0xffffffffu, v, o);
            if (lane >= o) v += u;
        }
        wsum[lane] = v;
    }
    __syncthreads();
    int pos = (w > 0 ? wsum[w - 1] : 0) + exc;
#pragma unroll
    for (int i = 0; i < 4; i++)
        if (f[i]) idx[pos++] = base + i;
    if (t == 1023) {
        const int tot = wsum[31];
        meta[0] = tot;
        int pad = ((tot + 255) >> 8) << 8;
        meta[1] = pad < 256 ? 256 : pad;
    }
}

// ---------------------------------------------------------------------------
// Gather + fp16 split (mv). Block j handles compacted row j (zeros if padded).
// ---------------------------------------------------------------------------
__global__ void gather_split_kernel(const float* __restrict__ in, const int* __restrict__ idx,
                                    const int* __restrict__ meta,
                                    __half* __restrict__ oh, __half* __restrict__ ol)
{
    const int j = blockIdx.x, tid = threadIdx.x;
    const size_t off = (size_t)j * H_DIM + tid * 4;
    if (j >= meta[0]) {
        const __half2 z = __halves2half2(__float2half_rn(0.f), __float2half_rn(0.f));
        *(__half2*)(oh + off + 0) = z; *(__half2*)(oh + off + 2) = z;
        *(__half2*)(ol + off + 0) = z; *(__half2*)(ol + off + 2) = z;
        return;
    }
    const int row = idx[j];
    float4 v = ((const float4*)(in + (size_t)row * H_DIM))[tid];
    __half h0, l0, h1, l1, h2, l2, h3, l3;
    split1(v.x, h0, l0); split1(v.y, h1, l1); split1(v.z, h2, l2); split1(v.w, h3, l3);
    *(__half2*)(oh + off + 0) = __halves2half2(h0, h1);
    *(__half2*)(oh + off + 2) = __halves2half2(h2, h3);
    *(__half2*)(ol + off + 0) = __halves2half2(l0, l1);
    *(__half2*)(ol + off + 2) = __halves2half2(l2, l3);
}

// ---------------------------------------------------------------------------
// Gather + row L2-normalize -> fp16 hi only (mk).
// ---------------------------------------------------------------------------
__global__ void gather_rownorm_hi_kernel(const float* __restrict__ in,
                                         const int* __restrict__ idx,
                                         const int* __restrict__ meta,
                                         __half* __restrict__ oh)
{
    __shared__ float sh[4];
    const int j = blockIdx.x, tid = threadIdx.x;
    const size_t off = (size_t)j * H_DIM + tid * 4;
    if (j >= meta[0]) {
        const __half2 z = __halves2half2(__float2half_rn(0.f), __float2half_rn(0.f));
        *(__half2*)(oh + off + 0) = z; *(__half2*)(oh + off + 2) = z;
        return;
    }
    const int row = idx[j];
    float4 v = ((const float4*)(in + (size_t)row * H_DIM))[tid];
    float s = v.x * v.x + v.y * v.y + v.z * v.z + v.w * v.w;
#pragma unroll
    for (int o = 16; o; o >>= 1) s += __shfl_xor_sync(0xffffffffu, s, o);
    if ((tid & 31) == 0) sh[tid >> 5] = s;
    __syncthreads();
    const float r = rsqrtf(sh[0] + sh[1] + sh[2] + sh[3] + 1e-6f);
    *(__half2*)(oh + off + 0) = __halves2half2(__float2half_rn(v.x * r), __float2half_rn(v.y * r));
    *(__half2*)(oh + off + 2) = __halves2half2(__float2half_rn(v.z * r), __float2half_rn(v.w * r));
}

// ---------------------------------------------------------------------------
// HMMA GEMM:  C[M,N] = terms(A,B)   (A:[M,K], B:[N,K], fp16, row.col)
// CTA tile 128x256, 8 warps (2x4) of 64x64, BK=64, double-buffered cp.async.
// TERMS=1: Ah*Bh;  TERMS=2: Ah*(Bh+Bl);  TERMS=3: + Al*Bh. fp32 accum.
// EPI: 1 +bias (fp32 out);
//      2 scores->exp fp16: e = col<mact ? expf(10*acc-10)*8192 : 0, to Ch;
//      3 retrieval: out = acc*rowscale[r] + bias, K dyn = meta[1];
//      4 write hi fp16 (Ch), early-exit n0 >= meta[1].
// ---------------------------------------------------------------------------
#define BK       64
#define TROW     144
#define A_TSZ    (128 * TROW)              // 18432 B
#define B_TSZ    (256 * TROW)              // 36864 B
#define MM_SMEM1 (2 * (A_TSZ + B_TSZ))          // 110592
#define MM_SMEM2 (2 * (A_TSZ + 2 * B_TSZ))      // 184320
#define MM_SMEM3 (2 * (2 * A_TSZ + 2 * B_TSZ))  // 221184

template <int TERMS>
__device__ __forceinline__ void load_chunk(uint32_t st,
    const __half* __restrict__ Ah, const __half* __restrict__ Al,
    const __half* __restrict__ Bh, const __half* __restrict__ Bl,
    int LD, int m0, int n0, int k0, int t)
{
#pragma unroll
    for (int i = 0; i < 4; i++) {
        const int idx = (i << 8) + t;
        const int row = idx >> 3, j = idx & 7;
        const uint32_t so = (uint32_t)(row * TROW + j * 16);
        const size_t  go = (size_t)(m0 + row) * LD + k0 + (j << 3);
        cp16(st + so, Ah + go);
        if (TERMS == 3) cp16(st + A_TSZ + so, Al + go);
    }
    const uint32_t bb = st + (TERMS == 3 ? 2 : 1) * A_TSZ;
#pragma unroll
    for (int i = 0; i < 8; i++) {
        const int idx = (i << 8) + t;
        const int row = idx >> 3, j = idx & 7;
        const uint32_t so = (uint32_t)(row * TROW + j * 16);
        const size_t  go = (size_t)(n0 + row) * LD + k0 + (j << 3);
        cp16(bb + so, Bh + go);
        if (TERMS >= 2) cp16(bb + B_TSZ + so, Bl + go);
    }
}

template <int EPI, int TERMS>
__global__ __launch_bounds__(256, 1)
void mm_gemm(const __half* __restrict__ Ah, const __half* __restrict__ Al,
             const __half* __restrict__ Bh, const __half* __restrict__ Bl,
             float* __restrict__ C, __half* __restrict__ Ch,
             int Ntot, int LD, int Kstat,
             const int* __restrict__ meta, const float* __restrict__ bias,
             const float* __restrict__ rowscale)
{
    constexpr uint32_t STG = (TERMS == 3 ? 2 : 1) * A_TSZ + (TERMS >= 2 ? 2 : 1) * B_TSZ;
    extern __shared__ char smem[];
    const uint32_t sb = su32(smem);
    const int t   = threadIdx.x;
    const int wid = t >> 5, l = t & 31;
    const int wm  = wid & 1;
    const int wn  = wid >> 1;
    const int m0  = blockIdx.y << 7, n0 = blockIdx.x << 8;

    if ((EPI == 2 || EPI == 4) && n0 >= __ldg(meta + 1)) return;
    const int K = (EPI == 3) ? __ldg(meta + 1) : Kstat;

    const uint32_t aoff = (uint32_t)(wm * 64 + (l & 7) + ((l >> 3) & 1) * 8) * TROW
                        + ((l >> 4) & 1) * 16;
    const uint32_t boff = (uint32_t)(wn * 64 + (l & 7) + ((l >> 4) & 1) * 8) * TROW
                        + ((l >> 3) & 1) * 16;
    const uint32_t bbase = (TERMS == 3 ? 2 : 1) * A_TSZ;

    float acc[4][8][4];
#pragma unroll
    for (int mf = 0; mf < 4; mf++)
#pragma unroll
        for (int nf = 0; nf < 8; nf++)
#pragma unroll
            for (int i = 0; i < 4; i++) acc[mf][nf][i] = 0.0f;

    const int nch = K / BK;

    load_chunk<TERMS>(sb, Ah, Al, Bh, Bl, LD, m0, n0, 0, t);        cp_commit();
    load_chunk<TERMS>(sb + STG, Ah, Al, Bh, Bl, LD, m0, n0, BK, t); cp_commit();

    for (int c = 0; c < nch; c++) {
        cp_wait1();
        __syncthreads();
        const uint32_t st = sb + (uint32_t)(c & 1) * STG;
#pragma unroll
        for (int ks = 0; ks < 4; ks++) {
            uint32_t ah[4][4], al[4][4], bh[4][4], bl[4][4];
#pragma unroll
            for (int mf = 0; mf < 4; mf++) {
                ldsm_x4(ah[mf], st + aoff + mf * (16 * TROW) + ks * 32);
                if (TERMS == 3)
                    ldsm_x4(al[mf], st + A_TSZ + aoff + mf * (16 * TROW) + ks * 32);
            }
#pragma unroll
            for (int nf2 = 0; nf2 < 4; nf2++) {
                ldsm_x4(bh[nf2], st + bbase + boff + nf2 * (16 * TROW) + ks * 32);
                if (TERMS >= 2)
                    ldsm_x4(bl[nf2], st + bbase + B_TSZ + boff + nf2 * (16 * TROW) + ks * 32);
            }
#pragma unroll
            for (int mf = 0; mf < 4; mf++)
#pragma unroll
                for (int nf = 0; nf < 8; nf++) {
                    const uint32_t* bhp = &bh[nf >> 1][(nf & 1) * 2];
                    const uint32_t* blp = &bl[nf >> 1][(nf & 1) * 2];
                    mma16816(acc[mf][nf], ah[mf], bhp);
                    if (TERMS >= 2) mma16816(acc[mf][nf], ah[mf], blp);
                    if (TERMS == 3) mma16816(acc[mf][nf], al[mf], bhp);
                }
        }
        __syncthreads();
        if (c + 2 < nch)
            load_chunk<TERMS>(sb + (uint32_t)(c & 1) * STG, Ah, Al, Bh, Bl,
                              LD, m0, n0, (c + 2) * BK, t);
        cp_commit();
    }

    const int mact = (EPI == 2) ? __ldg(meta + 0) : 0;

#pragma unroll
    for (int mf = 0; mf < 4; mf++) {
        const int r0 = m0 + wm * 64 + mf * 16 + (l >> 2);
        float s0 = 0.f, s1 = 0.f;
        if (EPI == 3) { s0 = __ldg(rowscale + r0); s1 = __ldg(rowscale + r0 + 8); }
#pragma unroll
        for (int nf = 0; nf < 8; nf++) {
            const int c0 = n0 + wn * 64 + nf * 8 + ((l & 3) << 1);
            float v0 = acc[mf][nf][0], v1 = acc[mf][nf][1];
            float v2 = acc[mf][nf][2], v3 = acc[mf][nf][3];
            if (EPI == 1) {
                const float b0 = __ldg(bias + c0), b1 = __ldg(bias + c0 + 1);
                v0 += b0; v1 += b1; v2 += b0; v3 += b1;
                *(float2*)(C + (size_t)r0 * Ntot + c0)       = make_float2(v0, v1);
                *(float2*)(C + (size_t)(r0 + 8) * Ntot + c0) = make_float2(v2, v3);
            }
            if (EPI == 2) {
                const bool u0 = c0 < mact, u1 = (c0 + 1) < mact;
                const float e0 = u0 ? __expf(fmaf(v0, 10.f, -10.f)) * EXP_SCALE : 0.f;
                const float e1 = u1 ? __expf(fmaf(v1, 10.f, -10.f)) * EXP_SCALE : 0.f;
                const float e2 = u0 ? __expf(fmaf(v2, 10.f, -10.f)) * EXP_SCALE : 0.f;
                const float e3 = u1 ? __expf(fmaf(v3, 10.f, -10.f)) * EXP_SCALE : 0.f;
                *(__half2*)(Ch + (size_t)r0 * Ntot + c0) =
                    __halves2half2(__float2half_rn(e0), __float2half_rn(e1));
                *(__half2*)(Ch + (size_t)(r0 + 8) * Ntot + c0) =
                    __halves2half2(__float2half_rn(e2), __float2half_rn(e3));
            }
            if (EPI == 3) {
                const float b0 = __ldg(bias + c0), b1 = __ldg(bias + c0 + 1);
                v0 = fmaf(v0, s0, b0); v1 = fmaf(v1, s0, b1);
                v2 = fmaf(v2, s1, b0); v3 = fmaf(v3, s1, b1);
                *(float2*)(C + (size_t)r0 * Ntot + c0)       = make_float2(v0, v1);
                *(float2*)(C + (size_t)(r0 + 8) * Ntot + c0) = make_float2(v2, v3);
            }
            if (EPI == 4) {
                *(__half2*)(Ch + (size_t)r0 * Ntot + c0) =
                    __halves2half2(__float2half_rn(v0), __float2half_rn(v1));
                *(__half2*)(Ch + (size_t)(r0 + 8) * Ntot + c0) =
                    __halves2half2(__float2half_rn(v2), __float2half_rn(v3));
            }
        }
    }
}

// ---------------------------------------------------------------------------
// Elementwise fp32 -> (hi, lo) fp16 split
// ---------------------------------------------------------------------------
__global__ void split_kernel(const float* __restrict__ in, __half* __restrict__ oh,
                             __half* __restrict__ ol, int n4)
{
    int idx = blockIdx.x * blockDim.x + threadIdx.x;
    const int stride = gridDim.x * blockDim.x;
    for (; idx < n4; idx += stride) {
        float4 v = ((const float4*)in)[idx];
        __half h0, l0, h1, l1, h2, l2, h3, l3;
        split1(v.x, h0, l0); split1(v.y, h1, l1); split1(v.z, h2, l2); split1(v.w, h3, l3);
        ((__half2*)oh)[idx * 2 + 0] = __halves2half2(h0, h1);
        ((__half2*)oh)[idx * 2 + 1] = __halves2half2(h2, h3);
        ((__half2*)ol)[idx * 2 + 0] = __halves2half2(l0, l1);
        ((__half2*)ol)[idx * 2 + 1] = __halves2half2(l2, l3);
    }
}

// ---------------------------------------------------------------------------
// Elementwise fp32 -> fp16 (hi only)
// ---------------------------------------------------------------------------
__global__ void convert_hi_kernel(const float* __restrict__ in, __half* __restrict__ oh, int n4)
{
    int idx = blockIdx.x * blockDim.x + threadIdx.x;
    const int stride = gridDim.x * blockDim.x;
    for (; idx < n4; idx += stride) {
        float4 v = ((const float4*)in)[idx];
        ((__half2*)oh)[idx * 2 + 0] = __halves2half2(__float2half_rn(v.x), __float2half_rn(v.y));
        ((__half2*)oh)[idx * 2 + 1] = __halves2half2(__float2half_rn(v.z), __float2half_rn(v.w));
    }
}

// ---------------------------------------------------------------------------
// Row L2-style normalize, fp16 hi only (for q)
// ---------------------------------------------------------------------------
__global__ void rownorm_hi_kernel(const float* __restrict__ in, __half* __restrict__ oh)
{
    __shared__ float sh[4];
    const int row = blockIdx.x;
    const int tid = threadIdx.x;
    float4 v = ((const float4*)(in + (size_t)row * H_DIM))[tid];
    float s = v.x * v.x + v.y * v.y + v.z * v.z + v.w * v.w;
#pragma unroll
    for (int o = 16; o; o >>= 1) s += __shfl_xor_sync(0xffffffffu, s, o);
    if ((tid & 31) == 0) sh[tid >> 5] = s;
    __syncthreads();
    const float r = rsqrtf(sh[0] + sh[1] + sh[2] + sh[3] + 1e-6f);
    const size_t off = (size_t)row * H_DIM + tid * 4;
    *(__half2*)(oh + off + 0) = __halves2half2(__float2half_rn(v.x * r), __float2half_rn(v.y * r));
    *(__half2*)(oh + off + 2) = __halves2half2(__float2half_rn(v.z * r), __float2half_rn(v.w * r));
}

// ---------------------------------------------------------------------------
// Row sums of exp buffer (fp16, dynamic width meta[1]) -> rowscale = 1/sum
// ---------------------------------------------------------------------------
__global__ void rowsum_kernel(const __half* __restrict__ e, float* __restrict__ rowscale,
                              const int* __restrict__ meta)
{
    __shared__ float sh[8];
    const int tid = threadIdx.x;
    const int nh8 = __ldg(meta + 1) >> 3;
    const uint4* p = (const uint4*)(e + (size_t)blockIdx.x * M_MEM);

    float s = 0.0f;
#pragma unroll
    for (int i = 0; i < 2; i++) {
        const int fi = tid + (i << 8);
        if (fi < nh8) {
            uint4 u = p[fi];
            float2 a = __half22float2(*(const __half2*)&u.x);
            float2 b = __half22float2(*(const __half2*)&u.y);
            float2 c = __half22float2(*(const __half2*)&u.z);
            float2 d = __half22float2(*(const __half2*)&u.w);
            s += (a.x + a.y) + (b.x + b.y) + (c.x + c.y) + (d.x + d.y);
        }
    }
#pragma unroll
    for (int o = 16; o; o >>= 1) s += __shfl_xor_sync(0xffffffffu, s, o);
    if ((tid & 31) == 0) sh[tid >> 5] = s;
    __syncthreads();
    if (tid == 0) {
        float tot = sh[0];
#pragma unroll
        for (int i = 1; i < 8; i++) tot += sh[i];
        rowscale[blockIdx.x] = 1.0f / tot;
    }
}

// ---------------------------------------------------------------------------
// Launch pipeline
// ---------------------------------------------------------------------------
extern "C" void kernel_launch(void* const* d_in, const int* in_sizes, int n_in,
                              void* d_out, int out_size)
{
    const float* hidden = (const float*)d_in[0];
    const float* mk     = (const float*)d_in[1];
    const float* mv     = (const float*)d_in[2];
    const float* Wk     = (const float*)d_in[3];
    const float* bk     = (const float*)d_in[4];
    const float* Wo     = (const float*)d_in[5];
    const float* bo     = (const float*)d_in[6];
    const int*   usage  = (const int*)d_in[7];
    float* out = (float*)d_out;

    __half *hid_hi, *wk_hi, *wo_hi, *wo_lo, *mv_hi, *mv_lo;
    __half *mk_hi, *w2t_hi, *q_hi, *expp;
    float *qp, *rsp;
    int *idxp, *metap;
    cudaGetSymbolAddress((void**)&hid_hi, g_hid_hi);
    cudaGetSymbolAddress((void**)&wk_hi, g_wk_hi);
    cudaGetSymbolAddress((void**)&wo_hi, g_wo_hi);
    cudaGetSymbolAddress((void**)&wo_lo, g_wo_lo);
    cudaGetSymbolAddress((void**)&mv_hi, g_mv_hi);
    cudaGetSymbolAddress((void**)&mv_lo, g_mv_lo);
    cudaGetSymbolAddress((void**)&mk_hi, g_mk_hi);
    cudaGetSymbolAddress((void**)&w2t_hi, g_w2t_hi);
    cudaGetSymbolAddress((void**)&qp, g_q);
    cudaGetSymbolAddress((void**)&q_hi, g_q_hi);
    cudaGetSymbolAddress((void**)&expp, g_exp);
    cudaGetSymbolAddress((void**)&rsp, g_rowscale);
    cudaGetSymbolAddress((void**)&idxp, g_idx);
    cudaGetSymbolAddress((void**)&metap, g_meta);

    cudaFuncSetAttribute(mm_gemm<1,1>, cudaFuncAttributeMaxDynamicSharedMemorySize, MM_SMEM1);
    cudaFuncSetAttribute(mm_gemm<4,3>, cudaFuncAttributeMaxDynamicSharedMemorySize, MM_SMEM3);
    cudaFuncSetAttribute(mm_gemm<2,1>, cudaFuncAttributeMaxDynamicSharedMemorySize, MM_SMEM1);
    cudaFuncSetAttribute(mm_gemm<3,1>, cudaFuncAttributeMaxDynamicSharedMemorySize, MM_SMEM1);

    // compaction + splits/conversions
    compact_kernel<<<1, 1024>>>(usage, idxp, metap);
    convert_hi_kernel<<<2048, 256>>>(hidden, hid_hi, T_TOK * H_DIM / 4);
    convert_hi_kernel<<<256, 256>>>(Wk, wk_hi, H_DIM * H_DIM / 4);
    split_kernel<<<256, 256>>>(Wo, wo_hi, wo_lo, H_DIM * H_DIM / 4);
    gather_split_kernel<<<M_MEM, 128>>>(mv, idxp, metap, mv_hi, mv_lo);
    gather_rownorm_hi_kernel<<<M_MEM, 128>>>(mk, idxp, metap, mk_hi);

    // W2T[h,j] = sum_v Wo[h,v] * mv_c[j,v]  (3-term; write hi fp16)
    mm_gemm<4,3><<<dim3(M_MEM / 256, H_DIM / 128), 256, MM_SMEM3>>>(
        wo_hi, wo_lo, mv_hi, mv_lo, nullptr, w2t_hi,
        M_MEM, H_DIM, H_DIM, metap, nullptr, nullptr);

    // q = hidden_hi @ wk_hi^T + bk  (1-term)
    mm_gemm<1,1><<<dim3(H_DIM / 256, T_TOK / 128), 256, MM_SMEM1>>>(
        hid_hi, nullptr, wk_hi, nullptr, qp, nullptr,
        H_DIM, H_DIM, H_DIM, nullptr, bk, nullptr);
    rownorm_hi_kernel<<<T_TOK, 128>>>(qp, q_hi);

    // exp scores over compacted bank (1-term): e = exp(10*cos - 10)*8192, fp16
    mm_gemm<2,1><<<dim3(M_MEM / 256, T_TOK / 128), 256, MM_SMEM1>>>(
        q_hi, nullptr, mk_hi, nullptr, nullptr, expp,
        M_MEM, H_DIM, H_DIM, metap, nullptr, nullptr);

    // row sums -> rowscale
    rowsum_kernel<<<T_TOK, 256>>>(expp, rsp, metap);

    // out = (exp @ w2t_hi^T) * rowscale + bo  (1-term, dynamic K)
    mm_gemm<3,1><<<dim3(H_DIM / 256, T_TOK / 128), 256, MM_SMEM1>>>(
        expp, nullptr, w2t_hi, nullptr, out, nullptr,
        H_DIM, M_MEM, 0, metap, bo, rsp);
}

// round 11
// speedup vs baseline: 3.9244x; 1.0412x over previous
#include <cuda_runtime.h>
#include <cuda_fp16.h>
#include <cstdint>

#define T_TOK 16384
#define H_DIM 512
#define M_MEM 4096
#define EXP_SCALE 8192.0f

// ---------------------------------------------------------------------------
// Scratch (static device globals; no allocations anywhere)
// ---------------------------------------------------------------------------
__device__ __half g_hid_hi[(size_t)T_TOK * H_DIM];
__device__ __half g_wk_hi[(size_t)H_DIM * H_DIM];
__device__ __half g_wo_hi[(size_t)H_DIM * H_DIM];
__device__ __half g_wo_lo[(size_t)H_DIM * H_DIM];
__device__ __half g_mv_hi[(size_t)M_MEM * H_DIM];   // compacted mv
__device__ __half g_mv_lo[(size_t)M_MEM * H_DIM];
__device__ __half g_mk_hi[(size_t)M_MEM * H_DIM];   // compacted, normalized mk (hi only)
__device__ __half g_w2t_hi[(size_t)H_DIM * M_MEM];  // W2T over compacted bank (hi only)
__device__ __half g_q_hi[(size_t)T_TOK * H_DIM];    // q (+bk), fp16, unnormalized
__device__ __half g_exp[(size_t)T_TOK * M_MEM];     // exp(logit-10)*8192, compacted cols
__device__ float  g_qnorm[T_TOK];                   // sum q^2 per row (atomic)
__device__ float  g_rowsum[T_TOK];                  // sum exp per row (atomic)
__device__ int    g_idx[M_MEM];                     // compacted slot -> original slot
__device__ int    g_meta[2];                        // [0]=M_active, [1]=pad256(M_active)

// ---------------------------------------------------------------------------
// Helpers (baseline PTX only: cp.async / ldmatrix / mma.sync)
// ---------------------------------------------------------------------------
__device__ __forceinline__ uint32_t su32(const void* p) {
    return (uint32_t)__cvta_generic_to_shared(p);
}
__device__ __forceinline__ void cp16(uint32_t dst, const void* src) {
    asm volatile("cp.async.cg.shared.global [%0], [%1], 16;\n" :: "r"(dst), "l"(src) : "memory");
}
__device__ __forceinline__ void cp_commit() { asm volatile("cp.async.commit_group;\n" ::: "memory"); }
__device__ __forceinline__ void cp_wait1()  { asm volatile("cp.async.wait_group 1;\n" ::: "memory"); }

__device__ __forceinline__ void ldsm_x4(uint32_t* r, uint32_t addr) {
    asm volatile("ldmatrix.sync.aligned.m8n8.x4.shared.b16 {%0,%1,%2,%3}, [%4];"
                 : "=r"(r[0]), "=r"(r[1]), "=r"(r[2]), "=r"(r[3]) : "r"(addr));
}
__device__ __forceinline__ void mma16816(float* c, const uint32_t* a, const uint32_t* b) {
    asm volatile(
        "mma.sync.aligned.m16n8k16.row.col.f32.f16.f16.f32 "
        "{%0,%1,%2,%3}, {%4,%5,%6,%7}, {%8,%9}, {%0,%1,%2,%3};"
        : "+f"(c[0]), "+f"(c[1]), "+f"(c[2]), "+f"(c[3])
        : "r"(a[0]), "r"(a[1]), "r"(a[2]), "r"(a[3]), "r"(b[0]), "r"(b[1]));
}

__device__ __forceinline__ void split1(float x, __half& h, __half& l) {
    h = __float2half_rn(x);
    l = __float2half_rn(x - __half2float(h));
}

// ---------------------------------------------------------------------------
// Compaction: stable prefix-scan over usage>0 -> idx list + meta
// ---------------------------------------------------------------------------
__global__ void compact_kernel(const int* __restrict__ usage, int* __restrict__ idx,
                               int* __restrict__ meta)
{
    __shared__ int wsum[32];
    const int t = threadIdx.x, lane = t & 31, w = t >> 5;
    const int base = t * 4;
    int f[4], cnt = 0;
#pragma unroll
    for (int i = 0; i < 4; i++) { f[i] = usage[base + i] > 0; cnt += f[i]; }
    int inc = cnt;
#pragma unroll
    for (int o = 1; o < 32; o <<= 1) {
        int v = __shfl_up_sync(0xffffffffu, inc, o);
        if (lane >= o) inc += v;
    }
    const int exc = inc - cnt;
    if (lane == 31) wsum[w] = inc;
    __syncthreads();
    if (w == 0) {
        int v = wsum[lane];
        __syncwarp();
#pragma unroll
        for (int o = 1; o < 32; o <<= 1) {
            int u = __shfl_up_sync(0xffffffffu, v, o);
            if (lane >= o) v += u;
        }
        wsum[lane] = v;
    }
    __syncthreads();
    int pos = (w > 0 ? wsum[w - 1] : 0) + exc;
#pragma unroll
    for (int i = 0; i < 4; i++)
        if (f[i]) idx[pos++] = base + i;
    if (t == 1023) {
        const int tot = wsum[31];
        meta[0] = tot;
        int pad = ((tot + 255) >> 8) << 8;
        meta[1] = pad < 256 ? 256 : pad;
    }
}

// ---------------------------------------------------------------------------
// Bank prep: block j handles compacted row j of BOTH mv (hi/lo split) and
// mk (L2-normalized, hi only). Zeros for padded rows.
// ---------------------------------------------------------------------------
__global__ void prep_bank_kernel(const float* __restrict__ mv, const float* __restrict__ mk,
                                 const int* __restrict__ idx, const int* __restrict__ meta,
                                 __half* __restrict__ mvh, __half* __restrict__ mvl,
                                 __half* __restrict__ mkh)
{
    __shared__ float sh[4];
    const int j = blockIdx.x, tid = threadIdx.x;
    const size_t off = (size_t)j * H_DIM + tid * 4;
    if (j >= meta[0]) {
        const __half2 z = __halves2half2(__float2half_rn(0.f), __float2half_rn(0.f));
        *(__half2*)(mvh + off + 0) = z; *(__half2*)(mvh + off + 2) = z;
        *(__half2*)(mvl + off + 0) = z; *(__half2*)(mvl + off + 2) = z;
        *(__half2*)(mkh + off + 0) = z; *(__half2*)(mkh + off + 2) = z;
        return;
    }
    const int row = idx[j];
    // mv: plain hi/lo split
    {
        float4 v = ((const float4*)(mv + (size_t)row * H_DIM))[tid];
        __half h0, l0, h1, l1, h2, l2, h3, l3;
        split1(v.x, h0, l0); split1(v.y, h1, l1); split1(v.z, h2, l2); split1(v.w, h3, l3);
        *(__half2*)(mvh + off + 0) = __halves2half2(h0, h1);
        *(__half2*)(mvh + off + 2) = __halves2half2(h2, h3);
        *(__half2*)(mvl + off + 0) = __halves2half2(l0, l1);
        *(__half2*)(mvl + off + 2) = __halves2half2(l2, l3);
    }
    // mk: rownorm + hi
    {
        float4 v = ((const float4*)(mk + (size_t)row * H_DIM))[tid];
        float s = v.x * v.x + v.y * v.y + v.z * v.z + v.w * v.w;
#pragma unroll
        for (int o = 16; o; o >>= 1) s += __shfl_xor_sync(0xffffffffu, s, o);
        if ((tid & 31) == 0) sh[tid >> 5] = s;
        __syncthreads();
        const float r = rsqrtf(sh[0] + sh[1] + sh[2] + sh[3] + 1e-6f);
        *(__half2*)(mkh + off + 0) = __halves2half2(__float2half_rn(v.x * r), __float2half_rn(v.y * r));
        *(__half2*)(mkh + off + 2) = __halves2half2(__float2half_rn(v.z * r), __float2half_rn(v.w * r));
    }
}

// ---------------------------------------------------------------------------
// Weights prep: one thread per float4; Wk -> hi, Wo -> hi/lo.
// Launch with exactly H*H/4 threads.
// ---------------------------------------------------------------------------
__global__ void prep_w_kernel(const float* __restrict__ Wk, const float* __restrict__ Wo,
                              __half* __restrict__ wkh,
                              __half* __restrict__ woh, __half* __restrict__ wol)
{
    const int idx = blockIdx.x * blockDim.x + threadIdx.x;
    {
        float4 v = ((const float4*)Wk)[idx];
        ((__half2*)wkh)[idx * 2 + 0] = __halves2half2(__float2half_rn(v.x), __float2half_rn(v.y));
        ((__half2*)wkh)[idx * 2 + 1] = __halves2half2(__float2half_rn(v.z), __float2half_rn(v.w));
    }
    {
        float4 v = ((const float4*)Wo)[idx];
        __half h0, l0, h1, l1, h2, l2, h3, l3;
        split1(v.x, h0, l0); split1(v.y, h1, l1); split1(v.z, h2, l2); split1(v.w, h3, l3);
        ((__half2*)woh)[idx * 2 + 0] = __halves2half2(h0, h1);
        ((__half2*)woh)[idx * 2 + 1] = __halves2half2(h2, h3);
        ((__half2*)wol)[idx * 2 + 0] = __halves2half2(l0, l1);
        ((__half2*)wol)[idx * 2 + 1] = __halves2half2(l2, l3);
    }
}

// ---------------------------------------------------------------------------
// Elementwise fp32 -> fp16 (hidden)
// ---------------------------------------------------------------------------
__global__ void convert_hi_kernel(const float* __restrict__ in, __half* __restrict__ oh, int n4)
{
    int idx = blockIdx.x * blockDim.x + threadIdx.x;
    const int stride = gridDim.x * blockDim.x;
    for (; idx < n4; idx += stride) {
        float4 v = ((const float4*)in)[idx];
        ((__half2*)oh)[idx * 2 + 0] = __halves2half2(__float2half_rn(v.x), __float2half_rn(v.y));
        ((__half2*)oh)[idx * 2 + 1] = __halves2half2(__float2half_rn(v.z), __float2half_rn(v.w));
    }
}

// ---------------------------------------------------------------------------
// HMMA GEMM:  C[M,N] = terms(A,B)   (A:[M,K], B:[N,K], fp16, row.col)
// CTA tile 128x256, 8 warps (2x4) of 64x64, BK=64, double-buffered cp.async.
// TERMS=1: Ah*Bh;  TERMS=2: Ah*(Bh+Bl);  TERMS=3: + Al*Bh. fp32 accum.
// EPI: 2 scores: invq=rsqrt(rd[r]+eps); e = col<mact ? exp(10*acc*invq-10)*8192 : 0
//        -> Ch fp16; atomicAdd row partials of e into wr. Early-exit n0>=meta[1].
//      3 retrieval: out = acc*(1/rd[r]) + bias, K dyn = meta[1]. fp32 out.
//      4 W2T: write hi fp16 (Ch), early-exit n0 >= meta[1].
//      5 qproj: write fp16(acc+bias) to Ch; atomicAdd row partials of v^2 into wr.
// ---------------------------------------------------------------------------
#define BK       64
#define TROW     144
#define A_TSZ    (128 * TROW)              // 18432 B
#define B_TSZ    (256 * TROW)              // 36864 B
#define MM_SMEM1 (2 * (A_TSZ + B_TSZ))          // 110592
#define MM_SMEM3 (2 * (2 * A_TSZ + 2 * B_TSZ))  // 221184

template <int TERMS>
__device__ __forceinline__ void load_chunk(uint32_t st,
    const __half* __restrict__ Ah, const __half* __restrict__ Al,
    const __half* __restrict__ Bh, const __half* __restrict__ Bl,
    int LD, int m0, int n0, int k0, int t)
{
#pragma unroll
    for (int i = 0; i < 4; i++) {
        const int idx = (i << 8) + t;
        const int row = idx >> 3, j = idx & 7;
        const uint32_t so = (uint32_t)(row * TROW + j * 16);
        const size_t  go = (size_t)(m0 + row) * LD + k0 + (j << 3);
        cp16(st + so, Ah + go);
        if (TERMS == 3) cp16(st + A_TSZ + so, Al + go);
    }
    const uint32_t bb = st + (TERMS == 3 ? 2 : 1) * A_TSZ;
#pragma unroll
    for (int i = 0; i < 8; i++) {
        const int idx = (i << 8) + t;
        const int row = idx >> 3, j = idx & 7;
        const uint32_t so = (uint32_t)(row * TROW + j * 16);
        const size_t  go = (size_t)(n0 + row) * LD + k0 + (j << 3);
        cp16(bb + so, Bh + go);
        if (TERMS >= 2) cp16(bb + B_TSZ + so, Bl + go);
    }
}

template <int EPI, int TERMS>
__global__ __launch_bounds__(256, 1)
void mm_gemm(const __half* __restrict__ Ah, const __half* __restrict__ Al,
             const __half* __restrict__ Bh, const __half* __restrict__ Bl,
             float* __restrict__ C, __half* __restrict__ Ch,
             int Ntot, int LD, int Kstat,
             const int* __restrict__ meta, const float* __restrict__ bias,
             const float* __restrict__ rd, float* __restrict__ wr)
{
    constexpr uint32_t STG = (TERMS == 3 ? 2 : 1) * A_TSZ + (TERMS >= 2 ? 2 : 1) * B_TSZ;
    extern __shared__ char smem[];
    const uint32_t sb = su32(smem);
    const int t   = threadIdx.x;
    const int wid = t >> 5, l = t & 31;
    const int wm  = wid & 1;
    const int wn  = wid >> 1;
    const int m0  = blockIdx.y << 7, n0 = blockIdx.x << 8;

    if ((EPI == 2 || EPI == 4) && n0 >= __ldg(meta + 1)) return;
    const int K = (EPI == 3) ? __ldg(meta + 1) : Kstat;

    const uint32_t aoff = (uint32_t)(wm * 64 + (l & 7) + ((l >> 3) & 1) * 8) * TROW
                        + ((l >> 4) & 1) * 16;
    const uint32_t boff = (uint32_t)(wn * 64 + (l & 7) + ((l >> 4) & 1) * 8) * TROW
                        + ((l >> 3) & 1) * 16;
    const uint32_t bbase = (TERMS == 3 ? 2 : 1) * A_TSZ;

    float acc[4][8][4];
#pragma unroll
    for (int mf = 0; mf < 4; mf++)
#pragma unroll
        for (int nf = 0; nf < 8; nf++)
#pragma unroll
            for (int i = 0; i < 4; i++) acc[mf][nf][i] = 0.0f;

    const int nch = K / BK;

    load_chunk<TERMS>(sb, Ah, Al, Bh, Bl, LD, m0, n0, 0, t);        cp_commit();
    load_chunk<TERMS>(sb + STG, Ah, Al, Bh, Bl, LD, m0, n0, BK, t); cp_commit();

    for (int c = 0; c < nch; c++) {
        cp_wait1();
        __syncthreads();
        const uint32_t st = sb + (uint32_t)(c & 1) * STG;
#pragma unroll
        for (int ks = 0; ks < 4; ks++) {
            uint32_t ah[4][4], al[4][4], bh[4][4], bl[4][4];
#pragma unroll
            for (int mf = 0; mf < 4; mf++) {
                ldsm_x4(ah[mf], st + aoff + mf * (16 * TROW) + ks * 32);
                if (TERMS == 3)
                    ldsm_x4(al[mf], st + A_TSZ + aoff + mf * (16 * TROW) + ks * 32);
            }
#pragma unroll
            for (int nf2 = 0; nf2 < 4; nf2++) {
                ldsm_x4(bh[nf2], st + bbase + boff + nf2 * (16 * TROW) + ks * 32);
                if (TERMS >= 2)
                    ldsm_x4(bl[nf2], st + bbase + B_TSZ + boff + nf2 * (16 * TROW) + ks * 32);
            }
#pragma unroll
            for (int mf = 0; mf < 4; mf++)
#pragma unroll
                for (int nf = 0; nf < 8; nf++) {
                    const uint32_t* bhp = &bh[nf >> 1][(nf & 1) * 2];
                    const uint32_t* blp = &bl[nf >> 1][(nf & 1) * 2];
                    mma16816(acc[mf][nf], ah[mf], bhp);
                    if (TERMS >= 2) mma16816(acc[mf][nf], ah[mf], blp);
                    if (TERMS == 3) mma16816(acc[mf][nf], al[mf], bhp);
                }
        }
        __syncthreads();
        if (c + 2 < nch)
            load_chunk<TERMS>(sb + (uint32_t)(c & 1) * STG, Ah, Al, Bh, Bl,
                              LD, m0, n0, (c + 2) * BK, t);
        cp_commit();
    }

    const int mact = (EPI == 2) ? __ldg(meta + 0) : 0;

#pragma unroll
    for (int mf = 0; mf < 4; mf++) {
        const int r0 = m0 + wm * 64 + mf * 16 + (l >> 2);
        float rd0 = 0.f, rd1 = 0.f, p0 = 0.f, p1 = 0.f;
        if (EPI == 2) {
            rd0 = rsqrtf(__ldg(rd + r0) + 1e-6f);
            rd1 = rsqrtf(__ldg(rd + r0 + 8) + 1e-6f);
        }
        if (EPI == 3) {
            rd0 = 1.0f / __ldg(rd + r0);
            rd1 = 1.0f / __ldg(rd + r0 + 8);
        }
#pragma unroll
        for (int nf = 0; nf < 8; nf++) {
            const int c0 = n0 + wn * 64 + nf * 8 + ((l & 3) << 1);
            float v0 = acc[mf][nf][0], v1 = acc[mf][nf][1];
            float v2 = acc[mf][nf][2], v3 = acc[mf][nf][3];
            if (EPI == 2) {
                const bool u0 = c0 < mact, u1 = (c0 + 1) < mact;
                const float e0 = u0 ? __expf(fmaf(v0 * rd0, 10.f, -10.f)) * EXP_SCALE : 0.f;
                const float e1 = u1 ? __expf(fmaf(v1 * rd0, 10.f, -10.f)) * EXP_SCALE : 0.f;
                const float e2 = u0 ? __expf(fmaf(v2 * rd1, 10.f, -10.f)) * EXP_SCALE : 0.f;
                const float e3 = u1 ? __expf(fmaf(v3 * rd1, 10.f, -10.f)) * EXP_SCALE : 0.f;
                *(__half2*)(Ch + (size_t)r0 * Ntot + c0) =
                    __halves2half2(__float2half_rn(e0), __float2half_rn(e1));
                *(__half2*)(Ch + (size_t)(r0 + 8) * Ntot + c0) =
                    __halves2half2(__float2half_rn(e2), __float2half_rn(e3));
                p0 += e0 + e1; p1 += e2 + e3;
            }
            if (EPI == 3) {
                const float b0 = __ldg(bias + c0), b1 = __ldg(bias + c0 + 1);
                v0 = fmaf(v0, rd0, b0); v1 = fmaf(v1, rd0, b1);
                v2 = fmaf(v2, rd1, b0); v3 = fmaf(v3, rd1, b1);
                *(float2*)(C + (size_t)r0 * Ntot + c0)       = make_float2(v0, v1);
                *(float2*)(C + (size_t)(r0 + 8) * Ntot + c0) = make_float2(v2, v3);
            }
            if (EPI == 4) {
                *(__half2*)(Ch + (size_t)r0 * Ntot + c0) =
                    __halves2half2(__float2half_rn(v0), __float2half_rn(v1));
                *(__half2*)(Ch + (size_t)(r0 + 8) * Ntot + c0) =
                    __halves2half2(__float2half_rn(v2), __float2half_rn(v3));
            }
            if (EPI == 5) {
                const float b0 = __ldg(bias + c0), b1 = __ldg(bias + c0 + 1);
                v0 += b0; v1 += b1; v2 += b0; v3 += b1;
                *(__half2*)(Ch + (size_t)r0 * Ntot + c0) =
                    __halves2half2(__float2half_rn(v0), __float2half_rn(v1));
                *(__half2*)(Ch + (size_t)(r0 + 8) * Ntot + c0) =
                    __halves2half2(__float2half_rn(v2), __float2half_rn(v3));
                p0 += v0 * v0 + v1 * v1; p1 += v2 * v2 + v3 * v3;
            }
        }
        if (EPI == 2 || EPI == 5) {
            atomicAdd(wr + r0, p0);
            atomicAdd(wr + r0 + 8, p1);
        }
    }
}

// ---------------------------------------------------------------------------
// Launch pipeline
// ---------------------------------------------------------------------------
extern "C" void kernel_launch(void* const* d_in, const int* in_sizes, int n_in,
                              void* d_out, int out_size)
{
    const float* hidden = (const float*)d_in[0];
    const float* mk     = (const float*)d_in[1];
    const float* mv     = (const float*)d_in[2];
    const float* Wk     = (const float*)d_in[3];
    const float* bk     = (const float*)d_in[4];
    const float* Wo     = (const float*)d_in[5];
    const float* bo     = (const float*)d_in[6];
    const int*   usage  = (const int*)d_in[7];
    float* out = (float*)d_out;

    __half *hid_hi, *wk_hi, *wo_hi, *wo_lo, *mv_hi, *mv_lo;
    __half *mk_hi, *w2t_hi, *q_hi, *expp;
    float *qnormp, *rowsump;
    int *idxp, *metap;
    cudaGetSymbolAddress((void**)&hid_hi, g_hid_hi);
    cudaGetSymbolAddress((void**)&wk_hi, g_wk_hi);
    cudaGetSymbolAddress((void**)&wo_hi, g_wo_hi);
    cudaGetSymbolAddress((void**)&wo_lo, g_wo_lo);
    cudaGetSymbolAddress((void**)&mv_hi, g_mv_hi);
    cudaGetSymbolAddress((void**)&mv_lo, g_mv_lo);
    cudaGetSymbolAddress((void**)&mk_hi, g_mk_hi);
    cudaGetSymbolAddress((void**)&w2t_hi, g_w2t_hi);
    cudaGetSymbolAddress((void**)&q_hi, g_q_hi);
    cudaGetSymbolAddress((void**)&expp, g_exp);
    cudaGetSymbolAddress((void**)&qnormp, g_qnorm);
    cudaGetSymbolAddress((void**)&rowsump, g_rowsum);
    cudaGetSymbolAddress((void**)&idxp, g_idx);
    cudaGetSymbolAddress((void**)&metap, g_meta);

    cudaFuncSetAttribute(mm_gemm<5,1>, cudaFuncAttributeMaxDynamicSharedMemorySize, MM_SMEM1);
    cudaFuncSetAttribute(mm_gemm<4,3>, cudaFuncAttributeMaxDynamicSharedMemorySize, MM_SMEM3);
    cudaFuncSetAttribute(mm_gemm<2,1>, cudaFuncAttributeMaxDynamicSharedMemorySize, MM_SMEM1);
    cudaFuncSetAttribute(mm_gemm<3,1>, cudaFuncAttributeMaxDynamicSharedMemorySize, MM_SMEM1);

    // zero atomic accumulators (graph-capturable memset nodes)
    cudaMemsetAsync(qnormp, 0, T_TOK * sizeof(float), 0);
    cudaMemsetAsync(rowsump, 0, T_TOK * sizeof(float), 0);

    // compaction + prep
    compact_kernel<<<1, 1024>>>(usage, idxp, metap);
    convert_hi_kernel<<<2048, 256>>>(hidden, hid_hi, T_TOK * H_DIM / 4);
    prep_w_kernel<<<H_DIM * H_DIM / 4 / 256, 256>>>(Wk, Wo, wk_hi, wo_hi, wo_lo);
    prep_bank_kernel<<<M_MEM, 128>>>(mv, mk, idxp, metap, mv_hi, mv_lo, mk_hi);

    // W2T[h,j] = sum_v Wo[h,v] * mv_c[j,v]  (3-term; write hi fp16)
    mm_gemm<4,3><<<dim3(M_MEM / 256, H_DIM / 128), 256, MM_SMEM3>>>(
        wo_hi, wo_lo, mv_hi, mv_lo, nullptr, w2t_hi,
        M_MEM, H_DIM, H_DIM, metap, nullptr, nullptr, nullptr);

    // q = hidden_hi @ wk_hi^T + bk  (1-term) -> q_hi fp16 + qnorm atomics
    mm_gemm<5,1><<<dim3(H_DIM / 256, T_TOK / 128), 256, MM_SMEM1>>>(
        hid_hi, nullptr, wk_hi, nullptr, nullptr, q_hi,
        H_DIM, H_DIM, H_DIM, metap, bk, nullptr, qnormp);

    // exp scores (1-term): e = exp(10*acc*rsqrt(qnorm)-10)*8192 -> fp16 + rowsum atomics
    mm_gemm<2,1><<<dim3(M_MEM / 256, T_TOK / 128), 256, MM_SMEM1>>>(
        q_hi, nullptr, mk_hi, nullptr, nullptr, expp,
        M_MEM, H_DIM, H_DIM, metap, nullptr, qnormp, rowsump);

    // out = (exp @ w2t_hi^T) / rowsum + bo  (1-term, dynamic K)
    mm_gemm<3,1><<<dim3(H_DIM / 256, T_TOK / 128), 256, MM_SMEM1>>>(
        expp, nullptr, w2t_hi, nullptr, out, nullptr,
        H_DIM, M_MEM, 0, metap, bo, rowsump, nullptr);
}

// round 12
// speedup vs baseline: 3.9531x; 1.0073x over previous
#include <cuda_runtime.h>
#include <cuda_fp16.h>
#include <cstdint>

#define T_TOK 16384
#define H_DIM 512
#define M_MEM 4096
#define EXP_SCALE 8192.0f

// ---------------------------------------------------------------------------
// Scratch (static device globals; no allocations anywhere)
// ---------------------------------------------------------------------------
__device__ __half g_hid_hi[(size_t)T_TOK * H_DIM];
__device__ __half g_wk_hi[(size_t)H_DIM * H_DIM];
__device__ __half g_wo_hi[(size_t)H_DIM * H_DIM];
__device__ __half g_wo_lo[(size_t)H_DIM * H_DIM];
__device__ __half g_mv_hi[(size_t)M_MEM * H_DIM];   // compacted mv
__device__ __half g_mv_lo[(size_t)M_MEM * H_DIM];
__device__ __half g_mk_hi[(size_t)M_MEM * H_DIM];   // compacted, normalized mk (hi only)
__device__ __half g_w2t_hi[(size_t)H_DIM * M_MEM];  // W2T over compacted bank (hi only)
__device__ __half g_q_hi[(size_t)T_TOK * H_DIM];    // q (+bk), fp16, unnormalized
__device__ __half g_exp[(size_t)T_TOK * M_MEM];     // exp(logit-10)*8192, compacted cols
__device__ float  g_qnorm[T_TOK];                   // sum q^2 per row (atomic)
__device__ float  g_rowsum[T_TOK];                  // sum exp per row (atomic)
__device__ int    g_idx[M_MEM];                     // compacted slot -> original slot
__device__ int    g_meta[2];                        // [0]=M_active, [1]=pad256(M_active)

// ---------------------------------------------------------------------------
// Helpers (baseline PTX only: cp.async / ldmatrix / mma.sync)
// ---------------------------------------------------------------------------
__device__ __forceinline__ uint32_t su32(const void* p) {
    return (uint32_t)__cvta_generic_to_shared(p);
}
__device__ __forceinline__ void cp16(uint32_t dst, const void* src) {
    asm volatile("cp.async.cg.shared.global [%0], [%1], 16;\n" :: "r"(dst), "l"(src) : "memory");
}
__device__ __forceinline__ void cp_commit() { asm volatile("cp.async.commit_group;\n" ::: "memory"); }
__device__ __forceinline__ void cp_wait1()  { asm volatile("cp.async.wait_group 1;\n" ::: "memory"); }

__device__ __forceinline__ void ldsm_x4(uint32_t* r, uint32_t addr) {
    asm volatile("ldmatrix.sync.aligned.m8n8.x4.shared.b16 {%0,%1,%2,%3}, [%4];"
                 : "=r"(r[0]), "=r"(r[1]), "=r"(r[2]), "=r"(r[3]) : "r"(addr));
}
__device__ __forceinline__ void mma16816(float* c, const uint32_t* a, const uint32_t* b) {
    asm volatile(
        "mma.sync.aligned.m16n8k16.row.col.f32.f16.f16.f32 "
        "{%0,%1,%2,%3}, {%4,%5,%6,%7}, {%8,%9}, {%0,%1,%2,%3};"
        : "+f"(c[0]), "+f"(c[1]), "+f"(c[2]), "+f"(c[3])
        : "r"(a[0]), "r"(a[1]), "r"(a[2]), "r"(a[3]), "r"(b[0]), "r"(b[1]));
}

__device__ __forceinline__ void split1(float x, __half& h, __half& l) {
    h = __float2half_rn(x);
    l = __float2half_rn(x - __half2float(h));
}

// ---------------------------------------------------------------------------
// Compaction: stable prefix-scan over usage>0 -> idx list + meta
// ---------------------------------------------------------------------------
__global__ void compact_kernel(const int* __restrict__ usage, int* __restrict__ idx,
                               int* __restrict__ meta)
{
    __shared__ int wsum[32];
    const int t = threadIdx.x, lane = t & 31, w = t >> 5;
    const int base = t * 4;
    int f[4], cnt = 0;
#pragma unroll
    for (int i = 0; i < 4; i++) { f[i] = usage[base + i] > 0; cnt += f[i]; }
    int inc = cnt;
#pragma unroll
    for (int o = 1; o < 32; o <<= 1) {
        int v = __shfl_up_sync(0xffffffffu, inc, o);
        if (lane >= o) inc += v;
    }
    const int exc = inc - cnt;
    if (lane == 31) wsum[w] = inc;
    __syncthreads();
    if (w == 0) {
        int v = wsum[lane];
        __syncwarp();
#pragma unroll
        for (int o = 1; o < 32; o <<= 1) {
            int u = __shfl_up_sync(0xffffffffu, v, o);
            if (lane >= o) v += u;
        }
        wsum[lane] = v;
    }
    __syncthreads();
    int pos = (w > 0 ? wsum[w - 1] : 0) + exc;
#pragma unroll
    for (int i = 0; i < 4; i++)
        if (f[i]) idx[pos++] = base + i;
    if (t == 1023) {
        const int tot = wsum[31];
        meta[0] = tot;
        int pad = ((tot + 255) >> 8) << 8;
        meta[1] = pad < 256 ? 256 : pad;
    }
}

// ---------------------------------------------------------------------------
// Bank prep: block j handles compacted row j of BOTH mv (hi/lo split) and
// mk (L2-normalized, hi only). Zeros for padded rows.
// ---------------------------------------------------------------------------
__global__ void prep_bank_kernel(const float* __restrict__ mv, const float* __restrict__ mk,
                                 const int* __restrict__ idx, const int* __restrict__ meta,
                                 __half* __restrict__ mvh, __half* __restrict__ mvl,
                                 __half* __restrict__ mkh)
{
    __shared__ float sh[4];
    const int j = blockIdx.x, tid = threadIdx.x;
    const size_t off = (size_t)j * H_DIM + tid * 4;
    if (j >= meta[0]) {
        const __half2 z = __halves2half2(__float2half_rn(0.f), __float2half_rn(0.f));
        *(__half2*)(mvh + off + 0) = z; *(__half2*)(mvh + off + 2) = z;
        *(__half2*)(mvl + off + 0) = z; *(__half2*)(mvl + off + 2) = z;
        *(__half2*)(mkh + off + 0) = z; *(__half2*)(mkh + off + 2) = z;
        return;
    }
    const int row = idx[j];
    {
        float4 v = ((const float4*)(mv + (size_t)row * H_DIM))[tid];
        __half h0, l0, h1, l1, h2, l2, h3, l3;
        split1(v.x, h0, l0); split1(v.y, h1, l1); split1(v.z, h2, l2); split1(v.w, h3, l3);
        *(__half2*)(mvh + off + 0) = __halves2half2(h0, h1);
        *(__half2*)(mvh + off + 2) = __halves2half2(h2, h3);
        *(__half2*)(mvl + off + 0) = __halves2half2(l0, l1);
        *(__half2*)(mvl + off + 2) = __halves2half2(l2, l3);
    }
    {
        float4 v = ((const float4*)(mk + (size_t)row * H_DIM))[tid];
        float s = v.x * v.x + v.y * v.y + v.z * v.z + v.w * v.w;
#pragma unroll
        for (int o = 16; o; o >>= 1) s += __shfl_xor_sync(0xffffffffu, s, o);
        if ((tid & 31) == 0) sh[tid >> 5] = s;
        __syncthreads();
        const float r = rsqrtf(sh[0] + sh[1] + sh[2] + sh[3] + 1e-6f);
        *(__half2*)(mkh + off + 0) = __halves2half2(__float2half_rn(v.x * r), __float2half_rn(v.y * r));
        *(__half2*)(mkh + off + 2) = __halves2half2(__float2half_rn(v.z * r), __float2half_rn(v.w * r));
    }
}

// ---------------------------------------------------------------------------
// Weights prep: one thread per float4; Wk -> hi, Wo -> hi/lo.
// ---------------------------------------------------------------------------
__global__ void prep_w_kernel(const float* __restrict__ Wk, const float* __restrict__ Wo,
                              __half* __restrict__ wkh,
                              __half* __restrict__ woh, __half* __restrict__ wol)
{
    const int idx = blockIdx.x * blockDim.x + threadIdx.x;
    {
        float4 v = ((const float4*)Wk)[idx];
        ((__half2*)wkh)[idx * 2 + 0] = __halves2half2(__float2half_rn(v.x), __float2half_rn(v.y));
        ((__half2*)wkh)[idx * 2 + 1] = __halves2half2(__float2half_rn(v.z), __float2half_rn(v.w));
    }
    {
        float4 v = ((const float4*)Wo)[idx];
        __half h0, l0, h1, l1, h2, l2, h3, l3;
        split1(v.x, h0, l0); split1(v.y, h1, l1); split1(v.z, h2, l2); split1(v.w, h3, l3);
        ((__half2*)woh)[idx * 2 + 0] = __halves2half2(h0, h1);
        ((__half2*)woh)[idx * 2 + 1] = __halves2half2(h2, h3);
        ((__half2*)wol)[idx * 2 + 0] = __halves2half2(l0, l1);
        ((__half2*)wol)[idx * 2 + 1] = __halves2half2(l2, l3);
    }
}

// ---------------------------------------------------------------------------
// Elementwise fp32 -> fp16 (hidden)
// ---------------------------------------------------------------------------
__global__ void convert_hi_kernel(const float* __restrict__ in, __half* __restrict__ oh, int n4)
{
    int idx = blockIdx.x * blockDim.x + threadIdx.x;
    const int stride = gridDim.x * blockDim.x;
    for (; idx < n4; idx += stride) {
        float4 v = ((const float4*)in)[idx];
        ((__half2*)oh)[idx * 2 + 0] = __halves2half2(__float2half_rn(v.x), __float2half_rn(v.y));
        ((__half2*)oh)[idx * 2 + 1] = __halves2half2(__float2half_rn(v.z), __float2half_rn(v.w));
    }
}

// ---------------------------------------------------------------------------
// HMMA GEMM:  C[M,N] = terms(A,B)   (A:[M,K], B:[N,K], fp16, row.col)
// CTA tile 128x256, 8 warps (2x4) of 64x64, BK=64, fp32 accum.
// TERMS=1: 3-stage single-sync pipeline (loads for c+2 issued right after the
//          chunk barrier, before compute). TERMS=3: 2-stage classic loop.
// EPI: 2 scores: invq=rsqrt(rd[r]+eps); e = col<mact ? exp(10*acc*invq-10)*8192 : 0
//        -> Ch fp16; atomicAdd row partials of e into wr. Early-exit n0>=meta[1].
//      3 retrieval: out = acc*(1/rd[r]) + bias, K dyn = meta[1]. fp32 out.
//      4 W2T: write hi fp16 (Ch), early-exit n0 >= meta[1].
//      5 qproj: write fp16(acc+bias) to Ch; atomicAdd row partials of v^2 into wr.
// ---------------------------------------------------------------------------
#define BK       64
#define TROW     144
#define A_TSZ    (128 * TROW)              // 18432 B
#define B_TSZ    (256 * TROW)              // 36864 B
#define STG1     (A_TSZ + B_TSZ)           // 55296 B (TERMS=1 stage)
#define STG3     (2 * A_TSZ + 2 * B_TSZ)   // 110592 B (TERMS=3 stage)
#define MM_SMEM1 (3 * STG1)                // 165888
#define MM_SMEM3 (2 * STG3)                // 221184

template <int TERMS>
__device__ __forceinline__ void load_chunk(uint32_t st,
    const __half* __restrict__ Ah, const __half* __restrict__ Al,
    const __half* __restrict__ Bh, const __half* __restrict__ Bl,
    int LD, int m0, int n0, int k0, int t)
{
#pragma unroll
    for (int i = 0; i < 4; i++) {
        const int idx = (i << 8) + t;
        const int row = idx >> 3, j = idx & 7;
        const uint32_t so = (uint32_t)(row * TROW + j * 16);
        const size_t  go = (size_t)(m0 + row) * LD + k0 + (j << 3);
        cp16(st + so, Ah + go);
        if (TERMS == 3) cp16(st + A_TSZ + so, Al + go);
    }
    const uint32_t bb = st + (TERMS == 3 ? 2 : 1) * A_TSZ;
#pragma unroll
    for (int i = 0; i < 8; i++) {
        const int idx = (i << 8) + t;
        const int row = idx >> 3, j = idx & 7;
        const uint32_t so = (uint32_t)(row * TROW + j * 16);
        const size_t  go = (size_t)(n0 + row) * LD + k0 + (j << 3);
        cp16(bb + so, Bh + go);
        if (TERMS == 3) cp16(bb + B_TSZ + so, Bl + go);
    }
}

template <int EPI, int TERMS>
__global__ __launch_bounds__(256, 1)
void mm_gemm(const __half* __restrict__ Ah, const __half* __restrict__ Al,
             const __half* __restrict__ Bh, const __half* __restrict__ Bl,
             float* __restrict__ C, __half* __restrict__ Ch,
             int Ntot, int LD, int Kstat,
             const int* __restrict__ meta, const float* __restrict__ bias,
             const float* __restrict__ rd, float* __restrict__ wr)
{
    constexpr uint32_t STG = (TERMS == 3) ? STG3 : STG1;
    extern __shared__ char smem[];
    const uint32_t sb = su32(smem);
    const int t   = threadIdx.x;
    const int wid = t >> 5, l = t & 31;
    const int wm  = wid & 1;
    const int wn  = wid >> 1;
    const int m0  = blockIdx.y << 7, n0 = blockIdx.x << 8;

    if ((EPI == 2 || EPI == 4) && n0 >= __ldg(meta + 1)) return;
    const int K = (EPI == 3) ? __ldg(meta + 1) : Kstat;

    const uint32_t aoff = (uint32_t)(wm * 64 + (l & 7) + ((l >> 3) & 1) * 8) * TROW
                        + ((l >> 4) & 1) * 16;
    const uint32_t boff = (uint32_t)(wn * 64 + (l & 7) + ((l >> 4) & 1) * 8) * TROW
                        + ((l >> 3) & 1) * 16;
    const uint32_t bbase = (TERMS == 3 ? 2 : 1) * A_TSZ;

    float acc[4][8][4];
#pragma unroll
    for (int mf = 0; mf < 4; mf++)
#pragma unroll
        for (int nf = 0; nf < 8; nf++)
#pragma unroll
            for (int i = 0; i < 4; i++) acc[mf][nf][i] = 0.0f;

    const int nch = K / BK;

    load_chunk<TERMS>(sb, Ah, Al, Bh, Bl, LD, m0, n0, 0, t);        cp_commit();
    load_chunk<TERMS>(sb + STG, Ah, Al, Bh, Bl, LD, m0, n0, BK, t); cp_commit();

    for (int c = 0; c < nch; c++) {
        cp_wait1();
        __syncthreads();
        uint32_t st;
        if (TERMS == 1) {
            // 3-stage: issue loads for c+2 into slot (c+2)%3 (all warps past
            // the barrier -> nobody still reads that slot), then compute c.
            if (c + 2 < nch) {
                const int s2 = (c + 2) % 3;
                load_chunk<TERMS>(sb + (uint32_t)s2 * STG, Ah, Al, Bh, Bl,
                                  LD, m0, n0, (c + 2) * BK, t);
            }
            cp_commit();
            st = sb + (uint32_t)(c % 3) * STG;
        } else {
            st = sb + (uint32_t)(c & 1) * STG;
        }
#pragma unroll
        for (int ks = 0; ks < 4; ks++) {
            uint32_t ah[4][4], al[4][4], bh[4][4], bl[4][4];
#pragma unroll
            for (int mf = 0; mf < 4; mf++) {
                ldsm_x4(ah[mf], st + aoff + mf * (16 * TROW) + ks * 32);
                if (TERMS == 3)
                    ldsm_x4(al[mf], st + A_TSZ + aoff + mf * (16 * TROW) + ks * 32);
            }
#pragma unroll
            for (int nf2 = 0; nf2 < 4; nf2++) {
                ldsm_x4(bh[nf2], st + bbase + boff + nf2 * (16 * TROW) + ks * 32);
                if (TERMS == 3)
                    ldsm_x4(bl[nf2], st + bbase + B_TSZ + boff + nf2 * (16 * TROW) + ks * 32);
            }
#pragma unroll
            for (int mf = 0; mf < 4; mf++)
#pragma unroll
                for (int nf = 0; nf < 8; nf++) {
                    const uint32_t* bhp = &bh[nf >> 1][(nf & 1) * 2];
                    const uint32_t* blp = &bl[nf >> 1][(nf & 1) * 2];
                    mma16816(acc[mf][nf], ah[mf], bhp);
                    if (TERMS == 3) {
                        mma16816(acc[mf][nf], ah[mf], blp);
                        mma16816(acc[mf][nf], al[mf], bhp);
                    }
                }
        }
        if (TERMS == 3) {
            __syncthreads();
            if (c + 2 < nch)
                load_chunk<TERMS>(sb + (uint32_t)(c & 1) * STG, Ah, Al, Bh, Bl,
                                  LD, m0, n0, (c + 2) * BK, t);
            cp_commit();
        }
    }

    const int mact = (EPI == 2) ? __ldg(meta + 0) : 0;

#pragma unroll
    for (int mf = 0; mf < 4; mf++) {
        const int r0 = m0 + wm * 64 + mf * 16 + (l >> 2);
        float rd0 = 0.f, rd1 = 0.f, p0 = 0.f, p1 = 0.f;
        if (EPI == 2) {
            rd0 = rsqrtf(__ldg(rd + r0) + 1e-6f);
            rd1 = rsqrtf(__ldg(rd + r0 + 8) + 1e-6f);
        }
        if (EPI == 3) {
            rd0 = 1.0f / __ldg(rd + r0);
            rd1 = 1.0f / __ldg(rd + r0 + 8);
        }
#pragma unroll
        for (int nf = 0; nf < 8; nf++) {
            const int c0 = n0 + wn * 64 + nf * 8 + ((l & 3) << 1);
            float v0 = acc[mf][nf][0], v1 = acc[mf][nf][1];
            float v2 = acc[mf][nf][2], v3 = acc[mf][nf][3];
            if (EPI == 2) {
                const bool u0 = c0 < mact, u1 = (c0 + 1) < mact;
                const float e0 = u0 ? __expf(fmaf(v0 * rd0, 10.f, -10.f)) * EXP_SCALE : 0.f;
                const float e1 = u1 ? __expf(fmaf(v1 * rd0, 10.f, -10.f)) * EXP_SCALE : 0.f;
                const float e2 = u0 ? __expf(fmaf(v2 * rd1, 10.f, -10.f)) * EXP_SCALE : 0.f;
                const float e3 = u1 ? __expf(fmaf(v3 * rd1, 10.f, -10.f)) * EXP_SCALE : 0.f;
                *(__half2*)(Ch + (size_t)r0 * Ntot + c0) =
                    __halves2half2(__float2half_rn(e0), __float2half_rn(e1));
                *(__half2*)(Ch + (size_t)(r0 + 8) * Ntot + c0) =
                    __halves2half2(__float2half_rn(e2), __float2half_rn(e3));
                p0 += e0 + e1; p1 += e2 + e3;
            }
            if (EPI == 3) {
                const float b0 = __ldg(bias + c0), b1 = __ldg(bias + c0 + 1);
                v0 = fmaf(v0, rd0, b0); v1 = fmaf(v1, rd0, b1);
                v2 = fmaf(v2, rd1, b0); v3 = fmaf(v3, rd1, b1);
                *(float2*)(C + (size_t)r0 * Ntot + c0)       = make_float2(v0, v1);
                *(float2*)(C + (size_t)(r0 + 8) * Ntot + c0) = make_float2(v2, v3);
            }
            if (EPI == 4) {
                *(__half2*)(Ch + (size_t)r0 * Ntot + c0) =
                    __halves2half2(__float2half_rn(v0), __float2half_rn(v1));
                *(__half2*)(Ch + (size_t)(r0 + 8) * Ntot + c0) =
                    __halves2half2(__float2half_rn(v2), __float2half_rn(v3));
            }
            if (EPI == 5) {
                const float b0 = __ldg(bias + c0), b1 = __ldg(bias + c0 + 1);
                v0 += b0; v1 += b1; v2 += b0; v3 += b1;
                *(__half2*)(Ch + (size_t)r0 * Ntot + c0) =
                    __halves2half2(__float2half_rn(v0), __float2half_rn(v1));
                *(__half2*)(Ch + (size_t)(r0 + 8) * Ntot + c0) =
                    __halves2half2(__float2half_rn(v2), __float2half_rn(v3));
                p0 += v0 * v0 + v1 * v1; p1 += v2 * v2 + v3 * v3;
            }
        }
        if (EPI == 2 || EPI == 5) {
            atomicAdd(wr + r0, p0);
            atomicAdd(wr + r0 + 8, p1);
        }
    }
}

// ---------------------------------------------------------------------------
// Launch pipeline
// ---------------------------------------------------------------------------
extern "C" void kernel_launch(void* const* d_in, const int* in_sizes, int n_in,
                              void* d_out, int out_size)
{
    const float* hidden = (const float*)d_in[0];
    const float* mk     = (const float*)d_in[1];
    const float* mv     = (const float*)d_in[2];
    const float* Wk     = (const float*)d_in[3];
    const float* bk     = (const float*)d_in[4];
    const float* Wo     = (const float*)d_in[5];
    const float* bo     = (const float*)d_in[6];
    const int*   usage  = (const int*)d_in[7];
    float* out = (float*)d_out;

    __half *hid_hi, *wk_hi, *wo_hi, *wo_lo, *mv_hi, *mv_lo;
    __half *mk_hi, *w2t_hi, *q_hi, *expp;
    float *qnormp, *rowsump;
    int *idxp, *metap;
    cudaGetSymbolAddress((void**)&hid_hi, g_hid_hi);
    cudaGetSymbolAddress((void**)&wk_hi, g_wk_hi);
    cudaGetSymbolAddress((void**)&wo_hi, g_wo_hi);
    cudaGetSymbolAddress((void**)&wo_lo, g_wo_lo);
    cudaGetSymbolAddress((void**)&mv_hi, g_mv_hi);
    cudaGetSymbolAddress((void**)&mv_lo, g_mv_lo);
    cudaGetSymbolAddress((void**)&mk_hi, g_mk_hi);
    cudaGetSymbolAddress((void**)&w2t_hi, g_w2t_hi);
    cudaGetSymbolAddress((void**)&q_hi, g_q_hi);
    cudaGetSymbolAddress((void**)&expp, g_exp);
    cudaGetSymbolAddress((void**)&qnormp, g_qnorm);
    cudaGetSymbolAddress((void**)&rowsump, g_rowsum);
    cudaGetSymbolAddress((void**)&idxp, g_idx);
    cudaGetSymbolAddress((void**)&metap, g_meta);

    cudaFuncSetAttribute(mm_gemm<5,1>, cudaFuncAttributeMaxDynamicSharedMemorySize, MM_SMEM1);
    cudaFuncSetAttribute(mm_gemm<4,3>, cudaFuncAttributeMaxDynamicSharedMemorySize, MM_SMEM3);
    cudaFuncSetAttribute(mm_gemm<2,1>, cudaFuncAttributeMaxDynamicSharedMemorySize, MM_SMEM1);
    cudaFuncSetAttribute(mm_gemm<3,1>, cudaFuncAttributeMaxDynamicSharedMemorySize, MM_SMEM1);

    // zero atomic accumulators (graph-capturable memset nodes)
    cudaMemsetAsync(qnormp, 0, T_TOK * sizeof(float), 0);
    cudaMemsetAsync(rowsump, 0, T_TOK * sizeof(float), 0);

    // compaction + prep
    compact_kernel<<<1, 1024>>>(usage, idxp, metap);
    convert_hi_kernel<<<2048, 256>>>(hidden, hid_hi, T_TOK * H_DIM / 4);
    prep_w_kernel<<<H_DIM * H_DIM / 4 / 256, 256>>>(Wk, Wo, wk_hi, wo_hi, wo_lo);
    prep_bank_kernel<<<M_MEM, 128>>>(mv, mk, idxp, metap, mv_hi, mv_lo, mk_hi);

    // W2T[h,j] = sum_v Wo[h,v] * mv_c[j,v]  (3-term; write hi fp16)
    mm_gemm<4,3><<<dim3(M_MEM / 256, H_DIM / 128), 256, MM_SMEM3>>>(
        wo_hi, wo_lo, mv_hi, mv_lo, nullptr, w2t_hi,
        M_MEM, H_DIM, H_DIM, metap, nullptr, nullptr, nullptr);

    // q = hidden_hi @ wk_hi^T + bk  (1-term) -> q_hi fp16 + qnorm atomics
    mm_gemm<5,1><<<dim3(H_DIM / 256, T_TOK / 128), 256, MM_SMEM1>>>(
        hid_hi, nullptr, wk_hi, nullptr, nullptr, q_hi,
        H_DIM, H_DIM, H_DIM, metap, bk, nullptr, qnormp);

    // exp scores (1-term): e = exp(10*acc*rsqrt(qnorm)-10)*8192 -> fp16 + rowsum atomics
    mm_gemm<2,1><<<dim3(M_MEM / 256, T_TOK / 128), 256, MM_SMEM1>>>(
        q_hi, nullptr, mk_hi, nullptr, nullptr, expp,
        M_MEM, H_DIM, H_DIM, metap, nullptr, qnormp, rowsump);

    // out = (exp @ w2t_hi^T) / rowsum + bo  (1-term, dynamic K)
    mm_gemm<3,1><<<dim3(H_DIM / 256, T_TOK / 128), 256, MM_SMEM1>>>(
        expp, nullptr, w2t_hi, nullptr, out, nullptr,
        H_DIM, M_MEM, 0, metap, bo, rowsump, nullptr);
}